// round 1
// baseline (speedup 1.0000x reference)
#include <cuda_runtime.h>

#define BB   4
#define NN   1024
#define TT   16
#define FINN 32
#define HH   128
#define LHID 64
#define NP   64   // BB*TT independent graph-attention problems

// ---------------- scratch (static device allocations) ----------------
__device__ float    d_Wh [NP * NN * HH];          // 33.5 MB  current layer's Wh
__device__ float    d_h1 [NP * NN * HH];          // 33.5 MB  layer-1 output
__device__ float    d_g  [BB * NN * TT * HH];     // 33.5 MB  layer-2 output, LSTM layout [b*N+n][t][h]
__device__ float    d_eu [NP * NN];
__device__ float    d_eu2[NP * NN];
__device__ float    d_ev [NP * NN];
__device__ float    d_ev2[NP * NN];
__device__ unsigned d_adjp[BB * NN * (NN / 32)];  // packed adjacency bits
__device__ float    d_XG [BB * NN * TT * 256];    // 67 MB    precomputed input gates
__device__ float    d_hT [BB * NN * LHID];        // final hidden state

// ---------------- helpers ----------------
__device__ __forceinline__ float sigf(float x)   { return 1.f / (1.f + __expf(-x)); }
__device__ __forceinline__ float tanhf_(float x) { return 1.f - 2.f / (__expf(2.f * x) + 1.f); }

// ---------------- 1. pack adjacency into bitmasks ----------------
__global__ void pack_adj_kernel(const int* __restrict__ adj) {
    int w = blockIdx.x * blockDim.x + threadIdx.x;     // word index, 131072 total
    if (w >= BB * NN * (NN / 32)) return;
    long base = (long)w * 32;
    unsigned bits = 0;
#pragma unroll
    for (int j = 0; j < 32; j++) bits |= (adj[base + j] > 0 ? 1u : 0u) << j;
    d_adjp[w] = bits;
}

// ---------------- 2. Wh = in @ W  (per p = b*T + t) ----------------
// MODE 0: in = x (B,N,T,F) slice;  MODE 1: in = d_h1 [p][n][128]
template <int KIN, int MODE>
__global__ void wh_kernel(const float* __restrict__ in, const float* __restrict__ W) {
    int p = blockIdx.y, row0 = blockIdx.x * 64;
    int tid = threadIdx.x, tx = tid & 31, ty = tid >> 5;
    int b_ = p >> 4, t_ = p & 15;
    __shared__ float As[64][33];
    __shared__ float Bs[32][128];
    float acc[8][4] = {};
    for (int kc = 0; kc < KIN; kc += 32) {
        for (int idx = tid; idx < 64 * 32; idx += 256) {
            int r = idx >> 5, k = idx & 31;
            long off;
            if (MODE == 0)
                off = ((long)(b_ * NN + row0 + r) * TT + t_) * FINN + kc + k;
            else
                off = ((long)p * NN + row0 + r) * HH + kc + k;
            As[r][k] = (MODE == 0) ? in[off] : d_h1[off];
        }
        for (int idx = tid; idx < 32 * 128; idx += 256) {
            int k = idx >> 7, c = idx & 127;
            Bs[k][c] = W[(kc + k) * HH + c];
        }
        __syncthreads();
#pragma unroll
        for (int k = 0; k < 32; k++) {
            float4 b4 = *(const float4*)&Bs[k][tx * 4];
#pragma unroll
            for (int r = 0; r < 8; r++) {
                float a = As[ty * 8 + r][k];
                acc[r][0] += a * b4.x; acc[r][1] += a * b4.y;
                acc[r][2] += a * b4.z; acc[r][3] += a * b4.w;
            }
        }
        __syncthreads();
    }
#pragma unroll
    for (int r = 0; r < 8; r++) {
        float4 v = make_float4(acc[r][0], acc[r][1], acc[r][2], acc[r][3]);
        *(float4*)&d_Wh[((long)p * NN + row0 + ty * 8 + r) * HH + tx * 4] = v;
    }
}

// ---------------- 3. per-node attention exps ----------------
__global__ void s_kernel(const float* __restrict__ a) {
    int lane = threadIdx.x & 31, w = threadIdx.x >> 5;
    long idx = (long)blockIdx.x * 8 + w;              // p*N + n, 0..65535
    float4 wh = *(const float4*)&d_Wh[idx * HH + lane * 4];
    float4 as = *(const float4*)&a[lane * 4];
    float4 ad = *(const float4*)&a[128 + lane * 4];
    float ss = wh.x * as.x + wh.y * as.y + wh.z * as.z + wh.w * as.w;
    float sd = wh.x * ad.x + wh.y * ad.y + wh.z * ad.z + wh.w * ad.w;
#pragma unroll
    for (int o = 16; o; o >>= 1) {
        ss += __shfl_xor_sync(~0u, ss, o);
        sd += __shfl_xor_sync(~0u, sd, o);
    }
    if (lane == 0) {
        d_eu [idx] = __expf(ss);
        d_eu2[idx] = __expf(0.2f * ss);
        d_ev [idx] = __expf(sd);
        d_ev2[idx] = __expf(0.2f * sd);
    }
}

// ---------------- 4. masked-softmax attention:  out = softmax(e) @ Wh, double-ELU ----
// exp(leakyrelu(u+v)) == max( e^u * e^v , e^{0.2u} * e^{0.2v} )  -> no exp in inner loop
template <int LAYER>
__global__ void att_kernel() {
    int p = blockIdx.y, row0 = blockIdx.x * 64;
    int tid = threadIdx.x, tx = tid & 15, ty = tid >> 4;   // tx: 16 col groups of 8, ty: 16 row groups of 4
    int b_ = p >> 4, t_ = p & 15;
    __shared__ float    WhS[32][128];
    __shared__ float    evS[32], ev2S[32];
    __shared__ unsigned adjS[64];
    float acc[4][8] = {};
    float z[4] = {};
    float eur[4], eu2r[4];
#pragma unroll
    for (int r = 0; r < 4; r++) {
        int gi = p * NN + row0 + ty * 4 + r;
        eur[r] = d_eu[gi]; eu2r[r] = d_eu2[gi];
    }
    const float* Whp = &d_Wh[(long)p * NN * HH];
    for (int jc = 0; jc < NN; jc += 32) {
        __syncthreads();
        for (int idx = tid; idx < 32 * 128; idx += 256) {
            int j = idx >> 7, c = idx & 127;
            WhS[j][c] = Whp[(long)(jc + j) * HH + c];
        }
        if (tid < 32) {
            evS[tid]  = d_ev [p * NN + jc + tid];
            ev2S[tid] = d_ev2[p * NN + jc + tid];
        } else if (tid >= 64 && tid < 128) {
            int i = tid - 64;
            adjS[i] = d_adjp[(long)(b_ * NN + row0 + i) * 32 + (jc >> 5)];
        }
        __syncthreads();
        unsigned aw[4];
#pragma unroll
        for (int r = 0; r < 4; r++) aw[r] = adjS[ty * 4 + r];
#pragma unroll 4
        for (int jj = 0; jj < 32; jj++) {
            float evj = evS[jj], ev2j = ev2S[jj];
            float4 w0 = *(const float4*)&WhS[jj][tx * 8];
            float4 w1 = *(const float4*)&WhS[jj][tx * 8 + 4];
#pragma unroll
            for (int r = 0; r < 4; r++) {
                float m  = fmaxf(eur[r] * evj, eu2r[r] * ev2j);
                float wv = ((aw[r] >> jj) & 1u) ? m : 0.f;
                z[r] += wv;
                acc[r][0] += wv * w0.x; acc[r][1] += wv * w0.y;
                acc[r][2] += wv * w0.z; acc[r][3] += wv * w0.w;
                acc[r][4] += wv * w1.x; acc[r][5] += wv * w1.y;
                acc[r][6] += wv * w1.z; acc[r][7] += wv * w1.w;
            }
        }
    }
#pragma unroll
    for (int r = 0; r < 4; r++) {
        float inv = 1.f / z[r];
        int n = row0 + ty * 4 + r;
#pragma unroll
        for (int c = 0; c < 8; c++) {
            float o = acc[r][c] * inv;
            o = o > 0.f ? o : __expf(o) - 1.f;   // GAT's own ELU
            o = o > 0.f ? o : __expf(o) - 1.f;   // outer F.elu
            int col = tx * 8 + c;
            if (LAYER == 0)
                d_h1[((long)p * NN + n) * HH + col] = o;
            else
                d_g[(((long)(b_ * NN + n)) * TT + t_) * HH + col] = o;
        }
    }
}

// ---------------- 5. XG = seq @ W_ih^T + (b_ih + b_hh) ----------------
__global__ void xg_kernel(const float* __restrict__ Wih, const float* __restrict__ bih,
                          const float* __restrict__ bhh) {
    int m0 = blockIdx.x * 64, g0 = blockIdx.y * 128;
    int tid = threadIdx.x, tx = tid & 31, ty = tid >> 5;
    __shared__ float As[64][33];
    __shared__ float Bs[32][132];
    float acc[8][4] = {};
    for (int kc = 0; kc < 128; kc += 32) {
        for (int idx = tid; idx < 64 * 32; idx += 256) {
            int r = idx >> 5, k = idx & 31;
            As[r][k] = d_g[(long)(m0 + r) * HH + kc + k];
        }
        for (int idx = tid; idx < 128 * 32; idx += 256) {
            int gc = idx >> 5, k = idx & 31;
            Bs[k][gc] = Wih[(long)(g0 + gc) * HH + kc + k];
        }
        __syncthreads();
#pragma unroll
        for (int k = 0; k < 32; k++) {
            float4 b4 = *(const float4*)&Bs[k][tx * 4];
#pragma unroll
            for (int r = 0; r < 8; r++) {
                float a = As[ty * 8 + r][k];
                acc[r][0] += a * b4.x; acc[r][1] += a * b4.y;
                acc[r][2] += a * b4.z; acc[r][3] += a * b4.w;
            }
        }
        __syncthreads();
    }
    float4 bias;
    bias.x = bih[g0 + tx * 4 + 0] + bhh[g0 + tx * 4 + 0];
    bias.y = bih[g0 + tx * 4 + 1] + bhh[g0 + tx * 4 + 1];
    bias.z = bih[g0 + tx * 4 + 2] + bhh[g0 + tx * 4 + 2];
    bias.w = bih[g0 + tx * 4 + 3] + bhh[g0 + tx * 4 + 3];
#pragma unroll
    for (int r = 0; r < 8; r++) {
        float4 v = make_float4(acc[r][0] + bias.x, acc[r][1] + bias.y,
                               acc[r][2] + bias.z, acc[r][3] + bias.w);
        *(float4*)&d_XG[(long)(m0 + ty * 8 + r) * 256 + g0 + tx * 4] = v;
    }
}

// ---------------- 6. LSTM recurrence (W_hh^T in smem), 16 rows / block ----------------
__global__ void lstm_kernel(const float* __restrict__ Whh) {
    extern __shared__ float sm[];
    float* WT = sm;                 // [64][257] transposed, padded
    float* hs = sm + 64 * 257;      // [16][68]
    int tid = threadIdx.x, lane = tid & 31, wp = tid >> 5;
    for (int idx = tid; idx < 256 * 64; idx += 256) {
        int g = idx >> 6, k = idx & 63;
        WT[k * 257 + g] = Whh[g * 64 + k];
    }
    for (int idx = tid; idx < 16 * 68; idx += 256) hs[idx] = 0.f;
    __syncthreads();

    int r0 = wp * 2, r1 = r0 + 1;
    long gr0 = (long)blockIdx.x * 16 + r0;
    long gr1 = gr0 + 1;
    float c[2][2] = {};
    float hn[2][2] = {};
    for (int t = 0; t < TT; t++) {
        float acc[2][4][2];
#pragma unroll
        for (int d = 0; d < 2; d++) {
            long base = ((d ? gr1 : gr0) * TT + t) * 256;
#pragma unroll
            for (int q = 0; q < 4; q++) {
                acc[d][q][0] = d_XG[base + q * 64 + lane];
                acc[d][q][1] = d_XG[base + q * 64 + 32 + lane];
            }
        }
#pragma unroll 8
        for (int k = 0; k < 64; k++) {
            float h0  = hs[r0 * 68 + k];
            float h1v = hs[r1 * 68 + k];
            const float* wr = &WT[k * 257];
#pragma unroll
            for (int q = 0; q < 4; q++) {
                float wv0 = wr[q * 64 + lane];
                float wv1 = wr[q * 64 + 32 + lane];
                acc[0][q][0] += wv0 * h0;  acc[0][q][1] += wv1 * h0;
                acc[1][q][0] += wv0 * h1v; acc[1][q][1] += wv1 * h1v;
            }
        }
#pragma unroll
        for (int d = 0; d < 2; d++)
#pragma unroll
            for (int u = 0; u < 2; u++) {
                float iv = sigf(acc[d][0][u]);
                float fv = sigf(acc[d][1][u]);
                float gv = tanhf_(acc[d][2][u]);
                float ov = sigf(acc[d][3][u]);
                c[d][u]  = fv * c[d][u] + iv * gv;
                hn[d][u] = ov * tanhf_(c[d][u]);
            }
        __syncthreads();
        hs[r0 * 68 + lane]      = hn[0][0];
        hs[r0 * 68 + 32 + lane] = hn[0][1];
        hs[r1 * 68 + lane]      = hn[1][0];
        hs[r1 * 68 + 32 + lane] = hn[1][1];
        __syncthreads();
    }
    d_hT[gr0 * 64 + lane]      = hn[0][0];
    d_hT[gr0 * 64 + 32 + lane] = hn[0][1];
    d_hT[gr1 * 64 + lane]      = hn[1][0];
    d_hT[gr1 * 64 + 32 + lane] = hn[1][1];
}

// ---------------- 7. output MLP ----------------
__global__ void mlp_kernel(const float* __restrict__ Wo1, const float* __restrict__ bo1,
                           const float* __restrict__ Wo2, const float* __restrict__ bo2,
                           float* __restrict__ out) {
    __shared__ float hsm[128][65];
    __shared__ float W1s[64 * 32];
    __shared__ float W2s[32];
    int tid = threadIdx.x;                 // 128 threads, one row each
    int row0 = blockIdx.x * 128;
    for (int idx = tid; idx < 64 * 32; idx += 128) W1s[idx] = Wo1[idx];
    if (tid < 32) W2s[tid] = Wo2[tid];
    for (int idx = tid; idx < 128 * 64; idx += 128) {
        int r = idx >> 6, k = idx & 63;
        hsm[r][k] = d_hT[(long)(row0 + r) * 64 + k];
    }
    __syncthreads();
    float acc[32];
#pragma unroll
    for (int j = 0; j < 32; j++) acc[j] = bo1[j];
    for (int k = 0; k < 64; k++) {
        float hk = hsm[tid][k];
#pragma unroll
        for (int j = 0; j < 32; j++) acc[j] += hk * W1s[k * 32 + j];
    }
    float o = bo2[0];
#pragma unroll
    for (int j = 0; j < 32; j++) {
        float m = acc[j] > 0.f ? acc[j] : 0.f;
        o += m * W2s[j];
    }
    out[row0 + tid] = o;
}

// ---------------- launcher ----------------
extern "C" void kernel_launch(void* const* d_in, const int* in_sizes, int n_in,
                              void* d_out, int out_size) {
    const float* x   = (const float*)d_in[0];
    const int*   adj = (const int*)  d_in[1];
    const float* W1  = (const float*)d_in[2];
    const float* a1  = (const float*)d_in[3];
    const float* W2  = (const float*)d_in[4];
    const float* a2  = (const float*)d_in[5];
    const float* Wih = (const float*)d_in[6];
    const float* Whh = (const float*)d_in[7];
    const float* bih = (const float*)d_in[8];
    const float* bhh = (const float*)d_in[9];
    const float* Wo1 = (const float*)d_in[10];
    const float* bo1 = (const float*)d_in[11];
    const float* Wo2 = (const float*)d_in[12];
    const float* bo2 = (const float*)d_in[13];
    float* out = (float*)d_out;

    pack_adj_kernel<<<512, 256>>>(adj);

    // GAT layer 1
    wh_kernel<32, 0><<<dim3(16, 64), 256>>>(x, W1);
    s_kernel<<<8192, 256>>>(a1);
    att_kernel<0><<<dim3(16, 64), 256>>>();

    // GAT layer 2
    wh_kernel<128, 1><<<dim3(16, 64), 256>>>(x /*unused*/, W2);
    s_kernel<<<8192, 256>>>(a2);
    att_kernel<1><<<dim3(16, 64), 256>>>();

    // LSTM
    xg_kernel<<<dim3(1024, 2), 256>>>(Wih, bih, bhh);
    size_t smem = (64 * 257 + 16 * 68) * sizeof(float);
    cudaFuncSetAttribute(lstm_kernel, cudaFuncAttributeMaxDynamicSharedMemorySize, (int)smem);
    lstm_kernel<<<256, 256, smem>>>(Whh);

    // MLP
    mlp_kernel<<<32, 128>>>(Wo1, bo1, Wo2, bo2, out);
}

// round 2
// speedup vs baseline: 1.9904x; 1.9904x over previous
#include <cuda_runtime.h>

#define BB   4
#define NN   1024
#define TT   16
#define FINN 32
#define HH   128
#define LHID 64
#define NP   64   // BB*TT independent graph-attention problems

// ---------------- scratch (static device allocations) ----------------
__device__ float    d_Wh [NP * NN * HH];
__device__ float    d_h1 [NP * NN * HH];
__device__ float    d_g  [BB * NN * TT * HH];     // LSTM layout [b*N+n][t][h]
__device__ float    d_eu [NP * NN];
__device__ float    d_eu2[NP * NN];
__device__ float    d_ev [NP * NN];
__device__ float    d_ev2[NP * NN];
__device__ unsigned d_adjp[BB * NN * (NN / 32)];
__device__ float    d_XG [BB * NN * TT * 256];
__device__ float    d_hT [BB * NN * LHID];

// ---------------- helpers ----------------
__device__ __forceinline__ float sigf(float x)   { return 1.f / (1.f + __expf(-x)); }
__device__ __forceinline__ float tanhf_(float x) { return 1.f - 2.f / (__expf(2.f * x) + 1.f); }
__device__ __forceinline__ unsigned tf32r(float x) {
    unsigned u;
    asm("cvt.rna.tf32.f32 %0, %1;" : "=r"(u) : "f"(x));
    return u;
}
__device__ __forceinline__ void mma_tf32(float& c0, float& c1, float& c2, float& c3,
                                         unsigned a0, unsigned a1, unsigned a2, unsigned a3,
                                         unsigned b0, unsigned b1) {
    asm volatile("mma.sync.aligned.m16n8k8.row.col.f32.tf32.tf32.f32 "
                 "{%0,%1,%2,%3}, {%4,%5,%6,%7}, {%8,%9}, {%0,%1,%2,%3};"
                 : "+f"(c0), "+f"(c1), "+f"(c2), "+f"(c3)
                 : "r"(a0), "r"(a1), "r"(a2), "r"(a3), "r"(b0), "r"(b1));
}

// ---------------- 1. pack adjacency into bitmasks ----------------
__global__ void pack_adj_kernel(const int* __restrict__ adj) {
    int w = blockIdx.x * blockDim.x + threadIdx.x;
    if (w >= BB * NN * (NN / 32)) return;
    long base = (long)w * 32;
    unsigned bits = 0;
#pragma unroll
    for (int j = 0; j < 32; j++) bits |= (adj[base + j] > 0 ? 1u : 0u) << j;
    d_adjp[w] = bits;
}

// ---------------- 2. Wh = in @ W  (per p = b*T + t) ----------------
template <int KIN, int MODE>
__global__ void wh_kernel(const float* __restrict__ in, const float* __restrict__ W) {
    int p = blockIdx.y, row0 = blockIdx.x * 64;
    int tid = threadIdx.x, tx = tid & 31, ty = tid >> 5;
    int b_ = p >> 4, t_ = p & 15;
    __shared__ float As[64][33];
    __shared__ float Bs[32][128];
    float acc[8][4] = {};
    for (int kc = 0; kc < KIN; kc += 32) {
        for (int idx = tid; idx < 64 * 32; idx += 256) {
            int r = idx >> 5, k = idx & 31;
            long off;
            if (MODE == 0)
                off = ((long)(b_ * NN + row0 + r) * TT + t_) * FINN + kc + k;
            else
                off = ((long)p * NN + row0 + r) * HH + kc + k;
            As[r][k] = (MODE == 0) ? in[off] : d_h1[off];
        }
        for (int idx = tid; idx < 32 * 128; idx += 256) {
            int k = idx >> 7, c = idx & 127;
            Bs[k][c] = W[(kc + k) * HH + c];
        }
        __syncthreads();
#pragma unroll
        for (int k = 0; k < 32; k++) {
            float4 b4 = *(const float4*)&Bs[k][tx * 4];
#pragma unroll
            for (int r = 0; r < 8; r++) {
                float a = As[ty * 8 + r][k];
                acc[r][0] += a * b4.x; acc[r][1] += a * b4.y;
                acc[r][2] += a * b4.z; acc[r][3] += a * b4.w;
            }
        }
        __syncthreads();
    }
#pragma unroll
    for (int r = 0; r < 8; r++) {
        float4 v = make_float4(acc[r][0], acc[r][1], acc[r][2], acc[r][3]);
        *(float4*)&d_Wh[((long)p * NN + row0 + ty * 8 + r) * HH + tx * 4] = v;
    }
}

// ---------------- 3. per-node attention exps ----------------
__global__ void s_kernel(const float* __restrict__ a) {
    int lane = threadIdx.x & 31, w = threadIdx.x >> 5;
    long idx = (long)blockIdx.x * 8 + w;
    float4 wh = *(const float4*)&d_Wh[idx * HH + lane * 4];
    float4 as = *(const float4*)&a[lane * 4];
    float4 ad = *(const float4*)&a[128 + lane * 4];
    float ss = wh.x * as.x + wh.y * as.y + wh.z * as.z + wh.w * as.w;
    float sd = wh.x * ad.x + wh.y * ad.y + wh.z * ad.z + wh.w * ad.w;
#pragma unroll
    for (int o = 16; o; o >>= 1) {
        ss += __shfl_xor_sync(~0u, ss, o);
        sd += __shfl_xor_sync(~0u, sd, o);
    }
    if (lane == 0) {
        d_eu [idx] = __expf(ss);
        d_eu2[idx] = __expf(0.2f * ss);
        d_ev [idx] = __expf(sd);
        d_ev2[idx] = __expf(0.2f * sd);
    }
}

// ---------------- 4. tensor-core masked-softmax attention ----------------
// out = elu(elu(softmax(mask ? leakyrelu-score : -inf) @ Wh))
// P tile materialized in smem (tf32), numerator on mma.sync tf32,
// denominator z kept exact fp32.
template <int LAYER>
__global__ void __launch_bounds__(256) att_tc_kernel() {
    int p = blockIdx.y, row0 = blockIdx.x * 64;
    int tid = threadIdx.x;
    int lane = tid & 31, wid = tid >> 5;
    int b_ = p >> 4, t_ = p & 15;

    __shared__ float WhS[32][132];   // staged Wh tile (tf32-rounded)
    __shared__ float PS [64][36];    // P tile (tf32-rounded)
    __shared__ float zS [64];
    __shared__ float evS[32], ev2S[32];

    // P-phase thread mapping: fixed row per thread across all jc tiles
    int prow = tid >> 2;             // 0..63
    int pgrp = tid & 3;              // col group of 8
    float eur  = d_eu [p * NN + row0 + prow];
    float eu2r = d_eu2[p * NN + row0 + prow];
    float zacc = 0.f;
    const unsigned* adjrow = &d_adjp[(long)(b_ * NN + row0 + prow) * (NN / 32)];

    // mma warp mapping: 2 m-tiles x 4 n-tiles
    int wm = wid >> 2;               // 0..1 : rows wm*32 .. +32
    int wn = wid & 3;                // 0..3 : cols wn*32 .. +32
    int g = lane >> 2, t = lane & 3;
    float acc[2][4][4] = {};         // [mf][nf][c0..c3]

    const float* Whp = &d_Wh[(long)p * NN * HH];

    for (int jc = 0; jc < NN; jc += 32) {
        __syncthreads();   // protect WhS/PS from previous iteration's mma reads
        // stage Wh tile 32x128 (tf32-rounded), float4 global loads
#pragma unroll
        for (int v = 0; v < 4; v++) {
            int idx = (tid + v * 256) * 4;         // 0..4095
            int j = idx >> 7, c = idx & 127;
            float4 w4 = *(const float4*)&Whp[(long)(jc + j) * HH + c];
            WhS[j][c + 0] = __uint_as_float(tf32r(w4.x));
            WhS[j][c + 1] = __uint_as_float(tf32r(w4.y));
            WhS[j][c + 2] = __uint_as_float(tf32r(w4.z));
            WhS[j][c + 3] = __uint_as_float(tf32r(w4.w));
        }
        if (tid < 32)            evS [tid]      = d_ev [p * NN + jc + tid];
        else if (tid < 64)       ev2S[tid - 32] = d_ev2[p * NN + jc + tid - 32];
        __syncthreads();   // evS ready before P compute reads it

        // P tile compute
        unsigned aw = adjrow[jc >> 5];
#pragma unroll
        for (int q = 0; q < 8; q++) {
            int jj = pgrp * 8 + q;
            float m  = fmaxf(eur * evS[jj], eu2r * ev2S[jj]);
            float wv = ((aw >> jj) & 1u) ? m : 0.f;
            zacc += wv;
            PS[prow][jj] = __uint_as_float(tf32r(wv));
        }
        __syncthreads();

        // mma phase: each warp 32x32 output tile, k = 32 in 4 steps of 8
#pragma unroll
        for (int ks = 0; ks < 4; ks++) {
            unsigned a[2][4], b[4][2];
#pragma unroll
            for (int mf = 0; mf < 2; mf++) {
                int r0 = wm * 32 + mf * 16 + g;
                a[mf][0] = __float_as_uint(PS[r0    ][ks * 8 + t    ]);
                a[mf][1] = __float_as_uint(PS[r0 + 8][ks * 8 + t    ]);
                a[mf][2] = __float_as_uint(PS[r0    ][ks * 8 + t + 4]);
                a[mf][3] = __float_as_uint(PS[r0 + 8][ks * 8 + t + 4]);
            }
#pragma unroll
            for (int nf = 0; nf < 4; nf++) {
                int cb = wn * 32 + nf * 8 + g;
                b[nf][0] = __float_as_uint(WhS[ks * 8 + t    ][cb]);
                b[nf][1] = __float_as_uint(WhS[ks * 8 + t + 4][cb]);
            }
#pragma unroll
            for (int mf = 0; mf < 2; mf++)
#pragma unroll
                for (int nf = 0; nf < 4; nf++)
                    mma_tf32(acc[mf][nf][0], acc[mf][nf][1], acc[mf][nf][2], acc[mf][nf][3],
                             a[mf][0], a[mf][1], a[mf][2], a[mf][3], b[nf][0], b[nf][1]);
        }
    }

    // reduce z across the 4 threads sharing a row, publish to smem
    zacc += __shfl_xor_sync(~0u, zacc, 1);
    zacc += __shfl_xor_sync(~0u, zacc, 2);
    __syncthreads();
    if (pgrp == 0) zS[prow] = zacc;
    __syncthreads();

    // epilogue: divide by z, double ELU, store
#pragma unroll
    for (int mf = 0; mf < 2; mf++) {
        int r0 = wm * 32 + mf * 16 + g;
        float iz0 = 1.f / zS[r0];
        float iz1 = 1.f / zS[r0 + 8];
#pragma unroll
        for (int nf = 0; nf < 4; nf++) {
            int col = wn * 32 + nf * 8 + t * 2;
            float o[4] = {acc[mf][nf][0] * iz0, acc[mf][nf][1] * iz0,
                          acc[mf][nf][2] * iz1, acc[mf][nf][3] * iz1};
#pragma unroll
            for (int u = 0; u < 4; u++) {
                float v = o[u];
                v = v > 0.f ? v : __expf(v) - 1.f;   // GAT ELU
                v = v > 0.f ? v : __expf(v) - 1.f;   // outer F.elu
                o[u] = v;
            }
            int n0 = row0 + r0, n1 = n0 + 8;
            if (LAYER == 0) {
                *(float2*)&d_h1[((long)p * NN + n0) * HH + col] = make_float2(o[0], o[1]);
                *(float2*)&d_h1[((long)p * NN + n1) * HH + col] = make_float2(o[2], o[3]);
            } else {
                *(float2*)&d_g[(((long)(b_ * NN + n0)) * TT + t_) * HH + col] = make_float2(o[0], o[1]);
                *(float2*)&d_g[(((long)(b_ * NN + n1)) * TT + t_) * HH + col] = make_float2(o[2], o[3]);
            }
        }
    }
}

// ---------------- 5. XG = seq @ W_ih^T + (b_ih + b_hh) ----------------
__global__ void xg_kernel(const float* __restrict__ Wih, const float* __restrict__ bih,
                          const float* __restrict__ bhh) {
    int m0 = blockIdx.x * 64, g0 = blockIdx.y * 128;
    int tid = threadIdx.x, tx = tid & 31, ty = tid >> 5;
    __shared__ float As[64][33];
    __shared__ float Bs[32][132];
    float acc[8][4] = {};
    for (int kc = 0; kc < 128; kc += 32) {
        for (int idx = tid; idx < 64 * 32; idx += 256) {
            int r = idx >> 5, k = idx & 31;
            As[r][k] = d_g[(long)(m0 + r) * HH + kc + k];
        }
        for (int idx = tid; idx < 128 * 32; idx += 256) {
            int gc = idx >> 5, k = idx & 31;
            Bs[k][gc] = Wih[(long)(g0 + gc) * HH + kc + k];
        }
        __syncthreads();
#pragma unroll
        for (int k = 0; k < 32; k++) {
            float4 b4 = *(const float4*)&Bs[k][tx * 4];
#pragma unroll
            for (int r = 0; r < 8; r++) {
                float a = As[ty * 8 + r][k];
                acc[r][0] += a * b4.x; acc[r][1] += a * b4.y;
                acc[r][2] += a * b4.z; acc[r][3] += a * b4.w;
            }
        }
        __syncthreads();
    }
    float4 bias;
    bias.x = bih[g0 + tx * 4 + 0] + bhh[g0 + tx * 4 + 0];
    bias.y = bih[g0 + tx * 4 + 1] + bhh[g0 + tx * 4 + 1];
    bias.z = bih[g0 + tx * 4 + 2] + bhh[g0 + tx * 4 + 2];
    bias.w = bih[g0 + tx * 4 + 3] + bhh[g0 + tx * 4 + 3];
#pragma unroll
    for (int r = 0; r < 8; r++) {
        float4 v = make_float4(acc[r][0] + bias.x, acc[r][1] + bias.y,
                               acc[r][2] + bias.z, acc[r][3] + bias.w);
        *(float4*)&d_XG[(long)(m0 + ty * 8 + r) * 256 + g0 + tx * 4] = v;
    }
}

// ---------------- 6. LSTM recurrence ----------------
__global__ void lstm_kernel(const float* __restrict__ Whh) {
    extern __shared__ float sm[];
    float* WT = sm;                 // [64][257]
    float* hs = sm + 64 * 257;      // [16][68]
    int tid = threadIdx.x, lane = tid & 31, wp = tid >> 5;
    for (int idx = tid; idx < 256 * 64; idx += 256) {
        int g = idx >> 6, k = idx & 63;
        WT[k * 257 + g] = Whh[g * 64 + k];
    }
    for (int idx = tid; idx < 16 * 68; idx += 256) hs[idx] = 0.f;
    __syncthreads();

    int r0 = wp * 2, r1 = r0 + 1;
    long gr0 = (long)blockIdx.x * 16 + r0;
    long gr1 = gr0 + 1;
    float c[2][2] = {};
    float hn[2][2] = {};
    for (int tt = 0; tt < TT; tt++) {
        float acc[2][4][2];
#pragma unroll
        for (int d = 0; d < 2; d++) {
            long base = ((d ? gr1 : gr0) * TT + tt) * 256;
#pragma unroll
            for (int q = 0; q < 4; q++) {
                acc[d][q][0] = d_XG[base + q * 64 + lane];
                acc[d][q][1] = d_XG[base + q * 64 + 32 + lane];
            }
        }
#pragma unroll 8
        for (int k = 0; k < 64; k++) {
            float h0  = hs[r0 * 68 + k];
            float h1v = hs[r1 * 68 + k];
            const float* wr = &WT[k * 257];
#pragma unroll
            for (int q = 0; q < 4; q++) {
                float wv0 = wr[q * 64 + lane];
                float wv1 = wr[q * 64 + 32 + lane];
                acc[0][q][0] += wv0 * h0;  acc[0][q][1] += wv1 * h0;
                acc[1][q][0] += wv0 * h1v; acc[1][q][1] += wv1 * h1v;
            }
        }
#pragma unroll
        for (int d = 0; d < 2; d++)
#pragma unroll
            for (int u = 0; u < 2; u++) {
                float iv = sigf(acc[d][0][u]);
                float fv = sigf(acc[d][1][u]);
                float gv = tanhf_(acc[d][2][u]);
                float ov = sigf(acc[d][3][u]);
                c[d][u]  = fv * c[d][u] + iv * gv;
                hn[d][u] = ov * tanhf_(c[d][u]);
            }
        __syncthreads();
        hs[r0 * 68 + lane]      = hn[0][0];
        hs[r0 * 68 + 32 + lane] = hn[0][1];
        hs[r1 * 68 + lane]      = hn[1][0];
        hs[r1 * 68 + 32 + lane] = hn[1][1];
        __syncthreads();
    }
    d_hT[gr0 * 64 + lane]      = hn[0][0];
    d_hT[gr0 * 64 + 32 + lane] = hn[0][1];
    d_hT[gr1 * 64 + lane]      = hn[1][0];
    d_hT[gr1 * 64 + 32 + lane] = hn[1][1];
}

// ---------------- 7. output MLP ----------------
__global__ void mlp_kernel(const float* __restrict__ Wo1, const float* __restrict__ bo1,
                           const float* __restrict__ Wo2, const float* __restrict__ bo2,
                           float* __restrict__ out) {
    __shared__ float hsm[128][65];
    __shared__ float W1s[64 * 32];
    __shared__ float W2s[32];
    int tid = threadIdx.x;
    int row0 = blockIdx.x * 128;
    for (int idx = tid; idx < 64 * 32; idx += 128) W1s[idx] = Wo1[idx];
    if (tid < 32) W2s[tid] = Wo2[tid];
    for (int idx = tid; idx < 128 * 64; idx += 128) {
        int r = idx >> 6, k = idx & 63;
        hsm[r][k] = d_hT[(long)(row0 + r) * 64 + k];
    }
    __syncthreads();
    float acc[32];
#pragma unroll
    for (int j = 0; j < 32; j++) acc[j] = bo1[j];
    for (int k = 0; k < 64; k++) {
        float hk = hsm[tid][k];
#pragma unroll
        for (int j = 0; j < 32; j++) acc[j] += hk * W1s[k * 32 + j];
    }
    float o = bo2[0];
#pragma unroll
    for (int j = 0; j < 32; j++) {
        float m = acc[j] > 0.f ? acc[j] : 0.f;
        o += m * W2s[j];
    }
    out[row0 + tid] = o;
}

// ---------------- launcher ----------------
extern "C" void kernel_launch(void* const* d_in, const int* in_sizes, int n_in,
                              void* d_out, int out_size) {
    const float* x   = (const float*)d_in[0];
    const int*   adj = (const int*)  d_in[1];
    const float* W1  = (const float*)d_in[2];
    const float* a1  = (const float*)d_in[3];
    const float* W2  = (const float*)d_in[4];
    const float* a2  = (const float*)d_in[5];
    const float* Wih = (const float*)d_in[6];
    const float* Whh = (const float*)d_in[7];
    const float* bih = (const float*)d_in[8];
    const float* bhh = (const float*)d_in[9];
    const float* Wo1 = (const float*)d_in[10];
    const float* bo1 = (const float*)d_in[11];
    const float* Wo2 = (const float*)d_in[12];
    const float* bo2 = (const float*)d_in[13];
    float* out = (float*)d_out;

    pack_adj_kernel<<<512, 256>>>(adj);

    // GAT layer 1
    wh_kernel<32, 0><<<dim3(16, 64), 256>>>(x, W1);
    s_kernel<<<8192, 256>>>(a1);
    att_tc_kernel<0><<<dim3(16, 64), 256>>>();

    // GAT layer 2
    wh_kernel<128, 1><<<dim3(16, 64), 256>>>(x /*unused*/, W2);
    s_kernel<<<8192, 256>>>(a2);
    att_tc_kernel<1><<<dim3(16, 64), 256>>>();

    // LSTM
    xg_kernel<<<dim3(1024, 2), 256>>>(Wih, bih, bhh);
    size_t smem = (64 * 257 + 16 * 68) * sizeof(float);
    cudaFuncSetAttribute(lstm_kernel, cudaFuncAttributeMaxDynamicSharedMemorySize, (int)smem);
    lstm_kernel<<<256, 256, smem>>>(Whh);

    // MLP
    mlp_kernel<<<32, 128>>>(Wo1, bo1, Wo2, bo2, out);
}

// round 3
// speedup vs baseline: 2.5821x; 1.2973x over previous
#include <cuda_runtime.h>
#include <cuda_bf16.h>

#define BB   4
#define NN   1024
#define TT   16
#define FINN 32
#define HH   128
#define LHID 64
#define NP   64
#define MTOT (NP * NN)   // 65536 total rows

// ---------------- scratch ----------------
__device__ float    d_Wh [MTOT * HH];
__device__ float    d_h1 [MTOT * HH];
__device__ float    d_g  [MTOT * HH];             // LSTM layout [(b*N+n)*T + t][h]
__device__ float    d_eu [MTOT];
__device__ float    d_eu2[MTOT];
__device__ float    d_ev [MTOT];
__device__ float    d_ev2[MTOT];
__device__ unsigned d_adjp[BB * NN * (NN / 32)];
__device__ float    d_XG [MTOT * 256];
__device__ float    d_hT [BB * NN * LHID];

// ---------------- helpers ----------------
__device__ __forceinline__ float sigf(float x)   { return 1.f / (1.f + __expf(-x)); }
__device__ __forceinline__ float tanhf_(float x) { return 1.f - 2.f / (__expf(2.f * x) + 1.f); }
__device__ __forceinline__ unsigned tf32r(float x) {
    unsigned u;
    asm("cvt.rna.tf32.f32 %0, %1;" : "=r"(u) : "f"(x));
    return u;
}
__device__ __forceinline__ void mma_tf32(float* c, const unsigned* a, const unsigned* b) {
    asm volatile("mma.sync.aligned.m16n8k8.row.col.f32.tf32.tf32.f32 "
                 "{%0,%1,%2,%3}, {%4,%5,%6,%7}, {%8,%9}, {%0,%1,%2,%3};"
                 : "+f"(c[0]), "+f"(c[1]), "+f"(c[2]), "+f"(c[3])
                 : "r"(a[0]), "r"(a[1]), "r"(a[2]), "r"(a[3]), "r"(b[0]), "r"(b[1]));
}
__device__ __forceinline__ void mma_bf16(float* c, const unsigned* a, const unsigned* b) {
    asm volatile("mma.sync.aligned.m16n8k16.row.col.f32.bf16.bf16.f32 "
                 "{%0,%1,%2,%3}, {%4,%5,%6,%7}, {%8,%9}, {%0,%1,%2,%3};"
                 : "+f"(c[0]), "+f"(c[1]), "+f"(c[2]), "+f"(c[3])
                 : "r"(a[0]), "r"(a[1]), "r"(a[2]), "r"(a[3]), "r"(b[0]), "r"(b[1]));
}
__device__ __forceinline__ float elu2(float v) {
    v = v > 0.f ? v : __expf(v) - 1.f;
    v = v > 0.f ? v : __expf(v) - 1.f;
    return v;
}

// ---------------- 1. pack adjacency ----------------
__global__ void pack_adj_kernel(const int* __restrict__ adj) {
    int w = blockIdx.x * blockDim.x + threadIdx.x;
    if (w >= BB * NN * (NN / 32)) return;
    long base = (long)w * 32;
    unsigned bits = 0;
#pragma unroll
    for (int j = 0; j < 32; j++) bits |= (adj[base + j] > 0 ? 1u : 0u) << j;
    d_adjp[w] = bits;
}

// ---------------- 2. tf32 tensor GEMM:  Out[M=65536, NTOT] ----------------
// AMODE 0: A = x gathered (K=32);  AMODE 1: A = dense [m][128]
// BMODE 0: B = W [K][NOUT] row-major;  BMODE 1: B[k][n] = Bw[c0+n][k]  (Wih)
template <int KDIM, int AMODE, int BMODE, int BIAS, int NTOT>
__global__ void __launch_bounds__(256) gemm_tc(const float* __restrict__ A,
                                               const float* __restrict__ Bw,
                                               const float* __restrict__ bi1,
                                               const float* __restrict__ bi2,
                                               float* __restrict__ Out) {
    int m0 = blockIdx.x * 128;
    int c0 = blockIdx.y * 128;
    int tid = threadIdx.x, lane = tid & 31, wid = tid >> 5;
    int wm = wid >> 2, wn = wid & 3;
    int g = lane >> 2, t = lane & 3;

    __shared__ float As[128][36];
    __shared__ float Bs[128 * 36];   // BMODE0 uses [32][136] view (4352<=4608)

    float acc[4][4][4] = {};
    const int KT = KDIM / 32;

    for (int kt = 0; kt < KT; kt++) {
        int kc = kt * 32;
        // ---- stage A tile [128 rows][32 k] ----
        {
            int r = tid >> 1, k0 = (tid & 1) * 16;
            const float* src;
            long base;
            if (AMODE == 0) {
                int m = m0 + r;
                int n = m & (NN - 1);
                int pp = m >> 10, tt2 = pp & 15, bb2 = pp >> 4;
                base = (((long)(bb2 * NN + n) * TT + tt2) * FINN) + k0;
            } else {
                base = (long)(m0 + r) * KDIM + kc + k0;
            }
            src = A + base;
#pragma unroll
            for (int q = 0; q < 4; q++) {
                float4 v = *(const float4*)(src + q * 4);
                As[r][k0 + q * 4 + 0] = __uint_as_float(tf32r(v.x));
                As[r][k0 + q * 4 + 1] = __uint_as_float(tf32r(v.y));
                As[r][k0 + q * 4 + 2] = __uint_as_float(tf32r(v.z));
                As[r][k0 + q * 4 + 3] = __uint_as_float(tf32r(v.w));
            }
        }
        // ---- stage B tile ----
        if (BMODE == 0) {
            int kr = tid >> 3, cq = tid & 7;
            const float* src = Bw + (long)(kc + kr) * NTOT + c0 + cq * 16;
#pragma unroll
            for (int q = 0; q < 4; q++) {
                float4 v = *(const float4*)(src + q * 4);
                float* dst = &Bs[kr * 136 + cq * 16 + q * 4];
                dst[0] = __uint_as_float(tf32r(v.x));
                dst[1] = __uint_as_float(tf32r(v.y));
                dst[2] = __uint_as_float(tf32r(v.z));
                dst[3] = __uint_as_float(tf32r(v.w));
            }
        } else {
            int n = tid >> 1, k0 = (tid & 1) * 16;
            const float* src = Bw + (long)(c0 + n) * KDIM + kc + k0;
#pragma unroll
            for (int q = 0; q < 4; q++) {
                float4 v = *(const float4*)(src + q * 4);
                float* dst = &Bs[n * 36 + k0 + q * 4];
                dst[0] = __uint_as_float(tf32r(v.x));
                dst[1] = __uint_as_float(tf32r(v.y));
                dst[2] = __uint_as_float(tf32r(v.z));
                dst[3] = __uint_as_float(tf32r(v.w));
            }
        }
        __syncthreads();
        // ---- MMA ----
#pragma unroll
        for (int ks = 0; ks < 4; ks++) {
            unsigned a[4][4], bf[4][2];
#pragma unroll
            for (int mf = 0; mf < 4; mf++) {
                int r = wm * 64 + mf * 16 + g;
                a[mf][0] = __float_as_uint(As[r    ][ks * 8 + t    ]);
                a[mf][1] = __float_as_uint(As[r + 8][ks * 8 + t    ]);
                a[mf][2] = __float_as_uint(As[r    ][ks * 8 + t + 4]);
                a[mf][3] = __float_as_uint(As[r + 8][ks * 8 + t + 4]);
            }
#pragma unroll
            for (int nf = 0; nf < 4; nf++) {
                int cc = wn * 32 + nf * 8 + g;
                if (BMODE == 0) {
                    bf[nf][0] = __float_as_uint(Bs[(ks * 8 + t    ) * 136 + cc]);
                    bf[nf][1] = __float_as_uint(Bs[(ks * 8 + t + 4) * 136 + cc]);
                } else {
                    bf[nf][0] = __float_as_uint(Bs[cc * 36 + ks * 8 + t    ]);
                    bf[nf][1] = __float_as_uint(Bs[cc * 36 + ks * 8 + t + 4]);
                }
            }
#pragma unroll
            for (int mf = 0; mf < 4; mf++)
#pragma unroll
                for (int nf = 0; nf < 4; nf++)
                    mma_tf32(acc[mf][nf], a[mf], bf[nf]);
        }
        __syncthreads();
    }
    // ---- epilogue ----
#pragma unroll
    for (int mf = 0; mf < 4; mf++) {
        int r = m0 + wm * 64 + mf * 16 + g;
#pragma unroll
        for (int nf = 0; nf < 4; nf++) {
            int cc = c0 + wn * 32 + nf * 8 + 2 * t;
            float b0 = 0.f, b1 = 0.f;
            if (BIAS) {
                b0 = bi1[cc] + bi2[cc];
                b1 = bi1[cc + 1] + bi2[cc + 1];
            }
            *(float2*)&Out[(long)r * NTOT + cc] =
                make_float2(acc[mf][nf][0] + b0, acc[mf][nf][1] + b1);
            *(float2*)&Out[(long)(r + 8) * NTOT + cc] =
                make_float2(acc[mf][nf][2] + b0, acc[mf][nf][3] + b1);
        }
    }
}

// ---------------- 3. per-node attention exps ----------------
__global__ void s_kernel(const float* __restrict__ a) {
    int lane = threadIdx.x & 31, w = threadIdx.x >> 5;
    long idx = (long)blockIdx.x * 8 + w;
    float4 wh = *(const float4*)&d_Wh[idx * HH + lane * 4];
    float4 as = *(const float4*)&a[lane * 4];
    float4 ad = *(const float4*)&a[128 + lane * 4];
    float ss = wh.x * as.x + wh.y * as.y + wh.z * as.z + wh.w * as.w;
    float sd = wh.x * ad.x + wh.y * ad.y + wh.z * ad.z + wh.w * ad.w;
#pragma unroll
    for (int o = 16; o; o >>= 1) {
        ss += __shfl_xor_sync(~0u, ss, o);
        sd += __shfl_xor_sync(~0u, sd, o);
    }
    if (lane == 0) {
        d_eu [idx] = __expf(ss);
        d_eu2[idx] = __expf(0.2f * ss);
        d_ev [idx] = __expf(sd);
        d_ev2[idx] = __expf(0.2f * sd);
    }
}

// ---------------- 4. bf16 tensor attention ----------------
// 128 rows x 128 cols per block, 8 warps (2 wm x 4 wn), m16n8k16 bf16.
// Wh staged transposed (WhT[c][j], 3 bufs); P bf16 (2 bufs); 1 barrier/tile.
template <int LAYER>
__global__ void __launch_bounds__(256) att_bf16_kernel() {
    int p = blockIdx.y, row0 = blockIdx.x * 128;
    int tid = threadIdx.x, lane = tid & 31, wid = tid >> 5;
    int b_ = p >> 4, t_ = p & 15;

    __shared__ __nv_bfloat16 WhT[3][128][36];   // [c][j] transposed
    __shared__ __nv_bfloat16 PS [2][128][36];   // [row][j]
    __shared__ float         evS[3][64];        // ev 0..31, ev2 32..63
    __shared__ unsigned      adjS[3][128];
    __shared__ float         zS[128];

    // P mapping: one row per 2 threads, 16 contiguous j each
    int prow = tid >> 1;
    int j0   = (tid & 1) * 16;
    float eur  = d_eu [p * NN + row0 + prow];
    float eu2r = d_eu2[p * NN + row0 + prow];
    float zacc = 0.f;

    // mma mapping
    int wm = wid >> 2, wn = wid & 3;
    int g = lane >> 2, t = lane & 3;
    float acc[4][4][4] = {};

    const float*    Whp   = &d_Wh[(long)p * NN * HH];
    const unsigned* adjpb = &d_adjp[(long)b_ * NN * (NN / 32)];

    // staging thread map: jp = tid&15 (j pair), ch = tid>>4 (8-col chunk)
    int jp = tid & 15, ch = tid >> 4;
    int sc0 = ch * 8;

    auto STAGE = [&](int i) {
        int bb = i % 3, jc = i * 32;
        const float* r0p = Whp + (long)(jc + 2 * jp) * HH + sc0;
        float4 a0 = *(const float4*)r0p;
        float4 a1 = *(const float4*)(r0p + 4);
        float4 b0 = *(const float4*)(r0p + HH);
        float4 b1 = *(const float4*)(r0p + HH + 4);
        float av[8] = {a0.x, a0.y, a0.z, a0.w, a1.x, a1.y, a1.z, a1.w};
        float bv[8] = {b0.x, b0.y, b0.z, b0.w, b1.x, b1.y, b1.z, b1.w};
#pragma unroll
        for (int u = 0; u < 8; u++)
            *(__nv_bfloat162*)&WhT[bb][sc0 + u][2 * jp] = __floats2bfloat162_rn(av[u], bv[u]);
        if (tid < 8)
            *(float4*)&evS[bb][tid * 4] = *(const float4*)&d_ev[p * NN + jc + tid * 4];
        else if (tid < 16)
            *(float4*)&evS[bb][32 + (tid - 8) * 4] = *(const float4*)&d_ev2[p * NN + jc + (tid - 8) * 4];
        if (tid >= 32 && tid < 160)
            adjS[bb][tid - 32] = adjpb[(long)(row0 + tid - 32) * (NN / 32) + i];
    };

    auto PCOMP = [&](int i) {
        int bb = i % 3, pb = i & 1;
        float ev[16], ev2[16];
#pragma unroll
        for (int q = 0; q < 4; q++) {
            *(float4*)&ev [q * 4] = *(float4*)&evS[bb][j0 + q * 4];
            *(float4*)&ev2[q * 4] = *(float4*)&evS[bb][32 + j0 + q * 4];
        }
        unsigned aw = adjS[bb][prow] >> j0;
#pragma unroll
        for (int q = 0; q < 8; q++) {
            float w0 = ((aw >> (2 * q))     & 1u) ? fmaxf(eur * ev[2 * q],     eu2r * ev2[2 * q])     : 0.f;
            float w1 = ((aw >> (2 * q + 1)) & 1u) ? fmaxf(eur * ev[2 * q + 1], eu2r * ev2[2 * q + 1]) : 0.f;
            zacc += w0 + w1;
            *(__nv_bfloat162*)&PS[pb][prow][j0 + 2 * q] = __floats2bfloat162_rn(w0, w1);
        }
    };

    auto MMAF = [&](int i) {
        int bb = i % 3, pb = i & 1;
#pragma unroll
        for (int ks = 0; ks < 2; ks++) {
            unsigned a[4][4], bf[4][2];
#pragma unroll
            for (int mf = 0; mf < 4; mf++) {
                int r = wm * 64 + mf * 16 + g;
                a[mf][0] = *(unsigned*)&PS[pb][r    ][ks * 16 + 2 * t    ];
                a[mf][1] = *(unsigned*)&PS[pb][r + 8][ks * 16 + 2 * t    ];
                a[mf][2] = *(unsigned*)&PS[pb][r    ][ks * 16 + 2 * t + 8];
                a[mf][3] = *(unsigned*)&PS[pb][r + 8][ks * 16 + 2 * t + 8];
            }
#pragma unroll
            for (int nf = 0; nf < 4; nf++) {
                int cc = wn * 32 + nf * 8 + g;
                bf[nf][0] = *(unsigned*)&WhT[bb][cc][ks * 16 + 2 * t    ];
                bf[nf][1] = *(unsigned*)&WhT[bb][cc][ks * 16 + 2 * t + 8];
            }
#pragma unroll
            for (int mf = 0; mf < 4; mf++)
#pragma unroll
                for (int nf = 0; nf < 4; nf++)
                    mma_bf16(acc[mf][nf], a[mf], bf[nf]);
        }
    };

    STAGE(0);
    __syncthreads();
    PCOMP(0);
    STAGE(1);
    __syncthreads();
    for (int i = 0; i < 32; i++) {
        MMAF(i);
        if (i + 1 < 32) PCOMP(i + 1);
        if (i + 2 < 32) STAGE(i + 2);
        __syncthreads();
    }

    zacc += __shfl_xor_sync(~0u, zacc, 1);
    if (!(tid & 1)) zS[prow] = zacc;
    __syncthreads();

#pragma unroll
    for (int mf = 0; mf < 4; mf++) {
        int r = wm * 64 + mf * 16 + g;
        float iz0 = 1.f / zS[r];
        float iz1 = 1.f / zS[r + 8];
#pragma unroll
        for (int nf = 0; nf < 4; nf++) {
            int col = wn * 32 + nf * 8 + 2 * t;
            float o0 = elu2(acc[mf][nf][0] * iz0);
            float o1 = elu2(acc[mf][nf][1] * iz0);
            float o2 = elu2(acc[mf][nf][2] * iz1);
            float o3 = elu2(acc[mf][nf][3] * iz1);
            int n0 = row0 + r, n1 = n0 + 8;
            if (LAYER == 0) {
                *(float2*)&d_h1[((long)p * NN + n0) * HH + col] = make_float2(o0, o1);
                *(float2*)&d_h1[((long)p * NN + n1) * HH + col] = make_float2(o2, o3);
            } else {
                *(float2*)&d_g[(((long)(b_ * NN + n0)) * TT + t_) * HH + col] = make_float2(o0, o1);
                *(float2*)&d_g[(((long)(b_ * NN + n1)) * TT + t_) * HH + col] = make_float2(o2, o3);
            }
        }
    }
}

// ---------------- 6. LSTM recurrence ----------------
__global__ void lstm_kernel(const float* __restrict__ Whh) {
    extern __shared__ float sm[];
    float* WT = sm;                 // [64][257]
    float* hs = sm + 64 * 257;      // [16][68]
    int tid = threadIdx.x, lane = tid & 31, wp = tid >> 5;
    for (int idx = tid; idx < 256 * 64; idx += 256) {
        int g = idx >> 6, k = idx & 63;
        WT[k * 257 + g] = Whh[g * 64 + k];
    }
    for (int idx = tid; idx < 16 * 68; idx += 256) hs[idx] = 0.f;
    __syncthreads();

    int r0 = wp * 2, r1 = r0 + 1;
    long gr0 = (long)blockIdx.x * 16 + r0;
    long gr1 = gr0 + 1;
    float c[2][2] = {};
    float hn[2][2] = {};
    for (int tt = 0; tt < TT; tt++) {
        float acc[2][4][2];
#pragma unroll
        for (int d = 0; d < 2; d++) {
            long base = ((d ? gr1 : gr0) * TT + tt) * 256;
#pragma unroll
            for (int q = 0; q < 4; q++) {
                acc[d][q][0] = d_XG[base + q * 64 + lane];
                acc[d][q][1] = d_XG[base + q * 64 + 32 + lane];
            }
        }
#pragma unroll 8
        for (int k = 0; k < 64; k++) {
            float h0  = hs[r0 * 68 + k];
            float h1v = hs[r1 * 68 + k];
            const float* wr = &WT[k * 257];
#pragma unroll
            for (int q = 0; q < 4; q++) {
                float wv0 = wr[q * 64 + lane];
                float wv1 = wr[q * 64 + 32 + lane];
                acc[0][q][0] += wv0 * h0;  acc[0][q][1] += wv1 * h0;
                acc[1][q][0] += wv0 * h1v; acc[1][q][1] += wv1 * h1v;
            }
        }
#pragma unroll
        for (int d = 0; d < 2; d++)
#pragma unroll
            for (int u = 0; u < 2; u++) {
                float iv = sigf(acc[d][0][u]);
                float fv = sigf(acc[d][1][u]);
                float gv = tanhf_(acc[d][2][u]);
                float ov = sigf(acc[d][3][u]);
                c[d][u]  = fv * c[d][u] + iv * gv;
                hn[d][u] = ov * tanhf_(c[d][u]);
            }
        __syncthreads();
        hs[r0 * 68 + lane]      = hn[0][0];
        hs[r0 * 68 + 32 + lane] = hn[0][1];
        hs[r1 * 68 + lane]      = hn[1][0];
        hs[r1 * 68 + 32 + lane] = hn[1][1];
        __syncthreads();
    }
    d_hT[gr0 * 64 + lane]      = hn[0][0];
    d_hT[gr0 * 64 + 32 + lane] = hn[0][1];
    d_hT[gr1 * 64 + lane]      = hn[1][0];
    d_hT[gr1 * 64 + 32 + lane] = hn[1][1];
}

// ---------------- 7. output MLP ----------------
__global__ void mlp_kernel(const float* __restrict__ Wo1, const float* __restrict__ bo1,
                           const float* __restrict__ Wo2, const float* __restrict__ bo2,
                           float* __restrict__ out) {
    __shared__ float hsm[128][65];
    __shared__ float W1s[64 * 32];
    __shared__ float W2s[32];
    int tid = threadIdx.x;
    int row0 = blockIdx.x * 128;
    for (int idx = tid; idx < 64 * 32; idx += 128) W1s[idx] = Wo1[idx];
    if (tid < 32) W2s[tid] = Wo2[tid];
    for (int idx = tid; idx < 128 * 64; idx += 128) {
        int r = idx >> 6, k = idx & 63;
        hsm[r][k] = d_hT[(long)(row0 + r) * 64 + k];
    }
    __syncthreads();
    float acc[32];
#pragma unroll
    for (int j = 0; j < 32; j++) acc[j] = bo1[j];
    for (int k = 0; k < 64; k++) {
        float hk = hsm[tid][k];
#pragma unroll
        for (int j = 0; j < 32; j++) acc[j] += hk * W1s[k * 32 + j];
    }
    float o = bo2[0];
#pragma unroll
    for (int j = 0; j < 32; j++) {
        float m = acc[j] > 0.f ? acc[j] : 0.f;
        o += m * W2s[j];
    }
    out[row0 + tid] = o;
}

// ---------------- launcher ----------------
extern "C" void kernel_launch(void* const* d_in, const int* in_sizes, int n_in,
                              void* d_out, int out_size) {
    const float* x   = (const float*)d_in[0];
    const int*   adj = (const int*)  d_in[1];
    const float* W1  = (const float*)d_in[2];
    const float* a1  = (const float*)d_in[3];
    const float* W2  = (const float*)d_in[4];
    const float* a2  = (const float*)d_in[5];
    const float* Wih = (const float*)d_in[6];
    const float* Whh = (const float*)d_in[7];
    const float* bih = (const float*)d_in[8];
    const float* bhh = (const float*)d_in[9];
    const float* Wo1 = (const float*)d_in[10];
    const float* bo1 = (const float*)d_in[11];
    const float* Wo2 = (const float*)d_in[12];
    const float* bo2 = (const float*)d_in[13];
    float* out = (float*)d_out;

    float* d_Wh_p;  cudaGetSymbolAddress((void**)&d_Wh_p,  d_Wh);
    float* d_h1_p;  cudaGetSymbolAddress((void**)&d_h1_p,  d_h1);
    float* d_g_p;   cudaGetSymbolAddress((void**)&d_g_p,   d_g);
    float* d_XG_p;  cudaGetSymbolAddress((void**)&d_XG_p,  d_XG);

    pack_adj_kernel<<<512, 256>>>(adj);

    // GAT layer 1
    gemm_tc<32, 0, 0, 0, 128><<<dim3(512, 1), 256>>>(x, W1, nullptr, nullptr, d_Wh_p);
    s_kernel<<<8192, 256>>>(a1);
    att_bf16_kernel<0><<<dim3(8, 64), 256>>>();

    // GAT layer 2
    gemm_tc<128, 1, 0, 0, 128><<<dim3(512, 1), 256>>>(d_h1_p, W2, nullptr, nullptr, d_Wh_p);
    s_kernel<<<8192, 256>>>(a2);
    att_bf16_kernel<1><<<dim3(8, 64), 256>>>();

    // LSTM input gates
    gemm_tc<128, 1, 1, 1, 256><<<dim3(512, 2), 256>>>(d_g_p, Wih, bih, bhh, d_XG_p);

    // LSTM recurrence
    size_t smem = (64 * 257 + 16 * 68) * sizeof(float);
    cudaFuncSetAttribute(lstm_kernel, cudaFuncAttributeMaxDynamicSharedMemorySize, (int)smem);
    lstm_kernel<<<256, 256, smem>>>(Whh);

    // MLP
    mlp_kernel<<<32, 128>>>(Wo1, bo1, Wo2, bo2, out);
}

// round 4
// speedup vs baseline: 2.8264x; 1.0946x over previous
#include <cuda_runtime.h>
#include <cuda_bf16.h>

#define BB   4
#define NN   1024
#define TT   16
#define FINN 32
#define HH   128
#define LHID 64
#define NP   64
#define MTOT (NP * NN)

// ---------------- scratch ----------------
__device__ float    d_Wh [MTOT * HH];
__device__ float    d_h1 [MTOT * HH];
__device__ float    d_g  [MTOT * HH];             // LSTM layout [(b*N+n)*T + t][h]
__device__ float    d_eu [MTOT];
__device__ float    d_eu2[MTOT];
__device__ float    d_ev [MTOT];
__device__ float    d_ev2[MTOT];
__device__ unsigned d_adjp[BB * NN * (NN / 32)];
__device__ float    d_XG [MTOT * 256];
__device__ float    d_hT [BB * NN * LHID];

// ---------------- helpers ----------------
__device__ __forceinline__ float sigf(float x)   { return 1.f / (1.f + __expf(-x)); }
__device__ __forceinline__ float tanhf_(float x) { return 1.f - 2.f / (__expf(2.f * x) + 1.f); }
__device__ __forceinline__ unsigned tf32r(float x) {
    unsigned u;
    asm("cvt.rna.tf32.f32 %0, %1;" : "=r"(u) : "f"(x));
    return u;
}
__device__ __forceinline__ void mma_tf32(float* c, const unsigned* a, const unsigned* b) {
    asm volatile("mma.sync.aligned.m16n8k8.row.col.f32.tf32.tf32.f32 "
                 "{%0,%1,%2,%3}, {%4,%5,%6,%7}, {%8,%9}, {%0,%1,%2,%3};"
                 : "+f"(c[0]), "+f"(c[1]), "+f"(c[2]), "+f"(c[3])
                 : "r"(a[0]), "r"(a[1]), "r"(a[2]), "r"(a[3]), "r"(b[0]), "r"(b[1]));
}
__device__ __forceinline__ void mma_bf16(float* c, const unsigned* a, const unsigned* b) {
    asm volatile("mma.sync.aligned.m16n8k16.row.col.f32.bf16.bf16.f32 "
                 "{%0,%1,%2,%3}, {%4,%5,%6,%7}, {%8,%9}, {%0,%1,%2,%3};"
                 : "+f"(c[0]), "+f"(c[1]), "+f"(c[2]), "+f"(c[3])
                 : "r"(a[0]), "r"(a[1]), "r"(a[2]), "r"(a[3]), "r"(b[0]), "r"(b[1]));
}
__device__ __forceinline__ float elu2(float v) {
    v = v > 0.f ? v : __expf(v) - 1.f;
    v = v > 0.f ? v : __expf(v) - 1.f;
    return v;
}
__device__ __forceinline__ unsigned packbf(float a, float b) {
    __nv_bfloat162 p = __floats2bfloat162_rn(a, b);
    return *(unsigned*)&p;
}

// ---------------- 1. pack adjacency ----------------
__global__ void pack_adj_kernel(const int* __restrict__ adj) {
    int w = blockIdx.x * blockDim.x + threadIdx.x;
    if (w >= BB * NN * (NN / 32)) return;
    long base = (long)w * 32;
    unsigned bits = 0;
#pragma unroll
    for (int j = 0; j < 32; j++) bits |= (adj[base + j] > 0 ? 1u : 0u) << j;
    d_adjp[w] = bits;
}

// ---------------- 2. tf32 tensor GEMM (+ optional fused attention-score epilogue) ----
// AMODE 0: A = x gathered (K=32);  AMODE 1: A dense [m][KDIM]
// BMODE 0: B = W [K][NTOT];        BMODE 1: B[k][n] = Bw[c0+n][k]
// SFUSE 1: also compute s_src/s_dst = Out@avec and write d_eu/eu2/ev/ev2 (needs NTOT=128, gridDim.y=1)
template <int KDIM, int AMODE, int BMODE, int BIAS, int NTOT, int SFUSE>
__global__ void __launch_bounds__(256) gemm_tc(const float* __restrict__ A,
                                               const float* __restrict__ Bw,
                                               const float* __restrict__ bi1,
                                               const float* __restrict__ bi2,
                                               const float* __restrict__ avec,
                                               float* __restrict__ Out) {
    int m0 = blockIdx.x * 128;
    int c0 = blockIdx.y * 128;
    int tid = threadIdx.x, lane = tid & 31, wid = tid >> 5;
    int wm = wid >> 2, wn = wid & 3;
    int g = lane >> 2, t = lane & 3;

    __shared__ float As[128][36];
    __shared__ float Bs[128 * 36];
    __shared__ float sA[SFUSE ? 256 : 1];
    __shared__ float red[SFUSE ? 4 : 1][SFUSE ? 128 : 1][2];

    if (SFUSE) sA[tid] = avec[tid];

    float acc[4][4][4] = {};
    const int KT = KDIM / 32;

    for (int kt = 0; kt < KT; kt++) {
        int kc = kt * 32;
        {
            int r = tid >> 1, k0 = (tid & 1) * 16;
            long base;
            if (AMODE == 0) {
                int m = m0 + r;
                int n = m & (NN - 1);
                int pp = m >> 10, tt2 = pp & 15, bb2 = pp >> 4;
                base = (((long)(bb2 * NN + n) * TT + tt2) * FINN) + k0;
            } else {
                base = (long)(m0 + r) * KDIM + kc + k0;
            }
            const float* src = A + base;
#pragma unroll
            for (int q = 0; q < 4; q++) {
                float4 v = *(const float4*)(src + q * 4);
                As[r][k0 + q * 4 + 0] = __uint_as_float(tf32r(v.x));
                As[r][k0 + q * 4 + 1] = __uint_as_float(tf32r(v.y));
                As[r][k0 + q * 4 + 2] = __uint_as_float(tf32r(v.z));
                As[r][k0 + q * 4 + 3] = __uint_as_float(tf32r(v.w));
            }
        }
        if (BMODE == 0) {
            int kr = tid >> 3, cq = tid & 7;
            const float* src = Bw + (long)(kc + kr) * NTOT + c0 + cq * 16;
#pragma unroll
            for (int q = 0; q < 4; q++) {
                float4 v = *(const float4*)(src + q * 4);
                float* dst = &Bs[kr * 136 + cq * 16 + q * 4];
                dst[0] = __uint_as_float(tf32r(v.x));
                dst[1] = __uint_as_float(tf32r(v.y));
                dst[2] = __uint_as_float(tf32r(v.z));
                dst[3] = __uint_as_float(tf32r(v.w));
            }
        } else {
            int n = tid >> 1, k0 = (tid & 1) * 16;
            const float* src = Bw + (long)(c0 + n) * KDIM + kc + k0;
#pragma unroll
            for (int q = 0; q < 4; q++) {
                float4 v = *(const float4*)(src + q * 4);
                float* dst = &Bs[n * 36 + k0 + q * 4];
                dst[0] = __uint_as_float(tf32r(v.x));
                dst[1] = __uint_as_float(tf32r(v.y));
                dst[2] = __uint_as_float(tf32r(v.z));
                dst[3] = __uint_as_float(tf32r(v.w));
            }
        }
        __syncthreads();
#pragma unroll
        for (int ks = 0; ks < 4; ks++) {
            unsigned a[4][4], bf[4][2];
#pragma unroll
            for (int mf = 0; mf < 4; mf++) {
                int r = wm * 64 + mf * 16 + g;
                a[mf][0] = __float_as_uint(As[r    ][ks * 8 + t    ]);
                a[mf][1] = __float_as_uint(As[r + 8][ks * 8 + t    ]);
                a[mf][2] = __float_as_uint(As[r    ][ks * 8 + t + 4]);
                a[mf][3] = __float_as_uint(As[r + 8][ks * 8 + t + 4]);
            }
#pragma unroll
            for (int nf = 0; nf < 4; nf++) {
                int cc = wn * 32 + nf * 8 + g;
                if (BMODE == 0) {
                    bf[nf][0] = __float_as_uint(Bs[(ks * 8 + t    ) * 136 + cc]);
                    bf[nf][1] = __float_as_uint(Bs[(ks * 8 + t + 4) * 136 + cc]);
                } else {
                    bf[nf][0] = __float_as_uint(Bs[cc * 36 + ks * 8 + t    ]);
                    bf[nf][1] = __float_as_uint(Bs[cc * 36 + ks * 8 + t + 4]);
                }
            }
#pragma unroll
            for (int mf = 0; mf < 4; mf++)
#pragma unroll
                for (int nf = 0; nf < 4; nf++)
                    mma_tf32(acc[mf][nf], a[mf], bf[nf]);
        }
        __syncthreads();
    }
    // ---- store epilogue ----
#pragma unroll
    for (int mf = 0; mf < 4; mf++) {
        int r = m0 + wm * 64 + mf * 16 + g;
#pragma unroll
        for (int nf = 0; nf < 4; nf++) {
            int cc = c0 + wn * 32 + nf * 8 + 2 * t;
            float b0 = 0.f, b1 = 0.f;
            if (BIAS) {
                b0 = bi1[cc] + bi2[cc];
                b1 = bi1[cc + 1] + bi2[cc + 1];
            }
            *(float2*)&Out[(long)r * NTOT + cc] =
                make_float2(acc[mf][nf][0] + b0, acc[mf][nf][1] + b1);
            *(float2*)&Out[(long)(r + 8) * NTOT + cc] =
                make_float2(acc[mf][nf][2] + b0, acc[mf][nf][3] + b1);
        }
    }
    // ---- fused attention-score epilogue ----
    if (SFUSE) {
#pragma unroll
        for (int mf = 0; mf < 4; mf++) {
            float ps0 = 0.f, pd0 = 0.f, ps1 = 0.f, pd1 = 0.f;
#pragma unroll
            for (int nf = 0; nf < 4; nf++) {
                int cc = wn * 32 + nf * 8 + 2 * t;
#pragma unroll
                for (int dd = 0; dd < 2; dd++) {
                    float a_s = sA[cc + dd], a_d = sA[128 + cc + dd];
                    ps0 += acc[mf][nf][dd]     * a_s;
                    pd0 += acc[mf][nf][dd]     * a_d;
                    ps1 += acc[mf][nf][2 + dd] * a_s;
                    pd1 += acc[mf][nf][2 + dd] * a_d;
                }
            }
#pragma unroll
            for (int o = 1; o <= 2; o <<= 1) {
                ps0 += __shfl_xor_sync(~0u, ps0, o);
                pd0 += __shfl_xor_sync(~0u, pd0, o);
                ps1 += __shfl_xor_sync(~0u, ps1, o);
                pd1 += __shfl_xor_sync(~0u, pd1, o);
            }
            if (t == 0) {
                int r = wm * 64 + mf * 16 + g;
                red[wn][r][0] = ps0;     red[wn][r][1] = pd0;
                red[wn][r + 8][0] = ps1; red[wn][r + 8][1] = pd1;
            }
        }
        __syncthreads();
        if (tid < 128) {
            float ss = red[0][tid][0] + red[1][tid][0] + red[2][tid][0] + red[3][tid][0];
            float sd = red[0][tid][1] + red[1][tid][1] + red[2][tid][1] + red[3][tid][1];
            long m = m0 + tid;
            d_eu [m] = __expf(ss);
            d_eu2[m] = __expf(0.2f * ss);
            d_ev [m] = __expf(sd);
            d_ev2[m] = __expf(0.2f * sd);
        }
    }
}

// ---------------- 3. attention v3: register-resident P, m16 x n128 warps ----------
// 128 rows x 128 cols per block; warp wid owns rows wid*16..+16, all 128 cols.
// A-fragments (P) computed directly in registers; Wh staged bf16 transposed
// (pad 40 -> conflict-free B loads); double-buffered; one barrier per tile.
template <int LAYER>
__global__ void __launch_bounds__(256) att_v3_kernel() {
    int p = blockIdx.y, row0 = blockIdx.x * 128;
    int tid = threadIdx.x, lane = tid & 31, wid = tid >> 5;
    int b_ = p >> 4, t_ = p & 15;
    int g = lane >> 2, t = lane & 3;

    __shared__ __nv_bfloat16 WhT[2][128][40];   // [c][j]
    __shared__ float         evS[2][64];        // ev 0..31, ev2 32..63
    __shared__ unsigned      adjS[2][128];

    int rlo = wid * 16 + g;                     // local row (and rlo+8)
    float eur0  = d_eu [p * NN + row0 + rlo];
    float eu2r0 = d_eu2[p * NN + row0 + rlo];
    float eur1  = d_eu [p * NN + row0 + rlo + 8];
    float eu2r1 = d_eu2[p * NN + row0 + rlo + 8];
    float zr0 = 0.f, zr1 = 0.f;
    float acc[16][4] = {};

    const float*    Whp   = &d_Wh[(long)p * NN * HH];
    const unsigned* adjpb = &d_adjp[(long)b_ * NN * (NN / 32)];

    int jp = tid & 15, ch = tid >> 4, sc0 = ch * 8;

    auto STAGE = [&](int i, int bb) {
        int jc = i * 32;
        const float* r0p = Whp + (long)(jc + 2 * jp) * HH + sc0;
        float4 a0 = *(const float4*)r0p;
        float4 a1 = *(const float4*)(r0p + 4);
        float4 b0 = *(const float4*)(r0p + HH);
        float4 b1 = *(const float4*)(r0p + HH + 4);
        float av[8] = {a0.x, a0.y, a0.z, a0.w, a1.x, a1.y, a1.z, a1.w};
        float bv[8] = {b0.x, b0.y, b0.z, b0.w, b1.x, b1.y, b1.z, b1.w};
#pragma unroll
        for (int u = 0; u < 8; u++)
            *(unsigned*)&WhT[bb][sc0 + u][2 * jp] = packbf(av[u], bv[u]);
        if (tid < 8)
            *(float4*)&evS[bb][tid * 4] = *(const float4*)&d_ev[p * NN + jc + tid * 4];
        else if (tid < 16)
            *(float4*)&evS[bb][32 + (tid - 8) * 4] = *(const float4*)&d_ev2[p * NN + jc + (tid - 8) * 4];
        if (tid >= 32 && tid < 160)
            adjS[bb][tid - 32] = adjpb[(long)(row0 + tid - 32) * (NN / 32) + i];
    };

    STAGE(0, 0);
    __syncthreads();

    for (int i = 0; i < 32; i++) {
        int bb = i & 1;
        if (i + 1 < 32) STAGE(i + 1, bb ^ 1);

        unsigned awlo = adjS[bb][rlo], awhi = adjS[bb][rlo + 8];
#pragma unroll
        for (int ks = 0; ks < 2; ks++) {
            int j0 = ks * 16 + 2 * t;
            float e0 = evS[bb][j0],     e1 = evS[bb][j0 + 1];
            float e8 = evS[bb][j0 + 8], e9 = evS[bb][j0 + 9];
            float f0 = evS[bb][32 + j0],     f1 = evS[bb][32 + j0 + 1];
            float f8 = evS[bb][32 + j0 + 8], f9 = evS[bb][32 + j0 + 9];

            float wl0 = ((awlo >> (j0    )) & 1u) ? fmaxf(eur0 * e0, eu2r0 * f0) : 0.f;
            float wl1 = ((awlo >> (j0 + 1)) & 1u) ? fmaxf(eur0 * e1, eu2r0 * f1) : 0.f;
            float wl8 = ((awlo >> (j0 + 8)) & 1u) ? fmaxf(eur0 * e8, eu2r0 * f8) : 0.f;
            float wl9 = ((awlo >> (j0 + 9)) & 1u) ? fmaxf(eur0 * e9, eu2r0 * f9) : 0.f;
            float wh0 = ((awhi >> (j0    )) & 1u) ? fmaxf(eur1 * e0, eu2r1 * f0) : 0.f;
            float wh1 = ((awhi >> (j0 + 1)) & 1u) ? fmaxf(eur1 * e1, eu2r1 * f1) : 0.f;
            float wh8 = ((awhi >> (j0 + 8)) & 1u) ? fmaxf(eur1 * e8, eu2r1 * f8) : 0.f;
            float wh9 = ((awhi >> (j0 + 9)) & 1u) ? fmaxf(eur1 * e9, eu2r1 * f9) : 0.f;

            unsigned a[4];
            a[0] = packbf(wl0, wl1);
            a[1] = packbf(wh0, wh1);
            a[2] = packbf(wl8, wl9);
            a[3] = packbf(wh8, wh9);

            // z consistent with bf16-rounded numerator
            __nv_bfloat162 q0 = *(__nv_bfloat162*)&a[0];
            __nv_bfloat162 q2 = *(__nv_bfloat162*)&a[2];
            __nv_bfloat162 q1 = *(__nv_bfloat162*)&a[1];
            __nv_bfloat162 q3 = *(__nv_bfloat162*)&a[3];
            zr0 += __bfloat162float(q0.x) + __bfloat162float(q0.y)
                 + __bfloat162float(q2.x) + __bfloat162float(q2.y);
            zr1 += __bfloat162float(q1.x) + __bfloat162float(q1.y)
                 + __bfloat162float(q3.x) + __bfloat162float(q3.y);

#pragma unroll
            for (int nf = 0; nf < 16; nf++) {
                int cc = nf * 8 + g;
                unsigned bf[2];
                bf[0] = *(unsigned*)&WhT[bb][cc][ks * 16 + 2 * t];
                bf[1] = *(unsigned*)&WhT[bb][cc][ks * 16 + 2 * t + 8];
                mma_bf16(acc[nf], a, bf);
            }
        }
        __syncthreads();
    }

    // reduce z across t-lanes (each t covered a disjoint j subset)
    zr0 += __shfl_xor_sync(~0u, zr0, 1);
    zr0 += __shfl_xor_sync(~0u, zr0, 2);
    zr1 += __shfl_xor_sync(~0u, zr1, 1);
    zr1 += __shfl_xor_sync(~0u, zr1, 2);
    float iz0 = 1.f / zr0, iz1 = 1.f / zr1;

    int n0 = row0 + rlo, n1 = n0 + 8;
#pragma unroll
    for (int nf = 0; nf < 16; nf++) {
        int col = nf * 8 + 2 * t;
        float o0 = elu2(acc[nf][0] * iz0);
        float o1 = elu2(acc[nf][1] * iz0);
        float o2 = elu2(acc[nf][2] * iz1);
        float o3 = elu2(acc[nf][3] * iz1);
        if (LAYER == 0) {
            *(float2*)&d_h1[((long)p * NN + n0) * HH + col] = make_float2(o0, o1);
            *(float2*)&d_h1[((long)p * NN + n1) * HH + col] = make_float2(o2, o3);
        } else {
            *(float2*)&d_g[(((long)(b_ * NN + n0)) * TT + t_) * HH + col] = make_float2(o0, o1);
            *(float2*)&d_g[(((long)(b_ * NN + n1)) * TT + t_) * HH + col] = make_float2(o2, o3);
        }
    }
}

// ---------------- 6. LSTM recurrence ----------------
__global__ void lstm_kernel(const float* __restrict__ Whh) {
    extern __shared__ float sm[];
    float* WT = sm;                 // [64][257]
    float* hs = sm + 64 * 257;      // [16][68]
    int tid = threadIdx.x, lane = tid & 31, wp = tid >> 5;
    for (int idx = tid; idx < 256 * 64; idx += 256) {
        int g = idx >> 6, k = idx & 63;
        WT[k * 257 + g] = Whh[g * 64 + k];
    }
    for (int idx = tid; idx < 16 * 68; idx += 256) hs[idx] = 0.f;
    __syncthreads();

    int r0 = wp * 2, r1 = r0 + 1;
    long gr0 = (long)blockIdx.x * 16 + r0;
    long gr1 = gr0 + 1;
    float c[2][2] = {};
    float hn[2][2] = {};
    for (int tt = 0; tt < TT; tt++) {
        float acc[2][4][2];
#pragma unroll
        for (int d = 0; d < 2; d++) {
            long base = ((d ? gr1 : gr0) * TT + tt) * 256;
#pragma unroll
            for (int q = 0; q < 4; q++) {
                acc[d][q][0] = d_XG[base + q * 64 + lane];
                acc[d][q][1] = d_XG[base + q * 64 + 32 + lane];
            }
        }
#pragma unroll 8
        for (int k = 0; k < 64; k++) {
            float h0  = hs[r0 * 68 + k];
            float h1v = hs[r1 * 68 + k];
            const float* wr = &WT[k * 257];
#pragma unroll
            for (int q = 0; q < 4; q++) {
                float wv0 = wr[q * 64 + lane];
                float wv1 = wr[q * 64 + 32 + lane];
                acc[0][q][0] += wv0 * h0;  acc[0][q][1] += wv1 * h0;
                acc[1][q][0] += wv0 * h1v; acc[1][q][1] += wv1 * h1v;
            }
        }
#pragma unroll
        for (int d = 0; d < 2; d++)
#pragma unroll
            for (int u = 0; u < 2; u++) {
                float iv = sigf(acc[d][0][u]);
                float fv = sigf(acc[d][1][u]);
                float gv = tanhf_(acc[d][2][u]);
                float ov = sigf(acc[d][3][u]);
                c[d][u]  = fv * c[d][u] + iv * gv;
                hn[d][u] = ov * tanhf_(c[d][u]);
            }
        __syncthreads();
        hs[r0 * 68 + lane]      = hn[0][0];
        hs[r0 * 68 + 32 + lane] = hn[0][1];
        hs[r1 * 68 + lane]      = hn[1][0];
        hs[r1 * 68 + 32 + lane] = hn[1][1];
        __syncthreads();
    }
    d_hT[gr0 * 64 + lane]      = hn[0][0];
    d_hT[gr0 * 64 + 32 + lane] = hn[0][1];
    d_hT[gr1 * 64 + lane]      = hn[1][0];
    d_hT[gr1 * 64 + 32 + lane] = hn[1][1];
}

// ---------------- 7. output MLP ----------------
__global__ void mlp_kernel(const float* __restrict__ Wo1, const float* __restrict__ bo1,
                           const float* __restrict__ Wo2, const float* __restrict__ bo2,
                           float* __restrict__ out) {
    __shared__ float hsm[128][65];
    __shared__ float W1s[64 * 32];
    __shared__ float W2s[32];
    int tid = threadIdx.x;
    int row0 = blockIdx.x * 128;
    for (int idx = tid; idx < 64 * 32; idx += 128) W1s[idx] = Wo1[idx];
    if (tid < 32) W2s[tid] = Wo2[tid];
    for (int idx = tid; idx < 128 * 64; idx += 128) {
        int r = idx >> 6, k = idx & 63;
        hsm[r][k] = d_hT[(long)(row0 + r) * 64 + k];
    }
    __syncthreads();
    float acc[32];
#pragma unroll
    for (int j = 0; j < 32; j++) acc[j] = bo1[j];
    for (int k = 0; k < 64; k++) {
        float hk = hsm[tid][k];
#pragma unroll
        for (int j = 0; j < 32; j++) acc[j] += hk * W1s[k * 32 + j];
    }
    float o = bo2[0];
#pragma unroll
    for (int j = 0; j < 32; j++) {
        float m = acc[j] > 0.f ? acc[j] : 0.f;
        o += m * W2s[j];
    }
    out[row0 + tid] = o;
}

// ---------------- launcher ----------------
extern "C" void kernel_launch(void* const* d_in, const int* in_sizes, int n_in,
                              void* d_out, int out_size) {
    const float* x   = (const float*)d_in[0];
    const int*   adj = (const int*)  d_in[1];
    const float* W1  = (const float*)d_in[2];
    const float* a1  = (const float*)d_in[3];
    const float* W2  = (const float*)d_in[4];
    const float* a2  = (const float*)d_in[5];
    const float* Wih = (const float*)d_in[6];
    const float* Whh = (const float*)d_in[7];
    const float* bih = (const float*)d_in[8];
    const float* bhh = (const float*)d_in[9];
    const float* Wo1 = (const float*)d_in[10];
    const float* bo1 = (const float*)d_in[11];
    const float* Wo2 = (const float*)d_in[12];
    const float* bo2 = (const float*)d_in[13];
    float* out = (float*)d_out;

    float* d_Wh_p;  cudaGetSymbolAddress((void**)&d_Wh_p,  d_Wh);
    float* d_h1_p;  cudaGetSymbolAddress((void**)&d_h1_p,  d_h1);
    float* d_g_p;   cudaGetSymbolAddress((void**)&d_g_p,   d_g);
    float* d_XG_p;  cudaGetSymbolAddress((void**)&d_XG_p,  d_XG);

    pack_adj_kernel<<<512, 256>>>(adj);

    // GAT layer 1: Wh + fused scores
    gemm_tc<32, 0, 0, 0, 128, 1><<<dim3(512, 1), 256>>>(x, W1, nullptr, nullptr, a1, d_Wh_p);
    att_v3_kernel<0><<<dim3(8, 64), 256>>>();

    // GAT layer 2: Wh + fused scores
    gemm_tc<128, 1, 0, 0, 128, 1><<<dim3(512, 1), 256>>>(d_h1_p, W2, nullptr, nullptr, a2, d_Wh_p);
    att_v3_kernel<1><<<dim3(8, 64), 256>>>();

    // LSTM input gates
    gemm_tc<128, 1, 1, 1, 256, 0><<<dim3(512, 2), 256>>>(d_g_p, Wih, bih, bhh, nullptr, d_XG_p);

    // LSTM recurrence
    size_t smem = (64 * 257 + 16 * 68) * sizeof(float);
    cudaFuncSetAttribute(lstm_kernel, cudaFuncAttributeMaxDynamicSharedMemorySize, (int)smem);
    lstm_kernel<<<256, 256, smem>>>(Whh);

    // MLP
    mlp_kernel<<<32, 128>>>(Wo1, bo1, Wo2, bo2, out);
}

// round 5
// speedup vs baseline: 3.3228x; 1.1756x over previous
#include <cuda_runtime.h>
#include <cuda_bf16.h>

#define BB   4
#define NN   1024
#define TT   16
#define FINN 32
#define HH   128
#define LHID 64
#define NP   64
#define MTOT (NP * NN)

// ---------------- scratch ----------------
__device__ __nv_bfloat16 d_Whb[MTOT * HH];        // bf16 Wh (written by GEMM epilogue)
__device__ float    d_h1 [MTOT * HH];
__device__ float    d_g  [MTOT * HH];             // LSTM layout [(b*N+n)*T + t][h]
__device__ float    d_eu [MTOT];
__device__ float    d_eu2[MTOT];
__device__ float    d_ev [MTOT];
__device__ float    d_ev2[MTOT];
__device__ unsigned d_adjp[BB * NN * (NN / 32)];
__device__ float    d_XG [MTOT * 256];

// ---------------- helpers ----------------
__device__ __forceinline__ float sigf(float x)   { return 1.f / (1.f + __expf(-x)); }
__device__ __forceinline__ float tanhf_(float x) { return 1.f - 2.f / (__expf(2.f * x) + 1.f); }
__device__ __forceinline__ void mma_tf32(float* c, const unsigned* a, const unsigned* b) {
    asm volatile("mma.sync.aligned.m16n8k8.row.col.f32.tf32.tf32.f32 "
                 "{%0,%1,%2,%3}, {%4,%5,%6,%7}, {%8,%9}, {%0,%1,%2,%3};"
                 : "+f"(c[0]), "+f"(c[1]), "+f"(c[2]), "+f"(c[3])
                 : "r"(a[0]), "r"(a[1]), "r"(a[2]), "r"(a[3]), "r"(b[0]), "r"(b[1]));
}
__device__ __forceinline__ void mma_bf16(float* c, const unsigned* a, const unsigned* b) {
    asm volatile("mma.sync.aligned.m16n8k16.row.col.f32.bf16.bf16.f32 "
                 "{%0,%1,%2,%3}, {%4,%5,%6,%7}, {%8,%9}, {%0,%1,%2,%3};"
                 : "+f"(c[0]), "+f"(c[1]), "+f"(c[2]), "+f"(c[3])
                 : "r"(a[0]), "r"(a[1]), "r"(a[2]), "r"(a[3]), "r"(b[0]), "r"(b[1]));
}
__device__ __forceinline__ void ldm_x4(unsigned& r0, unsigned& r1, unsigned& r2, unsigned& r3,
                                       unsigned saddr) {
    asm volatile("ldmatrix.sync.aligned.m8n8.x4.shared.b16 {%0,%1,%2,%3}, [%4];"
                 : "=r"(r0), "=r"(r1), "=r"(r2), "=r"(r3) : "r"(saddr));
}
__device__ __forceinline__ void cpasync16(unsigned saddr, const void* g) {
    asm volatile("cp.async.ca.shared.global [%0], [%1], 16;" :: "r"(saddr), "l"(g));
}
__device__ __forceinline__ void cpcommit() { asm volatile("cp.async.commit_group;"); }
__device__ __forceinline__ float elu2(float v) {
    v = v > 0.f ? v : __expf(v) - 1.f;
    v = v > 0.f ? v : __expf(v) - 1.f;
    return v;
}
__device__ __forceinline__ unsigned packbf(float a, float b) {
    __nv_bfloat162 p = __floats2bfloat162_rn(a, b);
    return *(unsigned*)&p;
}

// ---------------- 1. pack adjacency ----------------
__global__ void pack_adj_kernel(const int* __restrict__ adj) {
    int w = blockIdx.x * blockDim.x + threadIdx.x;
    if (w >= BB * NN * (NN / 32)) return;
    long base = (long)w * 32;
    unsigned bits = 0;
#pragma unroll
    for (int j = 0; j < 32; j++) bits |= (adj[base + j] > 0 ? 1u : 0u) << j;
    d_adjp[w] = bits;
}

// ---------------- 2. tf32 tensor GEMM, cp.async double-buffered ----------------
// AMODE 0: A = x gathered (K=32);  AMODE 1: A dense [m][KDIM]
// BMODE 0: B = W [K][NTOT];        BMODE 1: B[k][n] = Bw[c0+n][k]
// SFUSE:   fused attention-score epilogue (needs NTOT=128, gridDim.y=1)
// OUTBF:   1 -> write bf16 to d_Whb, skip fp32 out
template <int KDIM, int AMODE, int BMODE, int BIAS, int NTOT, int SFUSE, int OUTBF>
__global__ void __launch_bounds__(256) gemm_tc(const float* __restrict__ A,
                                               const float* __restrict__ Bw,
                                               const float* __restrict__ bi1,
                                               const float* __restrict__ bi2,
                                               const float* __restrict__ avec,
                                               float* __restrict__ Out) {
    int m0 = blockIdx.x * 128;
    int c0 = blockIdx.y * 128;
    int tid = threadIdx.x, lane = tid & 31, wid = tid >> 5;
    int wm = wid >> 2, wn = wid & 3;
    int g = lane >> 2, t = lane & 3;

    extern __shared__ float gsm[];
    float* AsBuf = gsm;              // 2 * 4608
    float* BsBuf = gsm + 2 * 4608;   // 2 * 4608
    __shared__ float sA[SFUSE ? 256 : 1];
    __shared__ float red[SFUSE ? 4 : 1][SFUSE ? 128 : 1][2];

    if (SFUSE) sA[tid] = avec[tid];

    float acc[4][4][4] = {};
    const int KT = KDIM / 32;

    auto STAGE = [&](int kt) {
        int bb = kt & 1, kc = kt * 32;
        {
            int r = tid >> 1, k0 = (tid & 1) * 16;
            long base;
            if (AMODE == 0) {
                int m = m0 + r;
                int n = m & (NN - 1);
                int pp = m >> 10, tt2 = pp & 15, bb2 = pp >> 4;
                base = (((long)(bb2 * NN + n) * TT + tt2) * FINN) + k0;
            } else {
                base = (long)(m0 + r) * KDIM + kc + k0;
            }
            unsigned dst = (unsigned)__cvta_generic_to_shared(&AsBuf[bb * 4608 + r * 36 + k0]);
#pragma unroll
            for (int q = 0; q < 4; q++) cpasync16(dst + q * 16, A + base + q * 4);
        }
        if (BMODE == 0) {
            int kr = tid >> 3, cq = tid & 7;
            const float* src = Bw + (long)(kc + kr) * NTOT + c0 + cq * 16;
            unsigned dst = (unsigned)__cvta_generic_to_shared(&BsBuf[bb * 4608 + kr * 136 + cq * 16]);
#pragma unroll
            for (int q = 0; q < 4; q++) cpasync16(dst + q * 16, src + q * 4);
        } else {
            int n = tid >> 1, k0 = (tid & 1) * 16;
            const float* src = Bw + (long)(c0 + n) * KDIM + kc + k0;
            unsigned dst = (unsigned)__cvta_generic_to_shared(&BsBuf[bb * 4608 + n * 36 + k0]);
#pragma unroll
            for (int q = 0; q < 4; q++) cpasync16(dst + q * 16, src + q * 4);
        }
        cpcommit();
    };

    STAGE(0);
    if (KT > 1) STAGE(1);

#pragma unroll
    for (int kt = 0; kt < KT; kt++) {
        if (kt + 2 <= KT) { asm volatile("cp.async.wait_group 1;" ::: "memory"); }
        else              { asm volatile("cp.async.wait_group 0;" ::: "memory"); }
        __syncthreads();
        const float* As_ = AsBuf + (kt & 1) * 4608;
        const float* Bs_ = BsBuf + (kt & 1) * 4608;
#pragma unroll
        for (int ks = 0; ks < 4; ks++) {
            unsigned a[4][4], bf[4][2];
#pragma unroll
            for (int mf = 0; mf < 4; mf++) {
                int r = wm * 64 + mf * 16 + g;
                a[mf][0] = __float_as_uint(As_[r * 36 + ks * 8 + t]);
                a[mf][1] = __float_as_uint(As_[(r + 8) * 36 + ks * 8 + t]);
                a[mf][2] = __float_as_uint(As_[r * 36 + ks * 8 + t + 4]);
                a[mf][3] = __float_as_uint(As_[(r + 8) * 36 + ks * 8 + t + 4]);
            }
#pragma unroll
            for (int nf = 0; nf < 4; nf++) {
                int cc = wn * 32 + nf * 8 + g;
                if (BMODE == 0) {
                    bf[nf][0] = __float_as_uint(Bs_[(ks * 8 + t) * 136 + cc]);
                    bf[nf][1] = __float_as_uint(Bs_[(ks * 8 + t + 4) * 136 + cc]);
                } else {
                    bf[nf][0] = __float_as_uint(Bs_[cc * 36 + ks * 8 + t]);
                    bf[nf][1] = __float_as_uint(Bs_[cc * 36 + ks * 8 + t + 4]);
                }
            }
#pragma unroll
            for (int mf = 0; mf < 4; mf++)
#pragma unroll
                for (int nf = 0; nf < 4; nf++)
                    mma_tf32(acc[mf][nf], a[mf], bf[nf]);
        }
        __syncthreads();
        if (kt + 2 < KT) STAGE(kt + 2);
    }

    // ---- store epilogue ----
#pragma unroll
    for (int mf = 0; mf < 4; mf++) {
        int r = m0 + wm * 64 + mf * 16 + g;
#pragma unroll
        for (int nf = 0; nf < 4; nf++) {
            int cc = c0 + wn * 32 + nf * 8 + 2 * t;
            if (OUTBF) {
                *(unsigned*)&d_Whb[(long)r * HH + cc] = packbf(acc[mf][nf][0], acc[mf][nf][1]);
                *(unsigned*)&d_Whb[(long)(r + 8) * HH + cc] = packbf(acc[mf][nf][2], acc[mf][nf][3]);
            } else {
                float b0 = 0.f, b1 = 0.f;
                if (BIAS) {
                    b0 = bi1[cc] + bi2[cc];
                    b1 = bi1[cc + 1] + bi2[cc + 1];
                }
                *(float2*)&Out[(long)r * NTOT + cc] =
                    make_float2(acc[mf][nf][0] + b0, acc[mf][nf][1] + b1);
                *(float2*)&Out[(long)(r + 8) * NTOT + cc] =
                    make_float2(acc[mf][nf][2] + b0, acc[mf][nf][3] + b1);
            }
        }
    }
    // ---- fused attention-score epilogue ----
    if (SFUSE) {
#pragma unroll
        for (int mf = 0; mf < 4; mf++) {
            float ps0 = 0.f, pd0 = 0.f, ps1 = 0.f, pd1 = 0.f;
#pragma unroll
            for (int nf = 0; nf < 4; nf++) {
                int cc = wn * 32 + nf * 8 + 2 * t;
#pragma unroll
                for (int dd = 0; dd < 2; dd++) {
                    float a_s = sA[cc + dd], a_d = sA[128 + cc + dd];
                    ps0 += acc[mf][nf][dd]     * a_s;
                    pd0 += acc[mf][nf][dd]     * a_d;
                    ps1 += acc[mf][nf][2 + dd] * a_s;
                    pd1 += acc[mf][nf][2 + dd] * a_d;
                }
            }
#pragma unroll
            for (int o = 1; o <= 2; o <<= 1) {
                ps0 += __shfl_xor_sync(~0u, ps0, o);
                pd0 += __shfl_xor_sync(~0u, pd0, o);
                ps1 += __shfl_xor_sync(~0u, ps1, o);
                pd1 += __shfl_xor_sync(~0u, pd1, o);
            }
            if (t == 0) {
                int r = wm * 64 + mf * 16 + g;
                red[wn][r][0] = ps0;     red[wn][r][1] = pd0;
                red[wn][r + 8][0] = ps1; red[wn][r + 8][1] = pd1;
            }
        }
        __syncthreads();
        if (tid < 128) {
            float ss = red[0][tid][0] + red[1][tid][0] + red[2][tid][0] + red[3][tid][0];
            float sd = red[0][tid][1] + red[1][tid][1] + red[2][tid][1] + red[3][tid][1];
            long m = m0 + tid;
            d_eu [m] = __expf(ss);
            d_eu2[m] = __expf(0.2f * ss);
            d_ev [m] = __expf(sd);
            d_ev2[m] = __expf(0.2f * sd);
        }
    }
}

// ---------------- 3. attention v4: ldmatrix B, ones-column z, bf16 Wh ----------------
template <int LAYER>
__global__ void __launch_bounds__(256) att_v4_kernel() {
    int p = blockIdx.y, row0 = blockIdx.x * 128;
    int tid = threadIdx.x, lane = tid & 31, wid = tid >> 5;
    int b_ = p >> 4, t_ = p & 15;
    int g = lane >> 2, t = lane & 3;

    __shared__ __nv_bfloat16 WhT[2][128][40];   // [c][j], 80B rows
    __shared__ float         evS[2][64];
    __shared__ unsigned      adjS[2][128];

    int rlo = wid * 16 + g;
    float eur0  = d_eu [p * NN + row0 + rlo];
    float eu2r0 = d_eu2[p * NN + row0 + rlo];
    float eur1  = d_eu [p * NN + row0 + rlo + 8];
    float eu2r1 = d_eu2[p * NN + row0 + rlo + 8];
    float acc[16][4] = {};
    float accz[4] = {};
    unsigned bz = (g == 0) ? packbf(1.f, 1.f) : 0u;
    unsigned bz2[2] = {bz, bz};

    const __nv_bfloat16* Whp = &d_Whb[(long)p * NN * HH];
    const unsigned* adjpb = &d_adjp[(long)b_ * NN * (NN / 32)];

    int jp = tid & 15, ch = tid >> 4, sc0 = ch * 8;

    // ldmatrix per-thread base: matrices (2f + msel>>1, kblk = msel&1)
    int mrow = lane & 7, msel = lane >> 3;
    unsigned whsm0 = (unsigned)__cvta_generic_to_shared(&WhT[0][0][0]);
    unsigned tbase = whsm0 + ((msel >> 1) * 8 + mrow) * 80 + (msel & 1) * 16;

    auto STAGE = [&](int i, int bb) {
        int jc = i * 32;
        const __nv_bfloat16* src = Whp + (long)(jc + 2 * jp) * HH + sc0;
        uint4 ra = *(const uint4*)src;
        uint4 rb = *(const uint4*)(src + HH);
        unsigned aw[4] = {ra.x, ra.y, ra.z, ra.w};
        unsigned bw[4] = {rb.x, rb.y, rb.z, rb.w};
#pragma unroll
        for (int w = 0; w < 4; w++) {
            *(unsigned*)&WhT[bb][sc0 + 2 * w    ][2 * jp] = __byte_perm(aw[w], bw[w], 0x5410);
            *(unsigned*)&WhT[bb][sc0 + 2 * w + 1][2 * jp] = __byte_perm(aw[w], bw[w], 0x7632);
        }
        if (tid < 8)
            *(float4*)&evS[bb][tid * 4] = *(const float4*)&d_ev[p * NN + jc + tid * 4];
        else if (tid < 16)
            *(float4*)&evS[bb][32 + (tid - 8) * 4] = *(const float4*)&d_ev2[p * NN + jc + (tid - 8) * 4];
        if (tid >= 32 && tid < 160)
            adjS[bb][tid - 32] = adjpb[(long)(row0 + tid - 32) * (NN / 32) + i];
    };

    STAGE(0, 0);
    __syncthreads();

    for (int i = 0; i < 32; i++) {
        int bb = i & 1;
        if (i + 1 < 32) STAGE(i + 1, bb ^ 1);

        unsigned awlo = adjS[bb][rlo], awhi = adjS[bb][rlo + 8];
        unsigned whbb = tbase + (unsigned)(bb * 128 * 80);
#pragma unroll
        for (int ks = 0; ks < 2; ks++) {
            int j0 = ks * 16 + 2 * t;
            float2 e01 = *(const float2*)&evS[bb][j0];
            float2 e89 = *(const float2*)&evS[bb][j0 + 8];
            float2 f01 = *(const float2*)&evS[bb][32 + j0];
            float2 f89 = *(const float2*)&evS[bb][32 + j0 + 8];

            float wl0 = ((awlo >> (j0    )) & 1u) ? fmaxf(eur0 * e01.x, eu2r0 * f01.x) : 0.f;
            float wl1 = ((awlo >> (j0 + 1)) & 1u) ? fmaxf(eur0 * e01.y, eu2r0 * f01.y) : 0.f;
            float wl8 = ((awlo >> (j0 + 8)) & 1u) ? fmaxf(eur0 * e89.x, eu2r0 * f89.x) : 0.f;
            float wl9 = ((awlo >> (j0 + 9)) & 1u) ? fmaxf(eur0 * e89.y, eu2r0 * f89.y) : 0.f;
            float wh0 = ((awhi >> (j0    )) & 1u) ? fmaxf(eur1 * e01.x, eu2r1 * f01.x) : 0.f;
            float wh1 = ((awhi >> (j0 + 1)) & 1u) ? fmaxf(eur1 * e01.y, eu2r1 * f01.y) : 0.f;
            float wh8 = ((awhi >> (j0 + 8)) & 1u) ? fmaxf(eur1 * e89.x, eu2r1 * f89.x) : 0.f;
            float wh9 = ((awhi >> (j0 + 9)) & 1u) ? fmaxf(eur1 * e89.y, eu2r1 * f89.y) : 0.f;

            unsigned a[4];
            a[0] = packbf(wl0, wl1);
            a[1] = packbf(wh0, wh1);
            a[2] = packbf(wl8, wl9);
            a[3] = packbf(wh8, wh9);

            mma_bf16(accz, a, bz2);   // z accumulation (ones column)

#pragma unroll
            for (int f = 0; f < 8; f++) {
                unsigned b0, b1, b2, b3;
                ldm_x4(b0, b1, b2, b3, whbb + f * 1280 + ks * 32);
                unsigned bf0[2] = {b0, b1}, bf1[2] = {b2, b3};
                mma_bf16(acc[2 * f], a, bf0);
                mma_bf16(acc[2 * f + 1], a, bf1);
            }
        }
        __syncthreads();
    }

    // z lives in col 0 (t==0 lanes); broadcast within each quad
    float z0 = __shfl_sync(~0u, accz[0], lane & ~3);
    float z1 = __shfl_sync(~0u, accz[2], lane & ~3);
    float iz0 = 1.f / z0, iz1 = 1.f / z1;

    int n0 = row0 + rlo, n1 = n0 + 8;
#pragma unroll
    for (int nf = 0; nf < 16; nf++) {
        int col = nf * 8 + 2 * t;
        float o0 = elu2(acc[nf][0] * iz0);
        float o1 = elu2(acc[nf][1] * iz0);
        float o2 = elu2(acc[nf][2] * iz1);
        float o3 = elu2(acc[nf][3] * iz1);
        if (LAYER == 0) {
            *(float2*)&d_h1[((long)p * NN + n0) * HH + col] = make_float2(o0, o1);
            *(float2*)&d_h1[((long)p * NN + n1) * HH + col] = make_float2(o2, o3);
        } else {
            *(float2*)&d_g[(((long)(b_ * NN + n0)) * TT + t_) * HH + col] = make_float2(o0, o1);
            *(float2*)&d_g[(((long)(b_ * NN + n1)) * TT + t_) * HH + col] = make_float2(o2, o3);
        }
    }
}

// ---------------- 4. LSTM recurrence + fused output MLP ----------------
__global__ void lstm_kernel(const float* __restrict__ Whh,
                            const float* __restrict__ Wo1, const float* __restrict__ bo1,
                            const float* __restrict__ Wo2, const float* __restrict__ bo2,
                            float* __restrict__ out) {
    extern __shared__ float sm[];
    float* WT  = sm;                       // [64][257]
    float* hs  = sm + 64 * 257;            // [16][68]
    float* W1s = sm + 64 * 257 + 16 * 68;  // [64][32]
    float* W2s = W1s + 64 * 32;            // [32]
    int tid = threadIdx.x, lane = tid & 31, wp = tid >> 5;
    for (int idx = tid; idx < 256 * 64; idx += 256) {
        int g = idx >> 6, k = idx & 63;
        WT[k * 257 + g] = Whh[g * 64 + k];
    }
    for (int idx = tid; idx < 16 * 68; idx += 256) hs[idx] = 0.f;
    for (int idx = tid; idx < 64 * 32; idx += 256) W1s[idx] = Wo1[idx];
    if (tid < 32) W2s[tid] = Wo2[tid];
    __syncthreads();

    int r0 = wp * 2, r1 = r0 + 1;
    long gr0 = (long)blockIdx.x * 16 + r0;
    long gr1 = gr0 + 1;
    float c[2][2] = {};
    float hn[2][2] = {};
    for (int tt = 0; tt < TT; tt++) {
        float acc[2][4][2];
#pragma unroll
        for (int d = 0; d < 2; d++) {
            long base = ((d ? gr1 : gr0) * TT + tt) * 256;
#pragma unroll
            for (int q = 0; q < 4; q++) {
                acc[d][q][0] = d_XG[base + q * 64 + lane];
                acc[d][q][1] = d_XG[base + q * 64 + 32 + lane];
            }
        }
#pragma unroll 8
        for (int k = 0; k < 64; k++) {
            float h0  = hs[r0 * 68 + k];
            float h1v = hs[r1 * 68 + k];
            const float* wr = &WT[k * 257];
#pragma unroll
            for (int q = 0; q < 4; q++) {
                float wv0 = wr[q * 64 + lane];
                float wv1 = wr[q * 64 + 32 + lane];
                acc[0][q][0] += wv0 * h0;  acc[0][q][1] += wv1 * h0;
                acc[1][q][0] += wv0 * h1v; acc[1][q][1] += wv1 * h1v;
            }
        }
#pragma unroll
        for (int d = 0; d < 2; d++)
#pragma unroll
            for (int u = 0; u < 2; u++) {
                float iv = sigf(acc[d][0][u]);
                float fv = sigf(acc[d][1][u]);
                float gv = tanhf_(acc[d][2][u]);
                float ov = sigf(acc[d][3][u]);
                c[d][u]  = fv * c[d][u] + iv * gv;
                hn[d][u] = ov * tanhf_(c[d][u]);
            }
        __syncthreads();
        hs[r0 * 68 + lane]      = hn[0][0];
        hs[r0 * 68 + 32 + lane] = hn[0][1];
        hs[r1 * 68 + lane]      = hn[1][0];
        hs[r1 * 68 + 32 + lane] = hn[1][1];
        __syncthreads();
    }

    // fused MLP: out = relu(hT @ Wo1 + bo1) @ Wo2 + bo2
    float b1v = bo1[lane], b2v = bo2[0];
#pragma unroll
    for (int rr = 0; rr < 2; rr++) {
        int r = wp * 2 + rr;
        float a = b1v;
#pragma unroll 16
        for (int k = 0; k < 64; k++) a += hs[r * 68 + k] * W1s[k * 32 + lane];
        float m = fmaxf(a, 0.f) * W2s[lane];
#pragma unroll
        for (int o = 16; o; o >>= 1) m += __shfl_xor_sync(~0u, m, o);
        if (lane == 0) out[(long)blockIdx.x * 16 + r] = m + b2v;
    }
}

// ---------------- launcher ----------------
extern "C" void kernel_launch(void* const* d_in, const int* in_sizes, int n_in,
                              void* d_out, int out_size) {
    const float* x   = (const float*)d_in[0];
    const int*   adj = (const int*)  d_in[1];
    const float* W1  = (const float*)d_in[2];
    const float* a1  = (const float*)d_in[3];
    const float* W2  = (const float*)d_in[4];
    const float* a2  = (const float*)d_in[5];
    const float* Wih = (const float*)d_in[6];
    const float* Whh = (const float*)d_in[7];
    const float* bih = (const float*)d_in[8];
    const float* bhh = (const float*)d_in[9];
    const float* Wo1 = (const float*)d_in[10];
    const float* bo1 = (const float*)d_in[11];
    const float* Wo2 = (const float*)d_in[12];
    const float* bo2 = (const float*)d_in[13];
    float* out = (float*)d_out;

    float* d_h1_p;  cudaGetSymbolAddress((void**)&d_h1_p,  d_h1);
    float* d_g_p;   cudaGetSymbolAddress((void**)&d_g_p,   d_g);
    float* d_XG_p;  cudaGetSymbolAddress((void**)&d_XG_p,  d_XG);

    const int GSM = 4 * 4608 * sizeof(float);   // 73728 B
    cudaFuncSetAttribute((const void*)gemm_tc<32, 0, 0, 0, 128, 1, 1>,
                         cudaFuncAttributeMaxDynamicSharedMemorySize, GSM);
    cudaFuncSetAttribute((const void*)gemm_tc<128, 1, 0, 0, 128, 1, 1>,
                         cudaFuncAttributeMaxDynamicSharedMemorySize, GSM);
    cudaFuncSetAttribute((const void*)gemm_tc<128, 1, 1, 1, 256, 0, 0>,
                         cudaFuncAttributeMaxDynamicSharedMemorySize, GSM);

    pack_adj_kernel<<<512, 256>>>(adj);

    // GAT layer 1: Wh (bf16) + fused scores
    gemm_tc<32, 0, 0, 0, 128, 1, 1><<<dim3(512, 1), 256, GSM>>>(x, W1, nullptr, nullptr, a1, nullptr);
    att_v4_kernel<0><<<dim3(8, 64), 256>>>();

    // GAT layer 2
    gemm_tc<128, 1, 0, 0, 128, 1, 1><<<dim3(512, 1), 256, GSM>>>(d_h1_p, W2, nullptr, nullptr, a2, nullptr);
    att_v4_kernel<1><<<dim3(8, 64), 256>>>();

    // LSTM input gates
    gemm_tc<128, 1, 1, 1, 256, 0, 0><<<dim3(512, 2), 256, GSM>>>(d_g_p, Wih, bih, bhh, nullptr, d_XG_p);

    // LSTM recurrence + fused MLP
    size_t smem = (64 * 257 + 16 * 68 + 64 * 32 + 32) * sizeof(float);
    cudaFuncSetAttribute(lstm_kernel, cudaFuncAttributeMaxDynamicSharedMemorySize, (int)smem);
    lstm_kernel<<<256, 256, smem>>>(Whh, Wo1, bo1, Wo2, bo2, out);
}

// round 6
// speedup vs baseline: 4.2990x; 1.2938x over previous
#include <cuda_runtime.h>
#include <cuda_bf16.h>

#define BB   4
#define NN   1024
#define TT   16
#define FINN 32
#define HH   128
#define LHID 64
#define NP   64
#define MTOT (NP * NN)

// ---------------- scratch ----------------
__device__ __nv_bfloat16 d_Whb[MTOT * HH];        // bf16 Wh (written by GEMM epilogue)
__device__ float         d_h1 [MTOT * HH];
__device__ float         d_g  [MTOT * HH];        // LSTM layout [(b*N+n)*T + t][h]
__device__ __nv_bfloat16 d_evb [MTOT];            // e^{s_dst}      (bf16)
__device__ __nv_bfloat16 d_ev2b[MTOT];            // e^{0.2 s_dst}  (bf16)
__device__ float         d_r  [MTOT];             // e^{-0.8 s_src}
__device__ unsigned      d_adjp[BB * NN * (NN / 32)];
__device__ float         d_XG [MTOT * 256];

// ---------------- helpers ----------------
__device__ __forceinline__ float sigf(float x)   { return 1.f / (1.f + __expf(-x)); }
__device__ __forceinline__ float tanhf_(float x) { return 1.f - 2.f / (__expf(2.f * x) + 1.f); }
__device__ __forceinline__ void mma_tf32(float* c, const unsigned* a, const unsigned* b) {
    asm volatile("mma.sync.aligned.m16n8k8.row.col.f32.tf32.tf32.f32 "
                 "{%0,%1,%2,%3}, {%4,%5,%6,%7}, {%8,%9}, {%0,%1,%2,%3};"
                 : "+f"(c[0]), "+f"(c[1]), "+f"(c[2]), "+f"(c[3])
                 : "r"(a[0]), "r"(a[1]), "r"(a[2]), "r"(a[3]), "r"(b[0]), "r"(b[1]));
}
__device__ __forceinline__ void mma_bf16(float* c, const unsigned* a, const unsigned* b) {
    asm volatile("mma.sync.aligned.m16n8k16.row.col.f32.bf16.bf16.f32 "
                 "{%0,%1,%2,%3}, {%4,%5,%6,%7}, {%8,%9}, {%0,%1,%2,%3};"
                 : "+f"(c[0]), "+f"(c[1]), "+f"(c[2]), "+f"(c[3])
                 : "r"(a[0]), "r"(a[1]), "r"(a[2]), "r"(a[3]), "r"(b[0]), "r"(b[1]));
}
__device__ __forceinline__ void ldm_x4_trans(unsigned& r0, unsigned& r1, unsigned& r2, unsigned& r3,
                                             unsigned saddr) {
    asm volatile("ldmatrix.sync.aligned.m8n8.x4.trans.shared.b16 {%0,%1,%2,%3}, [%4];"
                 : "=r"(r0), "=r"(r1), "=r"(r2), "=r"(r3) : "r"(saddr));
}
__device__ __forceinline__ void cpasync16(unsigned saddr, const void* g) {
    asm volatile("cp.async.ca.shared.global [%0], [%1], 16;" :: "r"(saddr), "l"(g));
}
__device__ __forceinline__ void cpasync4(unsigned saddr, const void* g) {
    asm volatile("cp.async.ca.shared.global [%0], [%1], 4;" :: "r"(saddr), "l"(g));
}
__device__ __forceinline__ void cpcommit() { asm volatile("cp.async.commit_group;"); }
__device__ __forceinline__ float elu2(float v) {
    v = v > 0.f ? v : __expf(v) - 1.f;
    v = v > 0.f ? v : __expf(v) - 1.f;
    return v;
}
__device__ __forceinline__ unsigned packbf(float a, float b) {
    __nv_bfloat162 p = __floats2bfloat162_rn(a, b);
    return *(unsigned*)&p;
}
__device__ __forceinline__ unsigned bfu(__nv_bfloat162 v) { return *(unsigned*)&v; }
__device__ __forceinline__ unsigned mask2(unsigned aw, int j0) {
    unsigned m = 0;
    if ((aw >> j0) & 1u)       m |= 0x0000FFFFu;
    if ((aw >> (j0 + 1)) & 1u) m |= 0xFFFF0000u;
    return m;
}

// ---------------- 1. pack adjacency ----------------
__global__ void pack_adj_kernel(const int* __restrict__ adj) {
    int w = blockIdx.x * blockDim.x + threadIdx.x;
    if (w >= BB * NN * (NN / 32)) return;
    long base = (long)w * 32;
    unsigned bits = 0;
#pragma unroll
    for (int j = 0; j < 32; j++) bits |= (adj[base + j] > 0 ? 1u : 0u) << j;
    d_adjp[w] = bits;
}

// ---------------- 2. tf32 tensor GEMM, cp.async double-buffered ----------------
template <int KDIM, int AMODE, int BMODE, int BIAS, int NTOT, int SFUSE, int OUTBF>
__global__ void __launch_bounds__(256, 2) gemm_tc(const float* __restrict__ A,
                                                  const float* __restrict__ Bw,
                                                  const float* __restrict__ bi1,
                                                  const float* __restrict__ bi2,
                                                  const float* __restrict__ avec,
                                                  float* __restrict__ Out) {
    int m0 = blockIdx.x * 128;
    int c0 = blockIdx.y * 128;
    int tid = threadIdx.x, lane = tid & 31, wid = tid >> 5;
    int wm = wid >> 2, wn = wid & 3;
    int g = lane >> 2, t = lane & 3;

    extern __shared__ float gsm[];
    float* AsBuf = gsm;              // 2 * 4608
    float* BsBuf = gsm + 2 * 4608;   // 2 * 4608
    __shared__ float sA[SFUSE ? 256 : 1];
    __shared__ float red[SFUSE ? 4 : 1][SFUSE ? 128 : 1][2];

    if (SFUSE) sA[tid] = avec[tid];

    float acc[4][4][4] = {};
    const int KT = KDIM / 32;

    auto STAGE = [&](int kt) {
        int bb = kt & 1, kc = kt * 32;
        {
            int r = tid >> 1, k0 = (tid & 1) * 16;
            long base;
            if (AMODE == 0) {
                int m = m0 + r;
                int n = m & (NN - 1);
                int pp = m >> 10, tt2 = pp & 15, bb2 = pp >> 4;
                base = (((long)(bb2 * NN + n) * TT + tt2) * FINN) + k0;
            } else {
                base = (long)(m0 + r) * KDIM + kc + k0;
            }
            unsigned dst = (unsigned)__cvta_generic_to_shared(&AsBuf[bb * 4608 + r * 36 + k0]);
#pragma unroll
            for (int q = 0; q < 4; q++) cpasync16(dst + q * 16, A + base + q * 4);
        }
        if (BMODE == 0) {
            int kr = tid >> 3, cq = tid & 7;
            const float* src = Bw + (long)(kc + kr) * NTOT + c0 + cq * 16;
            unsigned dst = (unsigned)__cvta_generic_to_shared(&BsBuf[bb * 4608 + kr * 136 + cq * 16]);
#pragma unroll
            for (int q = 0; q < 4; q++) cpasync16(dst + q * 16, src + q * 4);
        } else {
            int n = tid >> 1, k0 = (tid & 1) * 16;
            const float* src = Bw + (long)(c0 + n) * KDIM + kc + k0;
            unsigned dst = (unsigned)__cvta_generic_to_shared(&BsBuf[bb * 4608 + n * 36 + k0]);
#pragma unroll
            for (int q = 0; q < 4; q++) cpasync16(dst + q * 16, src + q * 4);
        }
        cpcommit();
    };

    STAGE(0);
    if (KT > 1) STAGE(1);

#pragma unroll
    for (int kt = 0; kt < KT; kt++) {
        if (kt + 2 <= KT) { asm volatile("cp.async.wait_group 1;" ::: "memory"); }
        else              { asm volatile("cp.async.wait_group 0;" ::: "memory"); }
        __syncthreads();
        const float* As_ = AsBuf + (kt & 1) * 4608;
        const float* Bs_ = BsBuf + (kt & 1) * 4608;
#pragma unroll
        for (int ks = 0; ks < 4; ks++) {
            unsigned a[4][4], bf[4][2];
#pragma unroll
            for (int mf = 0; mf < 4; mf++) {
                int r = wm * 64 + mf * 16 + g;
                a[mf][0] = __float_as_uint(As_[r * 36 + ks * 8 + t]);
                a[mf][1] = __float_as_uint(As_[(r + 8) * 36 + ks * 8 + t]);
                a[mf][2] = __float_as_uint(As_[r * 36 + ks * 8 + t + 4]);
                a[mf][3] = __float_as_uint(As_[(r + 8) * 36 + ks * 8 + t + 4]);
            }
#pragma unroll
            for (int nf = 0; nf < 4; nf++) {
                int cc = wn * 32 + nf * 8 + g;
                if (BMODE == 0) {
                    bf[nf][0] = __float_as_uint(Bs_[(ks * 8 + t) * 136 + cc]);
                    bf[nf][1] = __float_as_uint(Bs_[(ks * 8 + t + 4) * 136 + cc]);
                } else {
                    bf[nf][0] = __float_as_uint(Bs_[cc * 36 + ks * 8 + t]);
                    bf[nf][1] = __float_as_uint(Bs_[cc * 36 + ks * 8 + t + 4]);
                }
            }
#pragma unroll
            for (int mf = 0; mf < 4; mf++)
#pragma unroll
                for (int nf = 0; nf < 4; nf++)
                    mma_tf32(acc[mf][nf], a[mf], bf[nf]);
        }
        __syncthreads();
        if (kt + 2 < KT) STAGE(kt + 2);
    }

    // ---- store epilogue ----
#pragma unroll
    for (int mf = 0; mf < 4; mf++) {
        int r = m0 + wm * 64 + mf * 16 + g;
#pragma unroll
        for (int nf = 0; nf < 4; nf++) {
            int cc = c0 + wn * 32 + nf * 8 + 2 * t;
            if (OUTBF) {
                *(unsigned*)&d_Whb[(long)r * HH + cc] = packbf(acc[mf][nf][0], acc[mf][nf][1]);
                *(unsigned*)&d_Whb[(long)(r + 8) * HH + cc] = packbf(acc[mf][nf][2], acc[mf][nf][3]);
            } else {
                float b0 = 0.f, b1 = 0.f;
                if (BIAS) {
                    b0 = bi1[cc] + bi2[cc];
                    b1 = bi1[cc + 1] + bi2[cc + 1];
                }
                *(float2*)&Out[(long)r * NTOT + cc] =
                    make_float2(acc[mf][nf][0] + b0, acc[mf][nf][1] + b1);
                *(float2*)&Out[(long)(r + 8) * NTOT + cc] =
                    make_float2(acc[mf][nf][2] + b0, acc[mf][nf][3] + b1);
            }
        }
    }
    // ---- fused attention-score epilogue ----
    if (SFUSE) {
#pragma unroll
        for (int mf = 0; mf < 4; mf++) {
            float ps0 = 0.f, pd0 = 0.f, ps1 = 0.f, pd1 = 0.f;
#pragma unroll
            for (int nf = 0; nf < 4; nf++) {
                int cc = wn * 32 + nf * 8 + 2 * t;
#pragma unroll
                for (int dd = 0; dd < 2; dd++) {
                    float a_s = sA[cc + dd], a_d = sA[128 + cc + dd];
                    ps0 += acc[mf][nf][dd]     * a_s;
                    pd0 += acc[mf][nf][dd]     * a_d;
                    ps1 += acc[mf][nf][2 + dd] * a_s;
                    pd1 += acc[mf][nf][2 + dd] * a_d;
                }
            }
#pragma unroll
            for (int o = 1; o <= 2; o <<= 1) {
                ps0 += __shfl_xor_sync(~0u, ps0, o);
                pd0 += __shfl_xor_sync(~0u, pd0, o);
                ps1 += __shfl_xor_sync(~0u, ps1, o);
                pd1 += __shfl_xor_sync(~0u, pd1, o);
            }
            if (t == 0) {
                int r = wm * 64 + mf * 16 + g;
                red[wn][r][0] = ps0;     red[wn][r][1] = pd0;
                red[wn][r + 8][0] = ps1; red[wn][r + 8][1] = pd1;
            }
        }
        __syncthreads();
        if (tid < 128) {
            float ss = red[0][tid][0] + red[1][tid][0] + red[2][tid][0] + red[3][tid][0];
            float sd = red[0][tid][1] + red[1][tid][1] + red[2][tid][1] + red[3][tid][1];
            long m = m0 + tid;
            d_evb [m] = __float2bfloat16(__expf(sd));
            d_ev2b[m] = __float2bfloat16(__expf(0.2f * sd));
            d_r   [m] = __expf(-0.8f * ss);
        }
    }
}

// ---------------- 3. attention v5: cp.async + ldmatrix.trans + scale-free P ----------
// p'_ij = mask * max(ev_j, r_i * ev2_j)   (softmax invariant to the dropped e^{u_i})
template <int LAYER>
__global__ void __launch_bounds__(256) att_v5_kernel() {
    int p = blockIdx.y, row0 = blockIdx.x * 128;
    int tid = threadIdx.x, lane = tid & 31, wid = tid >> 5;
    int b_ = p >> 4, t_ = p & 15;
    int g = lane >> 2, t = lane & 3;

    __shared__ alignas(16) __nv_bfloat16 WhS[3][32][136];   // natural [j][col], row 272B
    __shared__ alignas(16) __nv_bfloat16 evS [3][32];
    __shared__ alignas(16) __nv_bfloat16 ev2S[3][32];
    __shared__ unsigned adjS[3][128];

    int rlo = wid * 16 + g;
    float r0f = d_r[p * NN + row0 + rlo];
    float r1f = d_r[p * NN + row0 + rlo + 8];
    unsigned r02 = packbf(r0f, r0f);
    unsigned r12 = packbf(r1f, r1f);

    float acc[16][4] = {};
    float accz[4] = {};
    unsigned bz = (g == 0) ? packbf(1.f, 1.f) : 0u;
    unsigned bz2[2] = {bz, bz};

    const __nv_bfloat16* Whp = &d_Whb[(long)p * NN * HH];
    const unsigned* adjpb = &d_adjp[(long)b_ * NN * (NN / 32)];

    unsigned whbase  = (unsigned)__cvta_generic_to_shared(&WhS[0][0][0]);
    unsigned evbase  = (unsigned)__cvta_generic_to_shared(&evS[0][0]);
    unsigned ev2base = (unsigned)__cvta_generic_to_shared(&ev2S[0][0]);
    unsigned adjbase = (unsigned)__cvta_generic_to_shared(&adjS[0][0]);
    unsigned laneoff = (lane & 15) * 272 + (lane >> 4) * 16;

    int js = tid >> 4, seg = tid & 15;

    auto STAGE = [&](int i) {
        int bb = i % 3, jc = i * 32;
        const __nv_bfloat16* src = Whp + (long)(jc + js) * HH + seg * 8;
        unsigned dst = whbase + bb * 8704 + js * 272 + seg * 16;
        cpasync16(dst, src);
        cpasync16(dst + 16 * 272, src + 16 * HH);
        if (tid < 4)
            cpasync16(evbase + bb * 64 + tid * 16, &d_evb[p * NN + jc + tid * 8]);
        else if (tid < 8)
            cpasync16(ev2base + bb * 64 + (tid - 4) * 16, &d_ev2b[p * NN + jc + (tid - 4) * 8]);
        if (tid >= 64 && tid < 192)
            cpasync4(adjbase + bb * 512 + (tid - 64) * 4,
                     adjpb + (long)(row0 + tid - 64) * (NN / 32) + i);
        cpcommit();
    };

    STAGE(0);
    STAGE(1);

    for (int i = 0; i < 32; i++) {
        if (i < 31) { asm volatile("cp.async.wait_group 1;" ::: "memory"); }
        else        { asm volatile("cp.async.wait_group 0;" ::: "memory"); }
        __syncthreads();
        if (i + 2 < 32) STAGE(i + 2);

        int bb = i % 3;
        unsigned awlo = adjS[bb][rlo], awhi = adjS[bb][rlo + 8];
        unsigned kb0 = whbase + bb * 8704 + laneoff;
#pragma unroll
        for (int ks = 0; ks < 2; ks++) {
            int j0 = ks * 16 + 2 * t;
            __nv_bfloat162 evp  = *(__nv_bfloat162*)&evS [bb][j0];
            __nv_bfloat162 evp8 = *(__nv_bfloat162*)&evS [bb][j0 + 8];
            __nv_bfloat162 e2p  = *(__nv_bfloat162*)&ev2S[bb][j0];
            __nv_bfloat162 e2p8 = *(__nv_bfloat162*)&ev2S[bb][j0 + 8];
            __nv_bfloat162 r0b = *(__nv_bfloat162*)&r02;
            __nv_bfloat162 r1b = *(__nv_bfloat162*)&r12;

            unsigned a[4];
            a[0] = bfu(__hmax2(evp,  __hmul2(r0b, e2p)))  & mask2(awlo, j0);
            a[1] = bfu(__hmax2(evp,  __hmul2(r1b, e2p)))  & mask2(awhi, j0);
            a[2] = bfu(__hmax2(evp8, __hmul2(r0b, e2p8))) & mask2(awlo, j0 + 8);
            a[3] = bfu(__hmax2(evp8, __hmul2(r1b, e2p8))) & mask2(awhi, j0 + 8);

            mma_bf16(accz, a, bz2);

            unsigned kbase = kb0 + ks * 4352;
#pragma unroll
            for (int nc = 0; nc < 8; nc++) {
                unsigned b0, b1, b2, b3;
                ldm_x4_trans(b0, b1, b2, b3, kbase + nc * 32);
                unsigned bf0[2] = {b0, b1}, bf1[2] = {b2, b3};
                mma_bf16(acc[2 * nc], a, bf0);
                mma_bf16(acc[2 * nc + 1], a, bf1);
            }
        }
    }

    float z0 = __shfl_sync(~0u, accz[0], lane & ~3);
    float z1 = __shfl_sync(~0u, accz[2], lane & ~3);
    float iz0 = 1.f / z0, iz1 = 1.f / z1;

    int n0 = row0 + rlo, n1 = n0 + 8;
#pragma unroll
    for (int nf = 0; nf < 16; nf++) {
        int col = nf * 8 + 2 * t;
        float o0 = elu2(acc[nf][0] * iz0);
        float o1 = elu2(acc[nf][1] * iz0);
        float o2 = elu2(acc[nf][2] * iz1);
        float o3 = elu2(acc[nf][3] * iz1);
        if (LAYER == 0) {
            *(float2*)&d_h1[((long)p * NN + n0) * HH + col] = make_float2(o0, o1);
            *(float2*)&d_h1[((long)p * NN + n1) * HH + col] = make_float2(o2, o3);
        } else {
            *(float2*)&d_g[(((long)(b_ * NN + n0)) * TT + t_) * HH + col] = make_float2(o0, o1);
            *(float2*)&d_g[(((long)(b_ * NN + n1)) * TT + t_) * HH + col] = make_float2(o2, o3);
        }
    }
}

// ---------------- 4. LSTM recurrence + fused output MLP ----------------
__global__ void lstm_kernel(const float* __restrict__ Whh,
                            const float* __restrict__ Wo1, const float* __restrict__ bo1,
                            const float* __restrict__ Wo2, const float* __restrict__ bo2,
                            float* __restrict__ out) {
    extern __shared__ float sm[];
    float* WT  = sm;                       // [64][257]
    float* hs  = sm + 64 * 257;            // [16][68]
    float* W1s = sm + 64 * 257 + 16 * 68;  // [64][32]
    float* W2s = W1s + 64 * 32;            // [32]
    int tid = threadIdx.x, lane = tid & 31, wp = tid >> 5;
    for (int idx = tid; idx < 256 * 64; idx += 256) {
        int g = idx >> 6, k = idx & 63;
        WT[k * 257 + g] = Whh[g * 64 + k];
    }
    for (int idx = tid; idx < 16 * 68; idx += 256) hs[idx] = 0.f;
    for (int idx = tid; idx < 64 * 32; idx += 256) W1s[idx] = Wo1[idx];
    if (tid < 32) W2s[tid] = Wo2[tid];
    __syncthreads();

    int r0 = wp * 2, r1 = r0 + 1;
    long gr0 = (long)blockIdx.x * 16 + r0;
    long gr1 = gr0 + 1;
    float c[2][2] = {};
    float hn[2][2] = {};
    for (int tt = 0; tt < TT; tt++) {
        float acc[2][4][2];
#pragma unroll
        for (int d = 0; d < 2; d++) {
            long base = ((d ? gr1 : gr0) * TT + tt) * 256;
#pragma unroll
            for (int q = 0; q < 4; q++) {
                acc[d][q][0] = d_XG[base + q * 64 + lane];
                acc[d][q][1] = d_XG[base + q * 64 + 32 + lane];
            }
        }
#pragma unroll 8
        for (int k = 0; k < 64; k++) {
            float h0  = hs[r0 * 68 + k];
            float h1v = hs[r1 * 68 + k];
            const float* wr = &WT[k * 257];
#pragma unroll
            for (int q = 0; q < 4; q++) {
                float wv0 = wr[q * 64 + lane];
                float wv1 = wr[q * 64 + 32 + lane];
                acc[0][q][0] += wv0 * h0;  acc[0][q][1] += wv1 * h0;
                acc[1][q][0] += wv0 * h1v; acc[1][q][1] += wv1 * h1v;
            }
        }
#pragma unroll
        for (int d = 0; d < 2; d++)
#pragma unroll
            for (int u = 0; u < 2; u++) {
                float iv = sigf(acc[d][0][u]);
                float fv = sigf(acc[d][1][u]);
                float gv = tanhf_(acc[d][2][u]);
                float ov = sigf(acc[d][3][u]);
                c[d][u]  = fv * c[d][u] + iv * gv;
                hn[d][u] = ov * tanhf_(c[d][u]);
            }
        __syncthreads();
        hs[r0 * 68 + lane]      = hn[0][0];
        hs[r0 * 68 + 32 + lane] = hn[0][1];
        hs[r1 * 68 + lane]      = hn[1][0];
        hs[r1 * 68 + 32 + lane] = hn[1][1];
        __syncthreads();
    }

    float b1v = bo1[lane], b2v = bo2[0];
#pragma unroll
    for (int rr = 0; rr < 2; rr++) {
        int r = wp * 2 + rr;
        float a = b1v;
#pragma unroll 16
        for (int k = 0; k < 64; k++) a += hs[r * 68 + k] * W1s[k * 32 + lane];
        float m = fmaxf(a, 0.f) * W2s[lane];
#pragma unroll
        for (int o = 16; o; o >>= 1) m += __shfl_xor_sync(~0u, m, o);
        if (lane == 0) out[(long)blockIdx.x * 16 + r] = m + b2v;
    }
}

// ---------------- launcher ----------------
extern "C" void kernel_launch(void* const* d_in, const int* in_sizes, int n_in,
                              void* d_out, int out_size) {
    const float* x   = (const float*)d_in[0];
    const int*   adj = (const int*)  d_in[1];
    const float* W1  = (const float*)d_in[2];
    const float* a1  = (const float*)d_in[3];
    const float* W2  = (const float*)d_in[4];
    const float* a2  = (const float*)d_in[5];
    const float* Wih = (const float*)d_in[6];
    const float* Whh = (const float*)d_in[7];
    const float* bih = (const float*)d_in[8];
    const float* bhh = (const float*)d_in[9];
    const float* Wo1 = (const float*)d_in[10];
    const float* bo1 = (const float*)d_in[11];
    const float* Wo2 = (const float*)d_in[12];
    const float* bo2 = (const float*)d_in[13];
    float* out = (float*)d_out;

    float* d_h1_p;  cudaGetSymbolAddress((void**)&d_h1_p,  d_h1);
    float* d_g_p;   cudaGetSymbolAddress((void**)&d_g_p,   d_g);
    float* d_XG_p;  cudaGetSymbolAddress((void**)&d_XG_p,  d_XG);

    const int GSM = 4 * 4608 * sizeof(float);   // 73728 B
    cudaFuncSetAttribute((const void*)gemm_tc<32, 0, 0, 0, 128, 1, 1>,
                         cudaFuncAttributeMaxDynamicSharedMemorySize, GSM);
    cudaFuncSetAttribute((const void*)gemm_tc<128, 1, 0, 0, 128, 1, 1>,
                         cudaFuncAttributeMaxDynamicSharedMemorySize, GSM);
    cudaFuncSetAttribute((const void*)gemm_tc<128, 1, 1, 1, 256, 0, 0>,
                         cudaFuncAttributeMaxDynamicSharedMemorySize, GSM);

    pack_adj_kernel<<<512, 256>>>(adj);

    // GAT layer 1: Wh (bf16) + fused scores
    gemm_tc<32, 0, 0, 0, 128, 1, 1><<<dim3(512, 1), 256, GSM>>>(x, W1, nullptr, nullptr, a1, nullptr);
    att_v5_kernel<0><<<dim3(8, 64), 256>>>();

    // GAT layer 2
    gemm_tc<128, 1, 0, 0, 128, 1, 1><<<dim3(512, 1), 256, GSM>>>(d_h1_p, W2, nullptr, nullptr, a2, nullptr);
    att_v5_kernel<1><<<dim3(8, 64), 256>>>();

    // LSTM input gates
    gemm_tc<128, 1, 1, 1, 256, 0, 0><<<dim3(512, 2), 256, GSM>>>(d_g_p, Wih, bih, bhh, nullptr, d_XG_p);

    // LSTM recurrence + fused MLP
    size_t smem = (64 * 257 + 16 * 68 + 64 * 32 + 32) * sizeof(float);
    cudaFuncSetAttribute(lstm_kernel, cudaFuncAttributeMaxDynamicSharedMemorySize, (int)smem);
    lstm_kernel<<<256, 256, smem>>>(Whh, Wo1, bo1, Wo2, bo2, out);
}

// round 7
// speedup vs baseline: 4.4840x; 1.0430x over previous
#include <cuda_runtime.h>
#include <cuda_bf16.h>

#define BB   4
#define NN   1024
#define TT   16
#define FINN 32
#define HH   128
#define LHID 64
#define NP   64
#define MTOT (NP * NN)

// ---------------- scratch ----------------
__device__ __nv_bfloat16 d_Whb[MTOT * HH];        // bf16 Wh (GEMM epilogue output)
__device__ __nv_bfloat16 d_h1b[MTOT * HH];        // bf16 layer-1 output
__device__ __nv_bfloat16 d_gb [MTOT * HH];        // bf16 layer-2 output, LSTM layout
__device__ __nv_bfloat16 d_evb [MTOT];
__device__ __nv_bfloat16 d_ev2b[MTOT];
__device__ float         d_r  [MTOT];             // e^{-0.8 s_src}
__device__ unsigned      d_adjp[BB * NN * (NN / 32)];
__device__ float         d_XG [MTOT * 256];
__device__ __nv_bfloat16 d_W2b [HH * HH];         // W2 transposed -> [n][k] bf16
__device__ __nv_bfloat16 d_Wihb[256 * HH];        // Wih [gate][k] bf16 (already [n][k])

// ---------------- helpers ----------------
__device__ __forceinline__ float sigf(float x)   { return 1.f / (1.f + __expf(-x)); }
__device__ __forceinline__ float tanhf_(float x) { return 1.f - 2.f / (__expf(2.f * x) + 1.f); }
__device__ __forceinline__ void mma_tf32(float* c, const unsigned* a, const unsigned* b) {
    asm volatile("mma.sync.aligned.m16n8k8.row.col.f32.tf32.tf32.f32 "
                 "{%0,%1,%2,%3}, {%4,%5,%6,%7}, {%8,%9}, {%0,%1,%2,%3};"
                 : "+f"(c[0]), "+f"(c[1]), "+f"(c[2]), "+f"(c[3])
                 : "r"(a[0]), "r"(a[1]), "r"(a[2]), "r"(a[3]), "r"(b[0]), "r"(b[1]));
}
__device__ __forceinline__ void mma_bf16(float* c, const unsigned* a, const unsigned* b) {
    asm volatile("mma.sync.aligned.m16n8k16.row.col.f32.bf16.bf16.f32 "
                 "{%0,%1,%2,%3}, {%4,%5,%6,%7}, {%8,%9}, {%0,%1,%2,%3};"
                 : "+f"(c[0]), "+f"(c[1]), "+f"(c[2]), "+f"(c[3])
                 : "r"(a[0]), "r"(a[1]), "r"(a[2]), "r"(a[3]), "r"(b[0]), "r"(b[1]));
}
__device__ __forceinline__ void ldm_x4(unsigned& r0, unsigned& r1, unsigned& r2, unsigned& r3,
                                       unsigned saddr) {
    asm volatile("ldmatrix.sync.aligned.m8n8.x4.shared.b16 {%0,%1,%2,%3}, [%4];"
                 : "=r"(r0), "=r"(r1), "=r"(r2), "=r"(r3) : "r"(saddr));
}
__device__ __forceinline__ void ldm_x4_trans(unsigned& r0, unsigned& r1, unsigned& r2, unsigned& r3,
                                             unsigned saddr) {
    asm volatile("ldmatrix.sync.aligned.m8n8.x4.trans.shared.b16 {%0,%1,%2,%3}, [%4];"
                 : "=r"(r0), "=r"(r1), "=r"(r2), "=r"(r3) : "r"(saddr));
}
__device__ __forceinline__ void cpasync16(unsigned saddr, const void* g) {
    asm volatile("cp.async.ca.shared.global [%0], [%1], 16;" :: "r"(saddr), "l"(g));
}
__device__ __forceinline__ void cpasync4(unsigned saddr, const void* g) {
    asm volatile("cp.async.ca.shared.global [%0], [%1], 4;" :: "r"(saddr), "l"(g));
}
__device__ __forceinline__ void cpcommit() { asm volatile("cp.async.commit_group;"); }
__device__ __forceinline__ float elu2(float v) {
    v = v > 0.f ? v : __expf(v) - 1.f;
    v = v > 0.f ? v : __expf(v) - 1.f;
    return v;
}
__device__ __forceinline__ unsigned packbf(float a, float b) {
    __nv_bfloat162 p = __floats2bfloat162_rn(a, b);
    return *(unsigned*)&p;
}
__device__ __forceinline__ unsigned bfu(__nv_bfloat162 v) { return *(unsigned*)&v; }
__device__ __forceinline__ unsigned mask2(unsigned aw, int j0) {
    unsigned m = 0;
    if ((aw >> j0) & 1u)       m |= 0x0000FFFFu;
    if ((aw >> (j0 + 1)) & 1u) m |= 0xFFFF0000u;
    return m;
}

// ---------------- 0. weight prep (fp32 -> bf16, W2 transposed) ----------------
__global__ void prep_w(const float* __restrict__ W2, const float* __restrict__ Wih) {
    int idx = blockIdx.x * blockDim.x + threadIdx.x;
    if (idx < HH * HH) {
        int n = idx >> 7, k = idx & 127;
        d_W2b[idx] = __float2bfloat16(W2[k * HH + n]);
    }
    if (idx < 256 * HH)
        d_Wihb[idx] = __float2bfloat16(Wih[idx]);
}

// ---------------- 1. pack adjacency ----------------
__global__ void pack_adj_kernel(const int* __restrict__ adj) {
    int w = blockIdx.x * blockDim.x + threadIdx.x;
    if (w >= BB * NN * (NN / 32)) return;
    long base = (long)w * 32;
    unsigned bits = 0;
#pragma unroll
    for (int j = 0; j < 32; j++) bits |= (adj[base + j] > 0 ? 1u : 0u) << j;
    d_adjp[w] = bits;
}

// ---------------- 2a. tf32 GEMM (layer 1 only: x gathered, K=32) ----------------
__global__ void __launch_bounds__(256, 2) gemm_l1(const float* __restrict__ A,
                                                  const float* __restrict__ Bw,
                                                  const float* __restrict__ avec) {
    int m0 = blockIdx.x * 128;
    int tid = threadIdx.x, lane = tid & 31, wid = tid >> 5;
    int wm = wid >> 2, wn = wid & 3;
    int g = lane >> 2, t = lane & 3;

    extern __shared__ float gsm[];
    float* As = gsm;             // [128][36]
    float* Bs = gsm + 4608;      // [32][136]
    __shared__ float sA[256];
    __shared__ float red[4][128][2];

    sA[tid] = avec[tid];

    float acc[4][4][4] = {};
    {
        int r = tid >> 1, k0 = (tid & 1) * 16;
        int m = m0 + r;
        int n = m & (NN - 1);
        int pp = m >> 10, tt2 = pp & 15, bb2 = pp >> 4;
        long base = (((long)(bb2 * NN + n) * TT + tt2) * FINN) + k0;
        unsigned dst = (unsigned)__cvta_generic_to_shared(&As[r * 36 + k0]);
#pragma unroll
        for (int q = 0; q < 4; q++) cpasync16(dst + q * 16, A + base + q * 4);
    }
    {
        int kr = tid >> 3, cq = tid & 7;
        const float* src = Bw + (long)kr * HH + cq * 16;
        unsigned dst = (unsigned)__cvta_generic_to_shared(&Bs[kr * 136 + cq * 16]);
#pragma unroll
        for (int q = 0; q < 4; q++) cpasync16(dst + q * 16, src + q * 4);
    }
    cpcommit();
    asm volatile("cp.async.wait_group 0;" ::: "memory");
    __syncthreads();

#pragma unroll
    for (int ks = 0; ks < 4; ks++) {
        unsigned a[4][4], bf[4][2];
#pragma unroll
        for (int mf = 0; mf < 4; mf++) {
            int r = wm * 64 + mf * 16 + g;
            a[mf][0] = __float_as_uint(As[r * 36 + ks * 8 + t]);
            a[mf][1] = __float_as_uint(As[(r + 8) * 36 + ks * 8 + t]);
            a[mf][2] = __float_as_uint(As[r * 36 + ks * 8 + t + 4]);
            a[mf][3] = __float_as_uint(As[(r + 8) * 36 + ks * 8 + t + 4]);
        }
#pragma unroll
        for (int nf = 0; nf < 4; nf++) {
            int cc = wn * 32 + nf * 8 + g;
            bf[nf][0] = __float_as_uint(Bs[(ks * 8 + t) * 136 + cc]);
            bf[nf][1] = __float_as_uint(Bs[(ks * 8 + t + 4) * 136 + cc]);
        }
#pragma unroll
        for (int mf = 0; mf < 4; mf++)
#pragma unroll
            for (int nf = 0; nf < 4; nf++)
                mma_tf32(acc[mf][nf], a[mf], bf[nf]);
    }

    // store bf16 Wh + fused scores
#pragma unroll
    for (int mf = 0; mf < 4; mf++) {
        int r = m0 + wm * 64 + mf * 16 + g;
#pragma unroll
        for (int nf = 0; nf < 4; nf++) {
            int cc = wn * 32 + nf * 8 + 2 * t;
            *(unsigned*)&d_Whb[(long)r * HH + cc] = packbf(acc[mf][nf][0], acc[mf][nf][1]);
            *(unsigned*)&d_Whb[(long)(r + 8) * HH + cc] = packbf(acc[mf][nf][2], acc[mf][nf][3]);
        }
    }
#pragma unroll
    for (int mf = 0; mf < 4; mf++) {
        float ps0 = 0.f, pd0 = 0.f, ps1 = 0.f, pd1 = 0.f;
#pragma unroll
        for (int nf = 0; nf < 4; nf++) {
            int cc = wn * 32 + nf * 8 + 2 * t;
#pragma unroll
            for (int dd = 0; dd < 2; dd++) {
                float a_s = sA[cc + dd], a_d = sA[128 + cc + dd];
                ps0 += acc[mf][nf][dd]     * a_s;
                pd0 += acc[mf][nf][dd]     * a_d;
                ps1 += acc[mf][nf][2 + dd] * a_s;
                pd1 += acc[mf][nf][2 + dd] * a_d;
            }
        }
#pragma unroll
        for (int o = 1; o <= 2; o <<= 1) {
            ps0 += __shfl_xor_sync(~0u, ps0, o);
            pd0 += __shfl_xor_sync(~0u, pd0, o);
            ps1 += __shfl_xor_sync(~0u, ps1, o);
            pd1 += __shfl_xor_sync(~0u, pd1, o);
        }
        if (t == 0) {
            int r = wm * 64 + mf * 16 + g;
            red[wn][r][0] = ps0;     red[wn][r][1] = pd0;
            red[wn][r + 8][0] = ps1; red[wn][r + 8][1] = pd1;
        }
    }
    __syncthreads();
    if (tid < 128) {
        float ss = red[0][tid][0] + red[1][tid][0] + red[2][tid][0] + red[3][tid][0];
        float sd = red[0][tid][1] + red[1][tid][1] + red[2][tid][1] + red[3][tid][1];
        long m = m0 + tid;
        d_evb [m] = __float2bfloat16(__expf(sd));
        d_ev2b[m] = __float2bfloat16(__expf(0.2f * sd));
        d_r   [m] = __expf(-0.8f * ss);
    }
}

// ---------------- 2b. bf16 GEMM (K=128): A[m][128] bf16, B[n][128] bf16 -------------
// SFUSE 1: fused score epilogue + bf16 out to d_Whb (layer 2; NTOT=128, gridDim.y=1)
// SFUSE 0: fp32 out + bias (xg; NTOT=256)
template <int BIAS, int NTOT, int SFUSE>
__global__ void __launch_bounds__(256, 2) gemm_bf(const __nv_bfloat16* __restrict__ A,
                                                  const __nv_bfloat16* __restrict__ Bw,
                                                  const float* __restrict__ bi1,
                                                  const float* __restrict__ bi2,
                                                  const float* __restrict__ avec,
                                                  float* __restrict__ Out) {
    int m0 = blockIdx.x * 128;
    int c0 = blockIdx.y * 128;
    int tid = threadIdx.x, lane = tid & 31, wid = tid >> 5;
    int wm = wid >> 2, wn = wid & 3;
    int g = lane >> 2, t = lane & 3;

    extern __shared__ __nv_bfloat16 bsm[];     // As [128][136], Bs [128][136]
    unsigned asmem = (unsigned)__cvta_generic_to_shared(&bsm[0]);
    unsigned bsmem = asmem + 128 * 272;
    __shared__ float sA[SFUSE ? 256 : 1];
    __shared__ float red[SFUSE ? 4 : 1][SFUSE ? 128 : 1][2];

    if (SFUSE) sA[tid] = avec[tid];

    // stage A and B whole-K (64 KB)
    {
        int r = tid >> 1, h = (tid & 1) * 8;
        const __nv_bfloat16* asrc = A + (long)(m0 + r) * HH + h * 8;
        const __nv_bfloat16* bsrc = Bw + (long)(c0 + r) * HH + h * 8;
        unsigned adst = asmem + r * 272 + h * 16;
        unsigned bdst = bsmem + r * 272 + h * 16;
#pragma unroll
        for (int q = 0; q < 8; q++) {
            cpasync16(adst + q * 16, asrc + q * 8);
            cpasync16(bdst + q * 16, bsrc + q * 8);
        }
    }
    cpcommit();

    int mrow = lane & 7, msel = lane >> 3;
    unsigned aLane = asmem + ((msel & 1) * 8 + mrow) * 272 + (msel >> 1) * 16
                   + (wm * 64) * 272;
    unsigned bLane = bsmem + ((msel >> 1) * 8 + mrow) * 272 + (msel & 1) * 16
                   + (wn * 32) * 272;

    float acc[4][4][4] = {};
    asm volatile("cp.async.wait_group 0;" ::: "memory");
    __syncthreads();

#pragma unroll
    for (int ks = 0; ks < 8; ks++) {
        unsigned a[4][4], bf[4][2];
#pragma unroll
        for (int mf = 0; mf < 4; mf++)
            ldm_x4(a[mf][0], a[mf][1], a[mf][2], a[mf][3],
                   aLane + mf * 16 * 272 + ks * 32);
#pragma unroll
        for (int pr = 0; pr < 2; pr++) {
            unsigned t0, t1, t2, t3;
            ldm_x4(t0, t1, t2, t3, bLane + pr * 16 * 272 + ks * 32);
            bf[2 * pr][0] = t0; bf[2 * pr][1] = t1;
            bf[2 * pr + 1][0] = t2; bf[2 * pr + 1][1] = t3;
        }
#pragma unroll
        for (int mf = 0; mf < 4; mf++)
#pragma unroll
            for (int nf = 0; nf < 4; nf++)
                mma_bf16(acc[mf][nf], a[mf], bf[nf]);
    }

    // ---- epilogue ----
#pragma unroll
    for (int mf = 0; mf < 4; mf++) {
        int r = m0 + wm * 64 + mf * 16 + g;
#pragma unroll
        for (int nf = 0; nf < 4; nf++) {
            int cc = c0 + wn * 32 + nf * 8 + 2 * t;
            if (SFUSE) {
                *(unsigned*)&d_Whb[(long)r * HH + cc] = packbf(acc[mf][nf][0], acc[mf][nf][1]);
                *(unsigned*)&d_Whb[(long)(r + 8) * HH + cc] = packbf(acc[mf][nf][2], acc[mf][nf][3]);
            } else {
                float b0 = 0.f, b1 = 0.f;
                if (BIAS) {
                    b0 = bi1[cc] + bi2[cc];
                    b1 = bi1[cc + 1] + bi2[cc + 1];
                }
                *(float2*)&Out[(long)r * NTOT + cc] =
                    make_float2(acc[mf][nf][0] + b0, acc[mf][nf][1] + b1);
                *(float2*)&Out[(long)(r + 8) * NTOT + cc] =
                    make_float2(acc[mf][nf][2] + b0, acc[mf][nf][3] + b1);
            }
        }
    }
    if (SFUSE) {
#pragma unroll
        for (int mf = 0; mf < 4; mf++) {
            float ps0 = 0.f, pd0 = 0.f, ps1 = 0.f, pd1 = 0.f;
#pragma unroll
            for (int nf = 0; nf < 4; nf++) {
                int cc = wn * 32 + nf * 8 + 2 * t;
#pragma unroll
                for (int dd = 0; dd < 2; dd++) {
                    float a_s = sA[cc + dd], a_d = sA[128 + cc + dd];
                    ps0 += acc[mf][nf][dd]     * a_s;
                    pd0 += acc[mf][nf][dd]     * a_d;
                    ps1 += acc[mf][nf][2 + dd] * a_s;
                    pd1 += acc[mf][nf][2 + dd] * a_d;
                }
            }
#pragma unroll
            for (int o = 1; o <= 2; o <<= 1) {
                ps0 += __shfl_xor_sync(~0u, ps0, o);
                pd0 += __shfl_xor_sync(~0u, pd0, o);
                ps1 += __shfl_xor_sync(~0u, ps1, o);
                pd1 += __shfl_xor_sync(~0u, pd1, o);
            }
            if (t == 0) {
                int r = wm * 64 + mf * 16 + g;
                red[wn][r][0] = ps0;     red[wn][r][1] = pd0;
                red[wn][r + 8][0] = ps1; red[wn][r + 8][1] = pd1;
            }
        }
        __syncthreads();
        if (tid < 128) {
            float ss = red[0][tid][0] + red[1][tid][0] + red[2][tid][0] + red[3][tid][0];
            float sd = red[0][tid][1] + red[1][tid][1] + red[2][tid][1] + red[3][tid][1];
            long m = m0 + tid;
            d_evb [m] = __float2bfloat16(__expf(sd));
            d_ev2b[m] = __float2bfloat16(__expf(0.2f * sd));
            d_r   [m] = __expf(-0.8f * ss);
        }
    }
}

// ---------------- 3. attention v5 (bf16 outputs) ----------------
template <int LAYER>
__global__ void __launch_bounds__(256) att_v5_kernel() {
    int p = blockIdx.y, row0 = blockIdx.x * 128;
    int tid = threadIdx.x, lane = tid & 31, wid = tid >> 5;
    int b_ = p >> 4, t_ = p & 15;
    int g = lane >> 2, t = lane & 3;

    __shared__ alignas(16) __nv_bfloat16 WhS[3][32][136];
    __shared__ alignas(16) __nv_bfloat16 evS [3][32];
    __shared__ alignas(16) __nv_bfloat16 ev2S[3][32];
    __shared__ unsigned adjS[3][128];

    int rlo = wid * 16 + g;
    float r0f = d_r[p * NN + row0 + rlo];
    float r1f = d_r[p * NN + row0 + rlo + 8];
    unsigned r02 = packbf(r0f, r0f);
    unsigned r12 = packbf(r1f, r1f);

    float acc[16][4] = {};
    float accz[4] = {};
    unsigned bz = (g == 0) ? packbf(1.f, 1.f) : 0u;
    unsigned bz2[2] = {bz, bz};

    const __nv_bfloat16* Whp = &d_Whb[(long)p * NN * HH];
    const unsigned* adjpb = &d_adjp[(long)b_ * NN * (NN / 32)];

    unsigned whbase  = (unsigned)__cvta_generic_to_shared(&WhS[0][0][0]);
    unsigned evbase  = (unsigned)__cvta_generic_to_shared(&evS[0][0]);
    unsigned ev2base = (unsigned)__cvta_generic_to_shared(&ev2S[0][0]);
    unsigned adjbase = (unsigned)__cvta_generic_to_shared(&adjS[0][0]);
    unsigned laneoff = (lane & 15) * 272 + (lane >> 4) * 16;

    int js = tid >> 4, seg = tid & 15;

    auto STAGE = [&](int i) {
        int bb = i % 3, jc = i * 32;
        const __nv_bfloat16* src = Whp + (long)(jc + js) * HH + seg * 8;
        unsigned dst = whbase + bb * 8704 + js * 272 + seg * 16;
        cpasync16(dst, src);
        cpasync16(dst + 16 * 272, src + 16 * HH);
        if (tid < 4)
            cpasync16(evbase + bb * 64 + tid * 16, &d_evb[p * NN + jc + tid * 8]);
        else if (tid < 8)
            cpasync16(ev2base + bb * 64 + (tid - 4) * 16, &d_ev2b[p * NN + jc + (tid - 4) * 8]);
        if (tid >= 64 && tid < 192)
            cpasync4(adjbase + bb * 512 + (tid - 64) * 4,
                     adjpb + (long)(row0 + tid - 64) * (NN / 32) + i);
        cpcommit();
    };

    STAGE(0);
    STAGE(1);

    for (int i = 0; i < 32; i++) {
        if (i < 31) { asm volatile("cp.async.wait_group 1;" ::: "memory"); }
        else        { asm volatile("cp.async.wait_group 0;" ::: "memory"); }
        __syncthreads();
        if (i + 2 < 32) STAGE(i + 2);

        int bb = i % 3;
        unsigned awlo = adjS[bb][rlo], awhi = adjS[bb][rlo + 8];
        unsigned kb0 = whbase + bb * 8704 + laneoff;
#pragma unroll
        for (int ks = 0; ks < 2; ks++) {
            int j0 = ks * 16 + 2 * t;
            __nv_bfloat162 evp  = *(__nv_bfloat162*)&evS [bb][j0];
            __nv_bfloat162 evp8 = *(__nv_bfloat162*)&evS [bb][j0 + 8];
            __nv_bfloat162 e2p  = *(__nv_bfloat162*)&ev2S[bb][j0];
            __nv_bfloat162 e2p8 = *(__nv_bfloat162*)&ev2S[bb][j0 + 8];
            __nv_bfloat162 r0b = *(__nv_bfloat162*)&r02;
            __nv_bfloat162 r1b = *(__nv_bfloat162*)&r12;

            unsigned a[4];
            a[0] = bfu(__hmax2(evp,  __hmul2(r0b, e2p)))  & mask2(awlo, j0);
            a[1] = bfu(__hmax2(evp,  __hmul2(r1b, e2p)))  & mask2(awhi, j0);
            a[2] = bfu(__hmax2(evp8, __hmul2(r0b, e2p8))) & mask2(awlo, j0 + 8);
            a[3] = bfu(__hmax2(evp8, __hmul2(r1b, e2p8))) & mask2(awhi, j0 + 8);

            mma_bf16(accz, a, bz2);

            unsigned kbase = kb0 + ks * 4352;
#pragma unroll
            for (int nc = 0; nc < 8; nc++) {
                unsigned b0, b1, b2, b3;
                ldm_x4_trans(b0, b1, b2, b3, kbase + nc * 32);
                unsigned bf0[2] = {b0, b1}, bf1[2] = {b2, b3};
                mma_bf16(acc[2 * nc], a, bf0);
                mma_bf16(acc[2 * nc + 1], a, bf1);
            }
        }
    }

    float z0 = __shfl_sync(~0u, accz[0], lane & ~3);
    float z1 = __shfl_sync(~0u, accz[2], lane & ~3);
    float iz0 = 1.f / z0, iz1 = 1.f / z1;

    int n0 = row0 + rlo, n1 = n0 + 8;
#pragma unroll
    for (int nf = 0; nf < 16; nf++) {
        int col = nf * 8 + 2 * t;
        float o0 = elu2(acc[nf][0] * iz0);
        float o1 = elu2(acc[nf][1] * iz0);
        float o2 = elu2(acc[nf][2] * iz1);
        float o3 = elu2(acc[nf][3] * iz1);
        if (LAYER == 0) {
            *(unsigned*)&d_h1b[((long)p * NN + n0) * HH + col] = packbf(o0, o1);
            *(unsigned*)&d_h1b[((long)p * NN + n1) * HH + col] = packbf(o2, o3);
        } else {
            *(unsigned*)&d_gb[(((long)(b_ * NN + n0)) * TT + t_) * HH + col] = packbf(o0, o1);
            *(unsigned*)&d_gb[(((long)(b_ * NN + n1)) * TT + t_) * HH + col] = packbf(o2, o3);
        }
    }
}

// ---------------- 4. LSTM recurrence + fused output MLP ----------------
__global__ void lstm_kernel(const float* __restrict__ Whh,
                            const float* __restrict__ Wo1, const float* __restrict__ bo1,
                            const float* __restrict__ Wo2, const float* __restrict__ bo2,
                            float* __restrict__ out) {
    extern __shared__ float sm[];
    float* WT  = sm;                       // [64][257]
    float* hs  = sm + 64 * 257;            // [16][68]
    float* W1s = sm + 64 * 257 + 16 * 68;  // [64][32]
    float* W2s = W1s + 64 * 32;            // [32]
    int tid = threadIdx.x, lane = tid & 31, wp = tid >> 5;
    for (int idx = tid; idx < 256 * 64; idx += 256) {
        int g = idx >> 6, k = idx & 63;
        WT[k * 257 + g] = Whh[g * 64 + k];
    }
    for (int idx = tid; idx < 16 * 68; idx += 256) hs[idx] = 0.f;
    for (int idx = tid; idx < 64 * 32; idx += 256) W1s[idx] = Wo1[idx];
    if (tid < 32) W2s[tid] = Wo2[tid];
    __syncthreads();

    int r0 = wp * 2, r1 = r0 + 1;
    long gr0 = (long)blockIdx.x * 16 + r0;
    long gr1 = gr0 + 1;
    float c[2][2] = {};
    float hn[2][2] = {};
    for (int tt = 0; tt < TT; tt++) {
        float acc[2][4][2];
#pragma unroll
        for (int d = 0; d < 2; d++) {
            long base = ((d ? gr1 : gr0) * TT + tt) * 256;
#pragma unroll
            for (int q = 0; q < 4; q++) {
                acc[d][q][0] = d_XG[base + q * 64 + lane];
                acc[d][q][1] = d_XG[base + q * 64 + 32 + lane];
            }
        }
#pragma unroll 8
        for (int k = 0; k < 64; k++) {
            float h0  = hs[r0 * 68 + k];
            float h1v = hs[r1 * 68 + k];
            const float* wr = &WT[k * 257];
#pragma unroll
            for (int q = 0; q < 4; q++) {
                float wv0 = wr[q * 64 + lane];
                float wv1 = wr[q * 64 + 32 + lane];
                acc[0][q][0] += wv0 * h0;  acc[0][q][1] += wv1 * h0;
                acc[1][q][0] += wv0 * h1v; acc[1][q][1] += wv1 * h1v;
            }
        }
#pragma unroll
        for (int d = 0; d < 2; d++)
#pragma unroll
            for (int u = 0; u < 2; u++) {
                float iv = sigf(acc[d][0][u]);
                float fv = sigf(acc[d][1][u]);
                float gv = tanhf_(acc[d][2][u]);
                float ov = sigf(acc[d][3][u]);
                c[d][u]  = fv * c[d][u] + iv * gv;
                hn[d][u] = ov * tanhf_(c[d][u]);
            }
        __syncthreads();
        hs[r0 * 68 + lane]      = hn[0][0];
        hs[r0 * 68 + 32 + lane] = hn[0][1];
        hs[r1 * 68 + lane]      = hn[1][0];
        hs[r1 * 68 + 32 + lane] = hn[1][1];
        __syncthreads();
    }

    float b1v = bo1[lane], b2v = bo2[0];
#pragma unroll
    for (int rr = 0; rr < 2; rr++) {
        int r = wp * 2 + rr;
        float a = b1v;
#pragma unroll 16
        for (int k = 0; k < 64; k++) a += hs[r * 68 + k] * W1s[k * 32 + lane];
        float m = fmaxf(a, 0.f) * W2s[lane];
#pragma unroll
        for (int o = 16; o; o >>= 1) m += __shfl_xor_sync(~0u, m, o);
        if (lane == 0) out[(long)blockIdx.x * 16 + r] = m + b2v;
    }
}

// ---------------- launcher ----------------
extern "C" void kernel_launch(void* const* d_in, const int* in_sizes, int n_in,
                              void* d_out, int out_size) {
    const float* x   = (const float*)d_in[0];
    const int*   adj = (const int*)  d_in[1];
    const float* W1  = (const float*)d_in[2];
    const float* a1  = (const float*)d_in[3];
    const float* W2  = (const float*)d_in[4];
    const float* a2  = (const float*)d_in[5];
    const float* Wih = (const float*)d_in[6];
    const float* Whh = (const float*)d_in[7];
    const float* bih = (const float*)d_in[8];
    const float* bhh = (const float*)d_in[9];
    const float* Wo1 = (const float*)d_in[10];
    const float* bo1 = (const float*)d_in[11];
    const float* Wo2 = (const float*)d_in[12];
    const float* bo2 = (const float*)d_in[13];
    float* out = (float*)d_out;

    __nv_bfloat16* d_h1b_p; cudaGetSymbolAddress((void**)&d_h1b_p, d_h1b);
    __nv_bfloat16* d_gb_p;  cudaGetSymbolAddress((void**)&d_gb_p,  d_gb);
    __nv_bfloat16* d_W2b_p; cudaGetSymbolAddress((void**)&d_W2b_p, d_W2b);
    __nv_bfloat16* d_Wihb_p;cudaGetSymbolAddress((void**)&d_Wihb_p,d_Wihb);
    float* d_XG_p;          cudaGetSymbolAddress((void**)&d_XG_p,  d_XG);

    const int L1SM = (4608 + 32 * 136) * sizeof(float);        // 36992 B
    const int BFSM = 2 * 128 * 272;                            // 69632 B
    cudaFuncSetAttribute((const void*)gemm_l1,
                         cudaFuncAttributeMaxDynamicSharedMemorySize, L1SM);
    cudaFuncSetAttribute((const void*)gemm_bf<0, 128, 1>,
                         cudaFuncAttributeMaxDynamicSharedMemorySize, BFSM);
    cudaFuncSetAttribute((const void*)gemm_bf<1, 256, 0>,
                         cudaFuncAttributeMaxDynamicSharedMemorySize, BFSM);

    pack_adj_kernel<<<512, 256>>>(adj);
    prep_w<<<128, 256>>>(W2, Wih);

    // GAT layer 1
    gemm_l1<<<512, 256, L1SM>>>(x, W1, a1);
    att_v5_kernel<0><<<dim3(8, 64), 256>>>();

    // GAT layer 2 (bf16 GEMM)
    gemm_bf<0, 128, 1><<<dim3(512, 1), 256, BFSM>>>(d_h1b_p, d_W2b_p, nullptr, nullptr, a2, nullptr);
    att_v5_kernel<1><<<dim3(8, 64), 256>>>();

    // LSTM input gates (bf16 GEMM, fp32 out)
    gemm_bf<1, 256, 0><<<dim3(512, 2), 256, BFSM>>>(d_gb_p, d_Wihb_p, bih, bhh, nullptr, d_XG_p);

    // LSTM recurrence + fused MLP
    size_t smem = (64 * 257 + 16 * 68 + 64 * 32 + 32) * sizeof(float);
    cudaFuncSetAttribute(lstm_kernel, cudaFuncAttributeMaxDynamicSharedMemorySize, (int)smem);
    lstm_kernel<<<256, 256, smem>>>(Whh, Wo1, bo1, Wo2, bo2, out);
}

// round 11
// speedup vs baseline: 4.6070x; 1.0274x over previous
#include <cuda_runtime.h>
#include <cuda_bf16.h>
#include <cstdint>

#define BB   4
#define NN   1024
#define TT   16
#define FINN 32
#define HH   128
#define LHID 64
#define NP   64
#define MTOT (NP * NN)

// ---------------- scratch ----------------
__device__ __nv_bfloat16 d_Whb[MTOT * HH];        // bf16 Wh (GEMM epilogue output, row-major)
__device__ __nv_bfloat16 d_h1b[MTOT * HH];        // bf16 layer-1 output [p][n][h]
__device__ __nv_bfloat16 d_gb [MTOT * HH];        // bf16 layer-2 output [p][n][h]
__device__ __nv_bfloat16 d_evb [MTOT];
__device__ __nv_bfloat16 d_ev2b[MTOT];
__device__ float         d_r  [MTOT];             // e^{-0.8 s_src}
__device__ unsigned      d_adjp[BB * NN * (NN / 32)];
__device__ float         d_XG [MTOT * 256];
__device__ __nv_bfloat16 d_W2b [HH * HH];         // W2 transposed -> [n][k] bf16
__device__ __nv_bfloat16 d_Wihb[256 * HH];        // Wih [gate][k] bf16

// ---------------- helpers ----------------
__device__ __forceinline__ float sigf(float x)   { return 1.f / (1.f + __expf(-x)); }
__device__ __forceinline__ float tanhf_(float x) { return 1.f - 2.f / (__expf(2.f * x) + 1.f); }
__device__ __forceinline__ void mma_tf32(float* c, const unsigned* a, const unsigned* b) {
    asm volatile("mma.sync.aligned.m16n8k8.row.col.f32.tf32.tf32.f32 "
                 "{%0,%1,%2,%3}, {%4,%5,%6,%7}, {%8,%9}, {%0,%1,%2,%3};"
                 : "+f"(c[0]), "+f"(c[1]), "+f"(c[2]), "+f"(c[3])
                 : "r"(a[0]), "r"(a[1]), "r"(a[2]), "r"(a[3]), "r"(b[0]), "r"(b[1]));
}
__device__ __forceinline__ void mma_bf16(float* c, const unsigned* a, const unsigned* b) {
    asm volatile("mma.sync.aligned.m16n8k16.row.col.f32.bf16.bf16.f32 "
                 "{%0,%1,%2,%3}, {%4,%5,%6,%7}, {%8,%9}, {%0,%1,%2,%3};"
                 : "+f"(c[0]), "+f"(c[1]), "+f"(c[2]), "+f"(c[3])
                 : "r"(a[0]), "r"(a[1]), "r"(a[2]), "r"(a[3]), "r"(b[0]), "r"(b[1]));
}
__device__ __forceinline__ void ldm_x4(unsigned& r0, unsigned& r1, unsigned& r2, unsigned& r3,
                                       unsigned saddr) {
    asm volatile("ldmatrix.sync.aligned.m8n8.x4.shared.b16 {%0,%1,%2,%3}, [%4];"
                 : "=r"(r0), "=r"(r1), "=r"(r2), "=r"(r3) : "r"(saddr));
}
__device__ __forceinline__ void ldm_x4_trans(unsigned& r0, unsigned& r1, unsigned& r2, unsigned& r3,
                                             unsigned saddr) {
    asm volatile("ldmatrix.sync.aligned.m8n8.x4.trans.shared.b16 {%0,%1,%2,%3}, [%4];"
                 : "=r"(r0), "=r"(r1), "=r"(r2), "=r"(r3) : "r"(saddr));
}
__device__ __forceinline__ void cpasync16(unsigned saddr, const void* g) {
    asm volatile("cp.async.ca.shared.global [%0], [%1], 16;" :: "r"(saddr), "l"(g));
}
__device__ __forceinline__ void cpcommit() { asm volatile("cp.async.commit_group;"); }
__device__ __forceinline__ float elu2(float v) {
    v = v > 0.f ? v : __expf(v) - 1.f;
    v = v > 0.f ? v : __expf(v) - 1.f;
    return v;
}
__device__ __forceinline__ unsigned packbf(float a, float b) {
    __nv_bfloat162 p = __floats2bfloat162_rn(a, b);
    return *(unsigned*)&p;
}
__device__ __forceinline__ unsigned bfu(__nv_bfloat162 v) { return *(unsigned*)&v; }
__device__ __forceinline__ unsigned mask2(unsigned aw, int j0) {
    unsigned m = 0;
    if ((aw >> j0) & 1u)       m |= 0x0000FFFFu;
    if ((aw >> (j0 + 1)) & 1u) m |= 0xFFFF0000u;
    return m;
}

// ---------------- 1. prep: pack adjacency + bf16 weights (one launch) ----------------
__global__ void prep_all(const int* __restrict__ adj,
                         const float* __restrict__ W2, const float* __restrict__ Wih) {
    int idx = blockIdx.x * blockDim.x + threadIdx.x;   // 131072 threads
    if (idx < BB * NN * (NN / 32)) {
        long base = (long)idx * 32;
        unsigned bits = 0;
#pragma unroll
        for (int j = 0; j < 32; j++) bits |= (adj[base + j] > 0 ? 1u : 0u) << j;
        d_adjp[idx] = bits;
    }
    if (idx < HH * HH) {
        int n = idx >> 7, k = idx & 127;
        d_W2b[idx] = __float2bfloat16(W2[k * HH + n]);
    }
    if (idx < 256 * HH)
        d_Wihb[idx] = __float2bfloat16(Wih[idx]);
}

// ---------------- 2a. tf32 GEMM (layer 1: x gathered, K=32) -> d_Whb + scores ----
__global__ void __launch_bounds__(256, 2) gemm_l1(const float* __restrict__ A,
                                                  const float* __restrict__ Bw,
                                                  const float* __restrict__ avec) {
    int m0 = blockIdx.x * 128;
    int tid = threadIdx.x, lane = tid & 31, wid = tid >> 5;
    int wm = wid >> 2, wn = wid & 3;
    int g = lane >> 2, t = lane & 3;

    extern __shared__ float gsm[];
    float* As = gsm;             // [128][36]
    float* Bs = gsm + 4608;      // [32][136]
    __shared__ float sA[256];
    __shared__ float red[4][128][2];

    sA[tid] = avec[tid];

    float acc[4][4][4] = {};
    {
        int r = tid >> 1, k0 = (tid & 1) * 16;
        int m = m0 + r;
        int n = m & (NN - 1);
        int pp = m >> 10, tt2 = pp & 15, bb2 = pp >> 4;
        long base = (((long)(bb2 * NN + n) * TT + tt2) * FINN) + k0;
        unsigned dst = (unsigned)__cvta_generic_to_shared(&As[r * 36 + k0]);
#pragma unroll
        for (int q = 0; q < 4; q++) cpasync16(dst + q * 16, A + base + q * 4);
    }
    {
        int kr = tid >> 3, cq = tid & 7;
        const float* src = Bw + (long)kr * HH + cq * 16;
        unsigned dst = (unsigned)__cvta_generic_to_shared(&Bs[kr * 136 + cq * 16]);
#pragma unroll
        for (int q = 0; q < 4; q++) cpasync16(dst + q * 16, src + q * 4);
    }
    cpcommit();
    asm volatile("cp.async.wait_group 0;" ::: "memory");
    __syncthreads();

#pragma unroll
    for (int ks = 0; ks < 4; ks++) {
        unsigned a[4][4], bf[4][2];
#pragma unroll
        for (int mf = 0; mf < 4; mf++) {
            int r = wm * 64 + mf * 16 + g;
            a[mf][0] = __float_as_uint(As[r * 36 + ks * 8 + t]);
            a[mf][1] = __float_as_uint(As[(r + 8) * 36 + ks * 8 + t]);
            a[mf][2] = __float_as_uint(As[r * 36 + ks * 8 + t + 4]);
            a[mf][3] = __float_as_uint(As[(r + 8) * 36 + ks * 8 + t + 4]);
        }
#pragma unroll
        for (int nf = 0; nf < 4; nf++) {
            int cc = wn * 32 + nf * 8 + g;
            bf[nf][0] = __float_as_uint(Bs[(ks * 8 + t) * 136 + cc]);
            bf[nf][1] = __float_as_uint(Bs[(ks * 8 + t + 4) * 136 + cc]);
        }
#pragma unroll
        for (int mf = 0; mf < 4; mf++)
#pragma unroll
            for (int nf = 0; nf < 4; nf++)
                mma_tf32(acc[mf][nf], a[mf], bf[nf]);
    }

    // store bf16 Wh + fused scores
#pragma unroll
    for (int mf = 0; mf < 4; mf++) {
        int r = m0 + wm * 64 + mf * 16 + g;
#pragma unroll
        for (int nf = 0; nf < 4; nf++) {
            int cc = wn * 32 + nf * 8 + 2 * t;
            *(unsigned*)&d_Whb[(long)r * HH + cc] = packbf(acc[mf][nf][0], acc[mf][nf][1]);
            *(unsigned*)&d_Whb[(long)(r + 8) * HH + cc] = packbf(acc[mf][nf][2], acc[mf][nf][3]);
        }
    }
#pragma unroll
    for (int mf = 0; mf < 4; mf++) {
        float ps0 = 0.f, pd0 = 0.f, ps1 = 0.f, pd1 = 0.f;
#pragma unroll
        for (int nf = 0; nf < 4; nf++) {
            int cc = wn * 32 + nf * 8 + 2 * t;
#pragma unroll
            for (int dd = 0; dd < 2; dd++) {
                float a_s = sA[cc + dd], a_d = sA[128 + cc + dd];
                ps0 += acc[mf][nf][dd]     * a_s;
                pd0 += acc[mf][nf][dd]     * a_d;
                ps1 += acc[mf][nf][2 + dd] * a_s;
                pd1 += acc[mf][nf][2 + dd] * a_d;
            }
        }
#pragma unroll
        for (int o = 1; o <= 2; o <<= 1) {
            ps0 += __shfl_xor_sync(~0u, ps0, o);
            pd0 += __shfl_xor_sync(~0u, pd0, o);
            ps1 += __shfl_xor_sync(~0u, ps1, o);
            pd1 += __shfl_xor_sync(~0u, pd1, o);
        }
        if (t == 0) {
            int r = wm * 64 + mf * 16 + g;
            red[wn][r][0] = ps0;     red[wn][r][1] = pd0;
            red[wn][r + 8][0] = ps1; red[wn][r + 8][1] = pd1;
        }
    }
    __syncthreads();
    if (tid < 128) {
        float ss = red[0][tid][0] + red[1][tid][0] + red[2][tid][0] + red[3][tid][0];
        float sd = red[0][tid][1] + red[1][tid][1] + red[2][tid][1] + red[3][tid][1];
        long m = m0 + tid;
        d_evb [m] = __float2bfloat16(__expf(sd));
        d_ev2b[m] = __float2bfloat16(__expf(0.2f * sd));
        d_r   [m] = __expf(-0.8f * ss);
    }
}

// ---------------- 2b. bf16 GEMM (K=128) ----------------
// AMODE 0: A dense rows [m][128];  AMODE 1: A = d_gb gathered via (b,t,n) for xg
// SFUSE 1: bf16 out -> d_Whb + fused scores (layer 2; NTOT=128, gridDim.y=1)
// SFUSE 0: fp32 out + bias (xg; NTOT=256)
template <int BIAS, int NTOT, int SFUSE, int AMODE>
__global__ void __launch_bounds__(256, 2) gemm_bf(const __nv_bfloat16* __restrict__ A,
                                                  const __nv_bfloat16* __restrict__ Bw,
                                                  const float* __restrict__ bi1,
                                                  const float* __restrict__ bi2,
                                                  const float* __restrict__ avec,
                                                  float* __restrict__ Out) {
    int m0 = blockIdx.x * 128;
    int c0 = blockIdx.y * 128;
    int tid = threadIdx.x, lane = tid & 31, wid = tid >> 5;
    int wm = wid >> 2, wn = wid & 3;
    int g = lane >> 2, t = lane & 3;

    extern __shared__ __nv_bfloat16 bsm[];
    unsigned asmem = (unsigned)__cvta_generic_to_shared(&bsm[0]);
    unsigned bsmem = asmem + 128 * 272;
    __shared__ float sA[SFUSE ? 256 : 1];
    __shared__ float red[SFUSE ? 4 : 1][SFUSE ? 128 : 1][2];

    if (SFUSE) sA[tid] = avec[tid];

    {
        int r = tid >> 1, h = (tid & 1) * 8;
        long arow;
        if (AMODE == 0) {
            arow = (long)(m0 + r) * HH;
        } else {
            int m = m0 + r;
            int tt2 = m & 15, bn = m >> 4;
            int n = bn & (NN - 1), b = bn >> 10;
            arow = ((long)(b * TT + tt2) * NN + n) * HH;   // d_gb [p][n][h]
        }
        const __nv_bfloat16* asrc = A + arow + h * 8;
        const __nv_bfloat16* bsrc = Bw + (long)(c0 + r) * HH + h * 8;
        unsigned adst = asmem + r * 272 + h * 16;
        unsigned bdst = bsmem + r * 272 + h * 16;
#pragma unroll
        for (int q = 0; q < 8; q++) {
            cpasync16(adst + q * 16, asrc + q * 8);
            cpasync16(bdst + q * 16, bsrc + q * 8);
        }
    }
    cpcommit();

    int mrow = lane & 7, msel = lane >> 3;
    unsigned aLane = asmem + ((msel & 1) * 8 + mrow) * 272 + (msel >> 1) * 16 + (wm * 64) * 272;
    unsigned bLane = bsmem + ((msel >> 1) * 8 + mrow) * 272 + (msel & 1) * 16 + (wn * 32) * 272;

    float acc[4][4][4] = {};
    asm volatile("cp.async.wait_group 0;" ::: "memory");
    __syncthreads();

#pragma unroll
    for (int ks = 0; ks < 8; ks++) {
        unsigned a[4][4], bf[4][2];
#pragma unroll
        for (int mf = 0; mf < 4; mf++)
            ldm_x4(a[mf][0], a[mf][1], a[mf][2], a[mf][3], aLane + mf * 16 * 272 + ks * 32);
#pragma unroll
        for (int pr = 0; pr < 2; pr++) {
            unsigned t0, t1, t2, t3;
            ldm_x4(t0, t1, t2, t3, bLane + pr * 16 * 272 + ks * 32);
            bf[2 * pr][0] = t0; bf[2 * pr][1] = t1;
            bf[2 * pr + 1][0] = t2; bf[2 * pr + 1][1] = t3;
        }
#pragma unroll
        for (int mf = 0; mf < 4; mf++)
#pragma unroll
            for (int nf = 0; nf < 4; nf++)
                mma_bf16(acc[mf][nf], a[mf], bf[nf]);
    }

#pragma unroll
    for (int mf = 0; mf < 4; mf++) {
        int m = m0 + wm * 64 + mf * 16 + g;
#pragma unroll
        for (int nf = 0; nf < 4; nf++) {
            int cc = c0 + wn * 32 + nf * 8 + 2 * t;
            if (SFUSE) {
                *(unsigned*)&d_Whb[(long)m * HH + cc] = packbf(acc[mf][nf][0], acc[mf][nf][1]);
                *(unsigned*)&d_Whb[(long)(m + 8) * HH + cc] = packbf(acc[mf][nf][2], acc[mf][nf][3]);
            } else {
                float b0 = 0.f, b1 = 0.f;
                if (BIAS) {
                    b0 = bi1[cc] + bi2[cc];
                    b1 = bi1[cc + 1] + bi2[cc + 1];
                }
                *(float2*)&Out[(long)m * NTOT + cc] =
                    make_float2(acc[mf][nf][0] + b0, acc[mf][nf][1] + b1);
                *(float2*)&Out[(long)(m + 8) * NTOT + cc] =
                    make_float2(acc[mf][nf][2] + b0, acc[mf][nf][3] + b1);
            }
        }
    }
    if (SFUSE) {
#pragma unroll
        for (int mf = 0; mf < 4; mf++) {
            float ps0 = 0.f, pd0 = 0.f, ps1 = 0.f, pd1 = 0.f;
#pragma unroll
            for (int nf = 0; nf < 4; nf++) {
                int cc = wn * 32 + nf * 8 + 2 * t;
#pragma unroll
                for (int dd = 0; dd < 2; dd++) {
                    float a_s = sA[cc + dd], a_d = sA[128 + cc + dd];
                    ps0 += acc[mf][nf][dd]     * a_s;
                    pd0 += acc[mf][nf][dd]     * a_d;
                    ps1 += acc[mf][nf][2 + dd] * a_s;
                    pd1 += acc[mf][nf][2 + dd] * a_d;
                }
            }
#pragma unroll
            for (int o = 1; o <= 2; o <<= 1) {
                ps0 += __shfl_xor_sync(~0u, ps0, o);
                pd0 += __shfl_xor_sync(~0u, pd0, o);
                ps1 += __shfl_xor_sync(~0u, ps1, o);
                pd1 += __shfl_xor_sync(~0u, pd1, o);
            }
            if (t == 0) {
                int r = wm * 64 + mf * 16 + g;
                red[wn][r][0] = ps0;     red[wn][r][1] = pd0;
                red[wn][r + 8][0] = ps1; red[wn][r + 8][1] = pd1;
            }
        }
        __syncthreads();
        if (tid < 128) {
            float ss = red[0][tid][0] + red[1][tid][0] + red[2][tid][0] + red[3][tid][0];
            float sd = red[0][tid][1] + red[1][tid][1] + red[2][tid][1] + red[3][tid][1];
            long m = m0 + tid;
            d_evb [m] = __float2bfloat16(__expf(sd));
            d_ev2b[m] = __float2bfloat16(__expf(0.2f * sd));
            d_r   [m] = __expf(-0.8f * ss);
        }
    }
}

// ---------------- 3. attention v6: hoisted ev/adj, per-tile Wh ring ----------------
// p'_ij = mask * max(ev_j, r_i * ev2_j); unified [p][n][h] output layout.
// adj staged via plain LDG.128 + 4B STS (pad 33 words -> bank-spread reads).
template <int LAYER>
__global__ void __launch_bounds__(256) att_v6_kernel() {
    __shared__ alignas(16) __nv_bfloat16 WhS[3][32][136];   // Wh tile ring [j][col]
    __shared__ alignas(16) __nv_bfloat16 evS [NN];          // full row, staged once
    __shared__ alignas(16) __nv_bfloat16 ev2S[NN];
    __shared__ alignas(16) unsigned adjS[128 * 33];         // full slab, pad 33

    int p = blockIdx.y, row0 = blockIdx.x * 128;
    int tid = threadIdx.x, lane = tid & 31, wid = tid >> 5;
    int b_ = p >> 4;
    int g = lane >> 2, t = lane & 3;

    int rlo = wid * 16 + g;
    float r0f = d_r[p * NN + row0 + rlo];
    float r1f = d_r[p * NN + row0 + rlo + 8];
    unsigned r02 = packbf(r0f, r0f);
    unsigned r12 = packbf(r1f, r1f);

    float acc[16][4] = {};
    float accz[4] = {};
    unsigned bz = (g == 0) ? packbf(1.f, 1.f) : 0u;
    unsigned bz2[2] = {bz, bz};

    const __nv_bfloat16* Whp = &d_Whb[(long)p * NN * HH];
    const unsigned* adjpb = &d_adjp[(long)b_ * NN * (NN / 32)];

    unsigned whbase  = (unsigned)__cvta_generic_to_shared(&WhS[0][0][0]);
    unsigned evbase  = (unsigned)__cvta_generic_to_shared(&evS[0]);
    unsigned ev2base = (unsigned)__cvta_generic_to_shared(&ev2S[0]);
    unsigned laneoff = (lane & 15) * 272 + (lane >> 4) * 16;

    int js = tid >> 4, seg = tid & 15;

    auto STAGE = [&](int i) {
        int bb = i % 3, jc = i * 32;
        const __nv_bfloat16* src = Whp + (long)(jc + js) * HH + seg * 8;
        unsigned dst = whbase + bb * 8704 + js * 272 + seg * 16;
        cpasync16(dst, src);
        cpasync16(dst + 16 * 272, src + 16 * HH);
        cpcommit();
    };

    // prologue group 0: ev + ev2 + Wh(0)  (cp.async); adj via plain LDG+STS
    if (tid < 128) cpasync16(evbase + tid * 16, d_evb + (long)p * NN + tid * 8);
    else           cpasync16(ev2base + (tid - 128) * 16, d_ev2b + (long)p * NN + (tid - 128) * 8);
    {
        int bb = 0;
        const __nv_bfloat16* src = Whp + (long)js * HH + seg * 8;
        unsigned dst = whbase + bb * 8704 + js * 272 + seg * 16;
        cpasync16(dst, src);
        cpasync16(dst + 16 * 272, src + 16 * HH);
    }
    cpcommit();
    STAGE(1);

    // adj slab: 128 rows x 32 words, each of 256 threads handles half a row (16 words)
    {
        int rr = tid >> 1, half = tid & 1;
        const uint4* src = (const uint4*)(adjpb + (long)(row0 + rr) * 32 + half * 16);
        unsigned* dstw = &adjS[rr * 33 + half * 16];
#pragma unroll
        for (int q = 0; q < 4; q++) {
            uint4 v = src[q];
            dstw[q * 4 + 0] = v.x; dstw[q * 4 + 1] = v.y;
            dstw[q * 4 + 2] = v.z; dstw[q * 4 + 3] = v.w;
        }
    }

    for (int i = 0; i < 32; i++) {
        if (i < 31) { asm volatile("cp.async.wait_group 1;" ::: "memory"); }
        else        { asm volatile("cp.async.wait_group 0;" ::: "memory"); }
        __syncthreads();
        if (i + 2 < 32) STAGE(i + 2);

        int bb = i % 3;
        unsigned awlo = adjS[rlo * 33 + i], awhi = adjS[(rlo + 8) * 33 + i];
        unsigned kb0 = whbase + bb * 8704 + laneoff;
#pragma unroll
        for (int ks = 0; ks < 2; ks++) {
            int jg = i * 32 + ks * 16 + 2 * t;
            int j0 = ks * 16 + 2 * t;
            __nv_bfloat162 evp  = *(__nv_bfloat162*)&evS [jg];
            __nv_bfloat162 evp8 = *(__nv_bfloat162*)&evS [jg + 8];
            __nv_bfloat162 e2p  = *(__nv_bfloat162*)&ev2S[jg];
            __nv_bfloat162 e2p8 = *(__nv_bfloat162*)&ev2S[jg + 8];
            __nv_bfloat162 r0b = *(__nv_bfloat162*)&r02;
            __nv_bfloat162 r1b = *(__nv_bfloat162*)&r12;

            unsigned a[4];
            a[0] = bfu(__hmax2(evp,  __hmul2(r0b, e2p)))  & mask2(awlo, j0);
            a[1] = bfu(__hmax2(evp,  __hmul2(r1b, e2p)))  & mask2(awhi, j0);
            a[2] = bfu(__hmax2(evp8, __hmul2(r0b, e2p8))) & mask2(awlo, j0 + 8);
            a[3] = bfu(__hmax2(evp8, __hmul2(r1b, e2p8))) & mask2(awhi, j0 + 8);

            mma_bf16(accz, a, bz2);

            unsigned kbase = kb0 + ks * 4352;
#pragma unroll
            for (int nc = 0; nc < 8; nc++) {
                unsigned b0, b1, b2, b3;
                ldm_x4_trans(b0, b1, b2, b3, kbase + nc * 32);
                unsigned bf0[2] = {b0, b1}, bf1[2] = {b2, b3};
                mma_bf16(acc[2 * nc], a, bf0);
                mma_bf16(acc[2 * nc + 1], a, bf1);
            }
        }
    }

    float z0 = __shfl_sync(~0u, accz[0], lane & ~3);
    float z1 = __shfl_sync(~0u, accz[2], lane & ~3);
    float iz0 = 1.f / z0, iz1 = 1.f / z1;

    __nv_bfloat16* gout = (LAYER == 0) ? d_h1b : d_gb;
    long b0r = ((long)p * NN + row0 + rlo) * HH;
    long b1r = ((long)p * NN + row0 + rlo + 8) * HH;
#pragma unroll
    for (int nf = 0; nf < 16; nf++) {
        int col = nf * 8 + 2 * t;
        float o0 = elu2(acc[nf][0] * iz0);
        float o1 = elu2(acc[nf][1] * iz0);
        float o2 = elu2(acc[nf][2] * iz1);
        float o3 = elu2(acc[nf][3] * iz1);
        *(unsigned*)&gout[b0r + col] = packbf(o0, o1);
        *(unsigned*)&gout[b1r + col] = packbf(o2, o3);
    }
}

// ---------------- 4. LSTM recurrence + fused output MLP ----------------
__global__ void lstm_kernel(const float* __restrict__ Whh,
                            const float* __restrict__ Wo1, const float* __restrict__ bo1,
                            const float* __restrict__ Wo2, const float* __restrict__ bo2,
                            float* __restrict__ out) {
    extern __shared__ float sm[];
    float* WT  = sm;                       // [64][257]
    float* hs  = sm + 64 * 257;            // [16][68]
    float* W1s = sm + 64 * 257 + 16 * 68;  // [64][32]
    float* W2s = W1s + 64 * 32;            // [32]
    int tid = threadIdx.x, lane = tid & 31, wp = tid >> 5;
    for (int idx = tid; idx < 256 * 64; idx += 256) {
        int g = idx >> 6, k = idx & 63;
        WT[k * 257 + g] = Whh[g * 64 + k];
    }
    for (int idx = tid; idx < 16 * 68; idx += 256) hs[idx] = 0.f;
    for (int idx = tid; idx < 64 * 32; idx += 256) W1s[idx] = Wo1[idx];
    if (tid < 32) W2s[tid] = Wo2[tid];
    __syncthreads();

    int r0 = wp * 2, r1 = r0 + 1;
    long gr0 = (long)blockIdx.x * 16 + r0;
    long gr1 = gr0 + 1;
    float c[2][2] = {};
    float hn[2][2] = {};
    for (int tt = 0; tt < TT; tt++) {
        float acc[2][4][2];
#pragma unroll
        for (int d = 0; d < 2; d++) {
            long base = ((d ? gr1 : gr0) * TT + tt) * 256;
#pragma unroll
            for (int q = 0; q < 4; q++) {
                acc[d][q][0] = d_XG[base + q * 64 + lane];
                acc[d][q][1] = d_XG[base + q * 64 + 32 + lane];
            }
        }
#pragma unroll 8
        for (int k = 0; k < 64; k++) {
            float h0  = hs[r0 * 68 + k];
            float h1v = hs[r1 * 68 + k];
            const float* wr = &WT[k * 257];
#pragma unroll
            for (int q = 0; q < 4; q++) {
                float wv0 = wr[q * 64 + lane];
                float wv1 = wr[q * 64 + 32 + lane];
                acc[0][q][0] += wv0 * h0;  acc[0][q][1] += wv1 * h0;
                acc[1][q][0] += wv0 * h1v; acc[1][q][1] += wv1 * h1v;
            }
        }
#pragma unroll
        for (int d = 0; d < 2; d++)
#pragma unroll
            for (int u = 0; u < 2; u++) {
                float iv = sigf(acc[d][0][u]);
                float fv = sigf(acc[d][1][u]);
                float gv = tanhf_(acc[d][2][u]);
                float ov = sigf(acc[d][3][u]);
                c[d][u]  = fv * c[d][u] + iv * gv;
                hn[d][u] = ov * tanhf_(c[d][u]);
            }
        __syncthreads();
        hs[r0 * 68 + lane]      = hn[0][0];
        hs[r0 * 68 + 32 + lane] = hn[0][1];
        hs[r1 * 68 + lane]      = hn[1][0];
        hs[r1 * 68 + 32 + lane] = hn[1][1];
        __syncthreads();
    }

    float b1v = bo1[lane], b2v = bo2[0];
#pragma unroll
    for (int rr = 0; rr < 2; rr++) {
        int r = wp * 2 + rr;
        float a = b1v;
#pragma unroll 16
        for (int k = 0; k < 64; k++) a += hs[r * 68 + k] * W1s[k * 32 + lane];
        float m = fmaxf(a, 0.f) * W2s[lane];
#pragma unroll
        for (int o = 16; o; o >>= 1) m += __shfl_xor_sync(~0u, m, o);
        if (lane == 0) out[(long)blockIdx.x * 16 + r] = m + b2v;
    }
}

// ---------------- launcher ----------------
extern "C" void kernel_launch(void* const* d_in, const int* in_sizes, int n_in,
                              void* d_out, int out_size) {
    const float* x   = (const float*)d_in[0];
    const int*   adj = (const int*)  d_in[1];
    const float* W1  = (const float*)d_in[2];
    const float* a1  = (const float*)d_in[3];
    const float* W2  = (const float*)d_in[4];
    const float* a2  = (const float*)d_in[5];
    const float* Wih = (const float*)d_in[6];
    const float* Whh = (const float*)d_in[7];
    const float* bih = (const float*)d_in[8];
    const float* bhh = (const float*)d_in[9];
    const float* Wo1 = (const float*)d_in[10];
    const float* bo1 = (const float*)d_in[11];
    const float* Wo2 = (const float*)d_in[12];
    const float* bo2 = (const float*)d_in[13];
    float* out = (float*)d_out;

    __nv_bfloat16* d_h1b_p; cudaGetSymbolAddress((void**)&d_h1b_p, d_h1b);
    __nv_bfloat16* d_gb_p;  cudaGetSymbolAddress((void**)&d_gb_p,  d_gb);
    __nv_bfloat16* d_W2b_p; cudaGetSymbolAddress((void**)&d_W2b_p, d_W2b);
    __nv_bfloat16* d_Wihb_p;cudaGetSymbolAddress((void**)&d_Wihb_p,d_Wihb);
    float* d_XG_p;          cudaGetSymbolAddress((void**)&d_XG_p,  d_XG);

    const int L1SM = (4608 + 32 * 136) * sizeof(float);
    const int BFSM = 2 * 128 * 272;
    cudaFuncSetAttribute((const void*)gemm_l1,
                         cudaFuncAttributeMaxDynamicSharedMemorySize, L1SM);
    cudaFuncSetAttribute((const void*)gemm_bf<0, 128, 1, 0>,
                         cudaFuncAttributeMaxDynamicSharedMemorySize, BFSM);
    cudaFuncSetAttribute((const void*)gemm_bf<1, 256, 0, 1>,
                         cudaFuncAttributeMaxDynamicSharedMemorySize, BFSM);

    prep_all<<<512, 256>>>(adj, W2, Wih);

    // GAT layer 1
    gemm_l1<<<512, 256, L1SM>>>(x, W1, a1);
    att_v6_kernel<0><<<dim3(8, 64), 256>>>();

    // GAT layer 2 (bf16 GEMM)
    gemm_bf<0, 128, 1, 0><<<dim3(512, 1), 256, BFSM>>>(d_h1b_p, d_W2b_p, nullptr, nullptr, a2, nullptr);
    att_v6_kernel<1><<<dim3(8, 64), 256>>>();

    // LSTM input gates (gathers d_gb [p][n][h])
    gemm_bf<1, 256, 0, 1><<<dim3(512, 2), 256, BFSM>>>(d_gb_p, d_Wihb_p, bih, bhh, nullptr, d_XG_p);

    // LSTM recurrence + fused MLP
    size_t smem = (64 * 257 + 16 * 68 + 64 * 32 + 32) * sizeof(float);
    cudaFuncSetAttribute(lstm_kernel, cudaFuncAttributeMaxDynamicSharedMemorySize, (int)smem);
    lstm_kernel<<<256, 256, smem>>>(Whh, Wo1, bo1, Wo2, bo2, out);
}

// round 13
// speedup vs baseline: 4.6593x; 1.0113x over previous
#include <cuda_runtime.h>
#include <cuda_bf16.h>
#include <cstdint>

#define BB   4
#define NN   1024
#define TT   16
#define FINN 32
#define HH   128
#define LHID 64
#define NP   64
#define MTOT (NP * NN)

// ---------------- scratch ----------------
__device__ __nv_bfloat16 d_Whb[MTOT * HH];        // bf16 Wh (GEMM epilogue output, row-major)
__device__ __nv_bfloat16 d_h1b[MTOT * HH];        // bf16 layer-1 output [p][n][h]
__device__ __nv_bfloat16 d_gb [MTOT * HH];        // bf16 layer-2 output [p][n][h]
__device__ __nv_bfloat16 d_evb [MTOT];
__device__ __nv_bfloat16 d_ev2b[MTOT];
__device__ float         d_r  [MTOT];             // e^{-0.8 s_src}
__device__ unsigned      d_adjp[BB * NN * (NN / 32)];
__device__ float         d_XG [MTOT * 256];
__device__ __nv_bfloat16 d_W2b [HH * HH];         // W2 transposed -> [n][k] bf16
__device__ __nv_bfloat16 d_Wihb[256 * HH];        // Wih [gate][k] bf16

// ---------------- helpers ----------------
__device__ __forceinline__ float sigf(float x)   { return 1.f / (1.f + __expf(-x)); }
__device__ __forceinline__ float tanhf_(float x) { return 1.f - 2.f / (__expf(2.f * x) + 1.f); }
__device__ __forceinline__ void mma_tf32(float* c, const unsigned* a, const unsigned* b) {
    asm volatile("mma.sync.aligned.m16n8k8.row.col.f32.tf32.tf32.f32 "
                 "{%0,%1,%2,%3}, {%4,%5,%6,%7}, {%8,%9}, {%0,%1,%2,%3};"
                 : "+f"(c[0]), "+f"(c[1]), "+f"(c[2]), "+f"(c[3])
                 : "r"(a[0]), "r"(a[1]), "r"(a[2]), "r"(a[3]), "r"(b[0]), "r"(b[1]));
}
__device__ __forceinline__ void mma_bf16(float* c, const unsigned* a, const unsigned* b) {
    asm volatile("mma.sync.aligned.m16n8k16.row.col.f32.bf16.bf16.f32 "
                 "{%0,%1,%2,%3}, {%4,%5,%6,%7}, {%8,%9}, {%0,%1,%2,%3};"
                 : "+f"(c[0]), "+f"(c[1]), "+f"(c[2]), "+f"(c[3])
                 : "r"(a[0]), "r"(a[1]), "r"(a[2]), "r"(a[3]), "r"(b[0]), "r"(b[1]));
}
__device__ __forceinline__ void ldm_x4(unsigned& r0, unsigned& r1, unsigned& r2, unsigned& r3,
                                       unsigned saddr) {
    asm volatile("ldmatrix.sync.aligned.m8n8.x4.shared.b16 {%0,%1,%2,%3}, [%4];"
                 : "=r"(r0), "=r"(r1), "=r"(r2), "=r"(r3) : "r"(saddr));
}
__device__ __forceinline__ void ldm_x4_trans(unsigned& r0, unsigned& r1, unsigned& r2, unsigned& r3,
                                             unsigned saddr) {
    asm volatile("ldmatrix.sync.aligned.m8n8.x4.trans.shared.b16 {%0,%1,%2,%3}, [%4];"
                 : "=r"(r0), "=r"(r1), "=r"(r2), "=r"(r3) : "r"(saddr));
}
__device__ __forceinline__ void cpasync16(unsigned saddr, const void* g) {
    asm volatile("cp.async.ca.shared.global [%0], [%1], 16;" :: "r"(saddr), "l"(g));
}
__device__ __forceinline__ void cpcommit() { asm volatile("cp.async.commit_group;"); }
__device__ __forceinline__ float elu2(float v) {
    v = v > 0.f ? v : __expf(v) - 1.f;
    v = v > 0.f ? v : __expf(v) - 1.f;
    return v;
}
__device__ __forceinline__ unsigned packbf(float a, float b) {
    __nv_bfloat162 p = __floats2bfloat162_rn(a, b);
    return *(unsigned*)&p;
}
__device__ __forceinline__ unsigned bfu(__nv_bfloat162 v) { return *(unsigned*)&v; }
__device__ __forceinline__ unsigned mask2(unsigned aw, int j0) {
    unsigned m = 0;
    if ((aw >> j0) & 1u)       m |= 0x0000FFFFu;
    if ((aw >> (j0 + 1)) & 1u) m |= 0xFFFF0000u;
    return m;
}

// ---------------- 1. prep: pack adjacency + bf16 weights (one launch) ----------------
__global__ void prep_all(const int* __restrict__ adj,
                         const float* __restrict__ W2, const float* __restrict__ Wih) {
    int idx = blockIdx.x * blockDim.x + threadIdx.x;   // 131072 threads
    if (idx < BB * NN * (NN / 32)) {
        long base = (long)idx * 32;
        unsigned bits = 0;
#pragma unroll
        for (int j = 0; j < 32; j++) bits |= (adj[base + j] > 0 ? 1u : 0u) << j;
        d_adjp[idx] = bits;
    }
    if (idx < HH * HH) {
        int n = idx >> 7, k = idx & 127;
        d_W2b[idx] = __float2bfloat16(W2[k * HH + n]);
    }
    if (idx < 256 * HH)
        d_Wihb[idx] = __float2bfloat16(Wih[idx]);
}

// ---------------- 2a. tf32 GEMM (layer 1: x gathered, K=32) -> d_Whb + scores ----
__global__ void __launch_bounds__(256, 2) gemm_l1(const float* __restrict__ A,
                                                  const float* __restrict__ Bw,
                                                  const float* __restrict__ avec) {
    int m0 = blockIdx.x * 128;
    int tid = threadIdx.x, lane = tid & 31, wid = tid >> 5;
    int wm = wid >> 2, wn = wid & 3;
    int g = lane >> 2, t = lane & 3;

    extern __shared__ float gsm[];
    float* As = gsm;             // [128][36]
    float* Bs = gsm + 4608;      // [32][136]
    __shared__ float sA[256];
    __shared__ float red[4][128][2];

    sA[tid] = avec[tid];

    float acc[4][4][4] = {};
    {
        int r = tid >> 1, k0 = (tid & 1) * 16;
        int m = m0 + r;
        int n = m & (NN - 1);
        int pp = m >> 10, tt2 = pp & 15, bb2 = pp >> 4;
        long base = (((long)(bb2 * NN + n) * TT + tt2) * FINN) + k0;
        unsigned dst = (unsigned)__cvta_generic_to_shared(&As[r * 36 + k0]);
#pragma unroll
        for (int q = 0; q < 4; q++) cpasync16(dst + q * 16, A + base + q * 4);
    }
    {
        int kr = tid >> 3, cq = tid & 7;
        const float* src = Bw + (long)kr * HH + cq * 16;
        unsigned dst = (unsigned)__cvta_generic_to_shared(&Bs[kr * 136 + cq * 16]);
#pragma unroll
        for (int q = 0; q < 4; q++) cpasync16(dst + q * 16, src + q * 4);
    }
    cpcommit();
    asm volatile("cp.async.wait_group 0;" ::: "memory");
    __syncthreads();

#pragma unroll
    for (int ks = 0; ks < 4; ks++) {
        unsigned a[4][4], bf[4][2];
#pragma unroll
        for (int mf = 0; mf < 4; mf++) {
            int r = wm * 64 + mf * 16 + g;
            a[mf][0] = __float_as_uint(As[r * 36 + ks * 8 + t]);
            a[mf][1] = __float_as_uint(As[(r + 8) * 36 + ks * 8 + t]);
            a[mf][2] = __float_as_uint(As[r * 36 + ks * 8 + t + 4]);
            a[mf][3] = __float_as_uint(As[(r + 8) * 36 + ks * 8 + t + 4]);
        }
#pragma unroll
        for (int nf = 0; nf < 4; nf++) {
            int cc = wn * 32 + nf * 8 + g;
            bf[nf][0] = __float_as_uint(Bs[(ks * 8 + t) * 136 + cc]);
            bf[nf][1] = __float_as_uint(Bs[(ks * 8 + t + 4) * 136 + cc]);
        }
#pragma unroll
        for (int mf = 0; mf < 4; mf++)
#pragma unroll
            for (int nf = 0; nf < 4; nf++)
                mma_tf32(acc[mf][nf], a[mf], bf[nf]);
    }

    // store bf16 Wh + fused scores
#pragma unroll
    for (int mf = 0; mf < 4; mf++) {
        int r = m0 + wm * 64 + mf * 16 + g;
#pragma unroll
        for (int nf = 0; nf < 4; nf++) {
            int cc = wn * 32 + nf * 8 + 2 * t;
            *(unsigned*)&d_Whb[(long)r * HH + cc] = packbf(acc[mf][nf][0], acc[mf][nf][1]);
            *(unsigned*)&d_Whb[(long)(r + 8) * HH + cc] = packbf(acc[mf][nf][2], acc[mf][nf][3]);
        }
    }
#pragma unroll
    for (int mf = 0; mf < 4; mf++) {
        float ps0 = 0.f, pd0 = 0.f, ps1 = 0.f, pd1 = 0.f;
#pragma unroll
        for (int nf = 0; nf < 4; nf++) {
            int cc = wn * 32 + nf * 8 + 2 * t;
#pragma unroll
            for (int dd = 0; dd < 2; dd++) {
                float a_s = sA[cc + dd], a_d = sA[128 + cc + dd];
                ps0 += acc[mf][nf][dd]     * a_s;
                pd0 += acc[mf][nf][dd]     * a_d;
                ps1 += acc[mf][nf][2 + dd] * a_s;
                pd1 += acc[mf][nf][2 + dd] * a_d;
            }
        }
#pragma unroll
        for (int o = 1; o <= 2; o <<= 1) {
            ps0 += __shfl_xor_sync(~0u, ps0, o);
            pd0 += __shfl_xor_sync(~0u, pd0, o);
            ps1 += __shfl_xor_sync(~0u, ps1, o);
            pd1 += __shfl_xor_sync(~0u, pd1, o);
        }
        if (t == 0) {
            int r = wm * 64 + mf * 16 + g;
            red[wn][r][0] = ps0;     red[wn][r][1] = pd0;
            red[wn][r + 8][0] = ps1; red[wn][r + 8][1] = pd1;
        }
    }
    __syncthreads();
    if (tid < 128) {
        float ss = red[0][tid][0] + red[1][tid][0] + red[2][tid][0] + red[3][tid][0];
        float sd = red[0][tid][1] + red[1][tid][1] + red[2][tid][1] + red[3][tid][1];
        long m = m0 + tid;
        d_evb [m] = __float2bfloat16(__expf(sd));
        d_ev2b[m] = __float2bfloat16(__expf(0.2f * sd));
        d_r   [m] = __expf(-0.8f * ss);
    }
}

// ---------------- 2b. bf16 GEMM (K=128) ----------------
// AMODE 0: A dense rows [m][128];  AMODE 1: A = d_gb gathered via (b,t,n) for xg
// SFUSE 1: bf16 out -> d_Whb + fused scores (layer 2; NTOT=128, gridDim.y=1)
// SFUSE 0: fp32 out + bias (xg; NTOT=256)
template <int BIAS, int NTOT, int SFUSE, int AMODE>
__global__ void __launch_bounds__(256, 2) gemm_bf(const __nv_bfloat16* __restrict__ A,
                                                  const __nv_bfloat16* __restrict__ Bw,
                                                  const float* __restrict__ bi1,
                                                  const float* __restrict__ bi2,
                                                  const float* __restrict__ avec,
                                                  float* __restrict__ Out) {
    int m0 = blockIdx.x * 128;
    int c0 = blockIdx.y * 128;
    int tid = threadIdx.x, lane = tid & 31, wid = tid >> 5;
    int wm = wid >> 2, wn = wid & 3;
    int g = lane >> 2, t = lane & 3;

    extern __shared__ __nv_bfloat16 bsm[];
    unsigned asmem = (unsigned)__cvta_generic_to_shared(&bsm[0]);
    unsigned bsmem = asmem + 128 * 272;
    __shared__ float sA[SFUSE ? 256 : 1];
    __shared__ float red[SFUSE ? 4 : 1][SFUSE ? 128 : 1][2];

    if (SFUSE) sA[tid] = avec[tid];

    {
        int r = tid >> 1, h = (tid & 1) * 8;
        long arow;
        if (AMODE == 0) {
            arow = (long)(m0 + r) * HH;
        } else {
            int m = m0 + r;
            int tt2 = m & 15, bn = m >> 4;
            int n = bn & (NN - 1), b = bn >> 10;
            arow = ((long)(b * TT + tt2) * NN + n) * HH;   // d_gb [p][n][h]
        }
        const __nv_bfloat16* asrc = A + arow + h * 8;
        const __nv_bfloat16* bsrc = Bw + (long)(c0 + r) * HH + h * 8;
        unsigned adst = asmem + r * 272 + h * 16;
        unsigned bdst = bsmem + r * 272 + h * 16;
#pragma unroll
        for (int q = 0; q < 8; q++) {
            cpasync16(adst + q * 16, asrc + q * 8);
            cpasync16(bdst + q * 16, bsrc + q * 8);
        }
    }
    cpcommit();

    int mrow = lane & 7, msel = lane >> 3;
    unsigned aLane = asmem + ((msel & 1) * 8 + mrow) * 272 + (msel >> 1) * 16 + (wm * 64) * 272;
    unsigned bLane = bsmem + ((msel >> 1) * 8 + mrow) * 272 + (msel & 1) * 16 + (wn * 32) * 272;

    float acc[4][4][4] = {};
    asm volatile("cp.async.wait_group 0;" ::: "memory");
    __syncthreads();

#pragma unroll
    for (int ks = 0; ks < 8; ks++) {
        unsigned a[4][4], bf[4][2];
#pragma unroll
        for (int mf = 0; mf < 4; mf++)
            ldm_x4(a[mf][0], a[mf][1], a[mf][2], a[mf][3], aLane + mf * 16 * 272 + ks * 32);
#pragma unroll
        for (int pr = 0; pr < 2; pr++) {
            unsigned t0, t1, t2, t3;
            ldm_x4(t0, t1, t2, t3, bLane + pr * 16 * 272 + ks * 32);
            bf[2 * pr][0] = t0; bf[2 * pr][1] = t1;
            bf[2 * pr + 1][0] = t2; bf[2 * pr + 1][1] = t3;
        }
#pragma unroll
        for (int mf = 0; mf < 4; mf++)
#pragma unroll
            for (int nf = 0; nf < 4; nf++)
                mma_bf16(acc[mf][nf], a[mf], bf[nf]);
    }

#pragma unroll
    for (int mf = 0; mf < 4; mf++) {
        int m = m0 + wm * 64 + mf * 16 + g;
#pragma unroll
        for (int nf = 0; nf < 4; nf++) {
            int cc = c0 + wn * 32 + nf * 8 + 2 * t;
            if (SFUSE) {
                *(unsigned*)&d_Whb[(long)m * HH + cc] = packbf(acc[mf][nf][0], acc[mf][nf][1]);
                *(unsigned*)&d_Whb[(long)(m + 8) * HH + cc] = packbf(acc[mf][nf][2], acc[mf][nf][3]);
            } else {
                float b0 = 0.f, b1 = 0.f;
                if (BIAS) {
                    b0 = bi1[cc] + bi2[cc];
                    b1 = bi1[cc + 1] + bi2[cc + 1];
                }
                *(float2*)&Out[(long)m * NTOT + cc] =
                    make_float2(acc[mf][nf][0] + b0, acc[mf][nf][1] + b1);
                *(float2*)&Out[(long)(m + 8) * NTOT + cc] =
                    make_float2(acc[mf][nf][2] + b0, acc[mf][nf][3] + b1);
            }
        }
    }
    if (SFUSE) {
#pragma unroll
        for (int mf = 0; mf < 4; mf++) {
            float ps0 = 0.f, pd0 = 0.f, ps1 = 0.f, pd1 = 0.f;
#pragma unroll
            for (int nf = 0; nf < 4; nf++) {
                int cc = wn * 32 + nf * 8 + 2 * t;
#pragma unroll
                for (int dd = 0; dd < 2; dd++) {
                    float a_s = sA[cc + dd], a_d = sA[128 + cc + dd];
                    ps0 += acc[mf][nf][dd]     * a_s;
                    pd0 += acc[mf][nf][dd]     * a_d;
                    ps1 += acc[mf][nf][2 + dd] * a_s;
                    pd1 += acc[mf][nf][2 + dd] * a_d;
                }
            }
#pragma unroll
            for (int o = 1; o <= 2; o <<= 1) {
                ps0 += __shfl_xor_sync(~0u, ps0, o);
                pd0 += __shfl_xor_sync(~0u, pd0, o);
                ps1 += __shfl_xor_sync(~0u, ps1, o);
                pd1 += __shfl_xor_sync(~0u, pd1, o);
            }
            if (t == 0) {
                int r = wm * 64 + mf * 16 + g;
                red[wn][r][0] = ps0;     red[wn][r][1] = pd0;
                red[wn][r + 8][0] = ps1; red[wn][r + 8][1] = pd1;
            }
        }
        __syncthreads();
        if (tid < 128) {
            float ss = red[0][tid][0] + red[1][tid][0] + red[2][tid][0] + red[3][tid][0];
            float sd = red[0][tid][1] + red[1][tid][1] + red[2][tid][1] + red[3][tid][1];
            long m = m0 + tid;
            d_evb [m] = __float2bfloat16(__expf(sd));
            d_ev2b[m] = __float2bfloat16(__expf(0.2f * sd));
            d_r   [m] = __expf(-0.8f * ss);
        }
    }
}

// ---------------- 3. attention v7: hoisted ev/adj, Wh ring, coalesced epilogue ----
// Epilogue staging row stride = 72 bf16 = 144 B (16B multiple -> legal uint4 access).
template <int LAYER>
__global__ void __launch_bounds__(256, 2) att_v7_kernel() {
    __shared__ alignas(16) __nv_bfloat16 WhS[3][32][136];   // Wh ring; reused as epi staging [128][72]
    __shared__ alignas(16) __nv_bfloat16 evS [NN];
    __shared__ alignas(16) __nv_bfloat16 ev2S[NN];
    __shared__ alignas(16) unsigned adjS[128 * 33];

    int p = blockIdx.y, row0 = blockIdx.x * 128;
    int tid = threadIdx.x, lane = tid & 31, wid = tid >> 5;
    int b_ = p >> 4;
    int g = lane >> 2, t = lane & 3;

    int rlo = wid * 16 + g;
    float r0f = d_r[p * NN + row0 + rlo];
    float r1f = d_r[p * NN + row0 + rlo + 8];
    unsigned r02 = packbf(r0f, r0f);
    unsigned r12 = packbf(r1f, r1f);

    float acc[16][4] = {};
    float accz[4] = {};
    unsigned bz = (g == 0) ? packbf(1.f, 1.f) : 0u;
    unsigned bz2[2] = {bz, bz};

    const __nv_bfloat16* Whp = &d_Whb[(long)p * NN * HH];
    const unsigned* adjpb = &d_adjp[(long)b_ * NN * (NN / 32)];

    unsigned whbase  = (unsigned)__cvta_generic_to_shared(&WhS[0][0][0]);
    unsigned evbase  = (unsigned)__cvta_generic_to_shared(&evS[0]);
    unsigned ev2base = (unsigned)__cvta_generic_to_shared(&ev2S[0]);
    unsigned laneoff = (lane & 15) * 272 + (lane >> 4) * 16;

    int js = tid >> 4, seg = tid & 15;

    auto STAGE = [&](int i) {
        int bb = i % 3, jc = i * 32;
        const __nv_bfloat16* src = Whp + (long)(jc + js) * HH + seg * 8;
        unsigned dst = whbase + bb * 8704 + js * 272 + seg * 16;
        cpasync16(dst, src);
        cpasync16(dst + 16 * 272, src + 16 * HH);
        cpcommit();
    };

    // prologue: ev + ev2 + Wh(0) (cp.async); adj via plain LDG+STS
    if (tid < 128) cpasync16(evbase + tid * 16, d_evb + (long)p * NN + tid * 8);
    else           cpasync16(ev2base + (tid - 128) * 16, d_ev2b + (long)p * NN + (tid - 128) * 8);
    {
        const __nv_bfloat16* src = Whp + (long)js * HH + seg * 8;
        unsigned dst = whbase + js * 272 + seg * 16;
        cpasync16(dst, src);
        cpasync16(dst + 16 * 272, src + 16 * HH);
    }
    cpcommit();
    STAGE(1);

    {
        int rr = tid >> 1, half = tid & 1;
        const uint4* src = (const uint4*)(adjpb + (long)(row0 + rr) * 32 + half * 16);
        unsigned* dstw = &adjS[rr * 33 + half * 16];
#pragma unroll
        for (int q = 0; q < 4; q++) {
            uint4 v = src[q];
            dstw[q * 4 + 0] = v.x; dstw[q * 4 + 1] = v.y;
            dstw[q * 4 + 2] = v.z; dstw[q * 4 + 3] = v.w;
        }
    }

    for (int i = 0; i < 32; i++) {
        if (i < 31) { asm volatile("cp.async.wait_group 1;" ::: "memory"); }
        else        { asm volatile("cp.async.wait_group 0;" ::: "memory"); }
        __syncthreads();
        if (i + 2 < 32) STAGE(i + 2);

        int bb = i % 3;
        unsigned awlo = adjS[rlo * 33 + i], awhi = adjS[(rlo + 8) * 33 + i];
        unsigned kb0 = whbase + bb * 8704 + laneoff;
#pragma unroll
        for (int ks = 0; ks < 2; ks++) {
            int jg = i * 32 + ks * 16 + 2 * t;
            int j0 = ks * 16 + 2 * t;
            __nv_bfloat162 evp  = *(__nv_bfloat162*)&evS [jg];
            __nv_bfloat162 evp8 = *(__nv_bfloat162*)&evS [jg + 8];
            __nv_bfloat162 e2p  = *(__nv_bfloat162*)&ev2S[jg];
            __nv_bfloat162 e2p8 = *(__nv_bfloat162*)&ev2S[jg + 8];
            __nv_bfloat162 r0b = *(__nv_bfloat162*)&r02;
            __nv_bfloat162 r1b = *(__nv_bfloat162*)&r12;

            unsigned a[4];
            a[0] = bfu(__hmax2(evp,  __hmul2(r0b, e2p)))  & mask2(awlo, j0);
            a[1] = bfu(__hmax2(evp,  __hmul2(r1b, e2p)))  & mask2(awhi, j0);
            a[2] = bfu(__hmax2(evp8, __hmul2(r0b, e2p8))) & mask2(awlo, j0 + 8);
            a[3] = bfu(__hmax2(evp8, __hmul2(r1b, e2p8))) & mask2(awhi, j0 + 8);

            mma_bf16(accz, a, bz2);

            unsigned kbase = kb0 + ks * 4352;
#pragma unroll
            for (int nc = 0; nc < 8; nc++) {
                unsigned b0, b1, b2, b3;
                ldm_x4_trans(b0, b1, b2, b3, kbase + nc * 32);
                unsigned bf0[2] = {b0, b1}, bf1[2] = {b2, b3};
                mma_bf16(acc[2 * nc], a, bf0);
                mma_bf16(acc[2 * nc + 1], a, bf1);
            }
        }
    }

    float z0 = __shfl_sync(~0u, accz[0], lane & ~3);
    float z1 = __shfl_sync(~0u, accz[2], lane & ~3);
    float iz0 = 1.f / z0, iz1 = 1.f / z1;

    // ---- coalesced epilogue: transpose through smem (stride 72 = 144B, 16B-aligned) ----
    __nv_bfloat16* stg = &WhS[0][0][0];            // [128 rows][72 cols] bf16 = 18432 B
    __nv_bfloat16* gout = (LAYER == 0) ? d_h1b : d_gb;
#pragma unroll
    for (int half = 0; half < 2; half++) {
        __syncthreads();
#pragma unroll
        for (int nf2 = 0; nf2 < 8; nf2++) {
            int nf = half * 8 + nf2;
            int col = nf2 * 8 + 2 * t;
            *(unsigned*)&stg[rlo * 72 + col]       = packbf(elu2(acc[nf][0] * iz0), elu2(acc[nf][1] * iz0));
            *(unsigned*)&stg[(rlo + 8) * 72 + col] = packbf(elu2(acc[nf][2] * iz1), elu2(acc[nf][3] * iz1));
        }
        __syncthreads();
        int r = tid >> 1, cq = tid & 1;             // each thread: 4x uint4 = 64B
        const uint4* srow = (const uint4*)&stg[r * 72 + cq * 32];
        uint4* drow = (uint4*)&gout[((long)p * NN + row0 + r) * HH + half * 64 + cq * 32];
#pragma unroll
        for (int q = 0; q < 4; q++) drow[q] = srow[q];
    }
}

// ---------------- 4. LSTM recurrence + fused output MLP ----------------
__global__ void lstm_kernel(const float* __restrict__ Whh,
                            const float* __restrict__ Wo1, const float* __restrict__ bo1,
                            const float* __restrict__ Wo2, const float* __restrict__ bo2,
                            float* __restrict__ out) {
    extern __shared__ float sm[];
    float* WT  = sm;                       // [64][257]
    float* hs  = sm + 64 * 257;            // [16][68]
    float* W1s = sm + 64 * 257 + 16 * 68;  // [64][32]
    float* W2s = W1s + 64 * 32;            // [32]
    int tid = threadIdx.x, lane = tid & 31, wp = tid >> 5;
    for (int idx = tid; idx < 256 * 64; idx += 256) {
        int g = idx >> 6, k = idx & 63;
        WT[k * 257 + g] = Whh[g * 64 + k];
    }
    for (int idx = tid; idx < 16 * 68; idx += 256) hs[idx] = 0.f;
    for (int idx = tid; idx < 64 * 32; idx += 256) W1s[idx] = Wo1[idx];
    if (tid < 32) W2s[tid] = Wo2[tid];
    __syncthreads();

    int r0 = wp * 2, r1 = r0 + 1;
    long gr0 = (long)blockIdx.x * 16 + r0;
    long gr1 = gr0 + 1;
    float c[2][2] = {};
    float hn[2][2] = {};
    for (int tt = 0; tt < TT; tt++) {
        float acc[2][4][2];
#pragma unroll
        for (int d = 0; d < 2; d++) {
            long base = ((d ? gr1 : gr0) * TT + tt) * 256;
#pragma unroll
            for (int q = 0; q < 4; q++) {
                acc[d][q][0] = d_XG[base + q * 64 + lane];
                acc[d][q][1] = d_XG[base + q * 64 + 32 + lane];
            }
        }
#pragma unroll 8
        for (int k = 0; k < 64; k++) {
            float h0  = hs[r0 * 68 + k];
            float h1v = hs[r1 * 68 + k];
            const float* wr = &WT[k * 257];
#pragma unroll
            for (int q = 0; q < 4; q++) {
                float wv0 = wr[q * 64 + lane];
                float wv1 = wr[q * 64 + 32 + lane];
                acc[0][q][0] += wv0 * h0;  acc[0][q][1] += wv1 * h0;
                acc[1][q][0] += wv0 * h1v; acc[1][q][1] += wv1 * h1v;
            }
        }
#pragma unroll
        for (int d = 0; d < 2; d++)
#pragma unroll
            for (int u = 0; u < 2; u++) {
                float iv = sigf(acc[d][0][u]);
                float fv = sigf(acc[d][1][u]);
                float gv = tanhf_(acc[d][2][u]);
                float ov = sigf(acc[d][3][u]);
                c[d][u]  = fv * c[d][u] + iv * gv;
                hn[d][u] = ov * tanhf_(c[d][u]);
            }
        __syncthreads();
        hs[r0 * 68 + lane]      = hn[0][0];
        hs[r0 * 68 + 32 + lane] = hn[0][1];
        hs[r1 * 68 + lane]      = hn[1][0];
        hs[r1 * 68 + 32 + lane] = hn[1][1];
        __syncthreads();
    }

    float b1v = bo1[lane], b2v = bo2[0];
#pragma unroll
    for (int rr = 0; rr < 2; rr++) {
        int r = wp * 2 + rr;
        float a = b1v;
#pragma unroll 16
        for (int k = 0; k < 64; k++) a += hs[r * 68 + k] * W1s[k * 32 + lane];
        float m = fmaxf(a, 0.f) * W2s[lane];
#pragma unroll
        for (int o = 16; o; o >>= 1) m += __shfl_xor_sync(~0u, m, o);
        if (lane == 0) out[(long)blockIdx.x * 16 + r] = m + b2v;
    }
}

// ---------------- launcher ----------------
extern "C" void kernel_launch(void* const* d_in, const int* in_sizes, int n_in,
                              void* d_out, int out_size) {
    const float* x   = (const float*)d_in[0];
    const int*   adj = (const int*)  d_in[1];
    const float* W1  = (const float*)d_in[2];
    const float* a1  = (const float*)d_in[3];
    const float* W2  = (const float*)d_in[4];
    const float* a2  = (const float*)d_in[5];
    const float* Wih = (const float*)d_in[6];
    const float* Whh = (const float*)d_in[7];
    const float* bih = (const float*)d_in[8];
    const float* bhh = (const float*)d_in[9];
    const float* Wo1 = (const float*)d_in[10];
    const float* bo1 = (const float*)d_in[11];
    const float* Wo2 = (const float*)d_in[12];
    const float* bo2 = (const float*)d_in[13];
    float* out = (float*)d_out;

    __nv_bfloat16* d_h1b_p; cudaGetSymbolAddress((void**)&d_h1b_p, d_h1b);
    __nv_bfloat16* d_gb_p;  cudaGetSymbolAddress((void**)&d_gb_p,  d_gb);
    __nv_bfloat16* d_W2b_p; cudaGetSymbolAddress((void**)&d_W2b_p, d_W2b);
    __nv_bfloat16* d_Wihb_p;cudaGetSymbolAddress((void**)&d_Wihb_p,d_Wihb);
    float* d_XG_p;          cudaGetSymbolAddress((void**)&d_XG_p,  d_XG);

    const int L1SM = (4608 + 32 * 136) * sizeof(float);
    const int BFSM = 2 * 128 * 272;
    cudaFuncSetAttribute((const void*)gemm_l1,
                         cudaFuncAttributeMaxDynamicSharedMemorySize, L1SM);
    cudaFuncSetAttribute((const void*)gemm_bf<0, 128, 1, 0>,
                         cudaFuncAttributeMaxDynamicSharedMemorySize, BFSM);
    cudaFuncSetAttribute((const void*)gemm_bf<1, 256, 0, 1>,
                         cudaFuncAttributeMaxDynamicSharedMemorySize, BFSM);

    prep_all<<<512, 256>>>(adj, W2, Wih);

    // GAT layer 1
    gemm_l1<<<512, 256, L1SM>>>(x, W1, a1);
    att_v7_kernel<0><<<dim3(8, 64), 256>>>();

    // GAT layer 2 (bf16 GEMM)
    gemm_bf<0, 128, 1, 0><<<dim3(512, 1), 256, BFSM>>>(d_h1b_p, d_W2b_p, nullptr, nullptr, a2, nullptr);
    att_v7_kernel<1><<<dim3(8, 64), 256>>>();

    // LSTM input gates (gathers d_gb [p][n][h])
    gemm_bf<1, 256, 0, 1><<<dim3(512, 2), 256, BFSM>>>(d_gb_p, d_Wihb_p, bih, bhh, nullptr, d_XG_p);

    // LSTM recurrence + fused MLP
    size_t smem = (64 * 257 + 16 * 68 + 64 * 32 + 32) * sizeof(float);
    cudaFuncSetAttribute(lstm_kernel, cudaFuncAttributeMaxDynamicSharedMemorySize, (int)smem);
    lstm_kernel<<<256, 256, smem>>>(Whh, Wo1, bo1, Wo2, bo2, out);
}